// round 9
// baseline (speedup 1.0000x reference)
#include <cuda_runtime.h>
#include <cuda_bf16.h>
#include <cstdint>

#define DIMSZ 2048
#define NHEADS 16
#define HDIM 128
#define BSZ 2
#define LSEQ 2048
#define MROWS (BSZ * LSEQ)   // 4096
#define KDIM 2048
#define SCALE_F 0.08838834764831845f

// ---------------------------------------------------------------------------
// Scratch (__device__ globals; no allocation allowed)
// ---------------------------------------------------------------------------
__device__ __nv_bfloat16 g_xh[(size_t)MROWS * DIMSZ];
__device__ __nv_bfloat16 g_xl[(size_t)MROWS * DIMSZ];
__device__ __nv_bfloat16 g_ch[(size_t)MROWS * DIMSZ];
__device__ __nv_bfloat16 g_cl[(size_t)MROWS * DIMSZ];
__device__ __nv_bfloat16 g_wqh[(size_t)3 * DIMSZ * DIMSZ];  // W_qkv^T [6144][2048]
__device__ __nv_bfloat16 g_wql[(size_t)3 * DIMSZ * DIMSZ];
__device__ __nv_bfloat16 g_wph[(size_t)DIMSZ * DIMSZ];      // W_proj^T [2048][2048]
__device__ __nv_bfloat16 g_wpl[(size_t)DIMSZ * DIMSZ];
__device__ __nv_bfloat16 g_qh[(size_t)MROWS * DIMSZ];
__device__ __nv_bfloat16 g_ql[(size_t)MROWS * DIMSZ];
__device__ __nv_bfloat16 g_kvh[(size_t)MROWS * 2 * DIMSZ];
__device__ __nv_bfloat16 g_kvl[(size_t)MROWS * 2 * DIMSZ];
__device__ __nv_bfloat16 g_ath[(size_t)MROWS * DIMSZ];
__device__ __nv_bfloat16 g_atl[(size_t)MROWS * DIMSZ];

// ---------------------------------------------------------------------------
// PTX helpers (baseline ISA: ldmatrix / mma.sync / cp.async)
// ---------------------------------------------------------------------------
__device__ __forceinline__ uint32_t smem_to_u32(const void* p) {
    uint32_t a;
    asm("{ .reg .u64 t; cvta.to.shared.u64 t, %1; cvt.u32.u64 %0, t; }" : "=r"(a) : "l"(p));
    return a;
}

#define CP_ASYNC16(dst, src) \
    asm volatile("cp.async.cg.shared.global [%0], [%1], 16;" :: "r"(dst), "l"(src) : "memory")
#define CP_COMMIT() asm volatile("cp.async.commit_group;" ::: "memory")
#define CP_WAIT(n)  asm volatile("cp.async.wait_group %0;" :: "n"(n) : "memory")

#define LDSM_X4(r0, r1, r2, r3, addr) \
    asm volatile("ldmatrix.sync.aligned.m8n8.x4.shared.b16 {%0,%1,%2,%3}, [%4];" \
                 : "=r"(r0), "=r"(r1), "=r"(r2), "=r"(r3) : "r"(addr))
#define LDSM_X4_T(r0, r1, r2, r3, addr) \
    asm volatile("ldmatrix.sync.aligned.m8n8.x4.trans.shared.b16 {%0,%1,%2,%3}, [%4];" \
                 : "=r"(r0), "=r"(r1), "=r"(r2), "=r"(r3) : "r"(addr))

#define MMA16816(d, a, b0, b1) \
    asm volatile("mma.sync.aligned.m16n8k16.row.col.f32.bf16.bf16.f32 " \
                 "{%0,%1,%2,%3}, {%4,%5,%6,%7}, {%8,%9}, {%0,%1,%2,%3};" \
                 : "+f"((d)[0]), "+f"((d)[1]), "+f"((d)[2]), "+f"((d)[3]) \
                 : "r"((a)[0]), "r"((a)[1]), "r"((a)[2]), "r"((a)[3]), \
                   "r"(b0), "r"(b1))

__device__ __forceinline__ uint32_t packbf(float lo, float hi) {
    uint32_t r;
    asm("cvt.rn.bf16x2.f32 %0, %1, %2;" : "=r"(r) : "f"(hi), "f"(lo));
    return r;
}
__device__ __forceinline__ float bflo_f(uint32_t u) { return __uint_as_float(u << 16); }
__device__ __forceinline__ float bfhi_f(uint32_t u) { return __uint_as_float(u & 0xffff0000u); }

// ---------------------------------------------------------------------------
// Conversion kernels
// ---------------------------------------------------------------------------
__global__ __launch_bounds__(256)
void split_fp32(const float* __restrict__ in, __nv_bfloat16* __restrict__ h,
                __nv_bfloat16* __restrict__ l, int n4)
{
    int i = blockIdx.x * 256 + threadIdx.x;
    if (i >= n4) return;
    float4 v = ((const float4*)in)[i];
    uint32_t h01 = packbf(v.x, v.y), h23 = packbf(v.z, v.w);
    uint32_t l01 = packbf(v.x - bflo_f(h01), v.y - bfhi_f(h01));
    uint32_t l23 = packbf(v.z - bflo_f(h23), v.w - bfhi_f(h23));
    ((uint32_t*)h)[2 * i] = h01; ((uint32_t*)h)[2 * i + 1] = h23;
    ((uint32_t*)l)[2 * i] = l01; ((uint32_t*)l)[2 * i + 1] = l23;
}

__global__ __launch_bounds__(256)
void transpose_split(const float* __restrict__ in, __nv_bfloat16* __restrict__ h,
                     __nv_bfloat16* __restrict__ l, int R, int C)
{
    __shared__ float tile[32][33];
    int c0 = blockIdx.x * 32, r0 = blockIdx.y * 32;
    int tx = threadIdx.x & 31, ty = threadIdx.x >> 5;
#pragma unroll
    for (int i = 0; i < 4; i++)
        tile[ty + 8 * i][tx] = in[(size_t)(r0 + ty + 8 * i) * C + c0 + tx];
    __syncthreads();
#pragma unroll
    for (int i = 0; i < 4; i++) {
        float v = tile[tx][ty + 8 * i];
        __nv_bfloat16 hv = __float2bfloat16(v);
        __nv_bfloat16 lv = __float2bfloat16(v - __bfloat162float(hv));
        size_t o = (size_t)(c0 + ty + 8 * i) * R + r0 + tx;
        h[o] = hv; l[o] = lv;
    }
}

// ---------------------------------------------------------------------------
// mma.sync split-bf16 GEMM (R7 version — proven fastest): C = A @ B^T + bias
// CTA 128x128x32, 8 warps (32m x 64n), double-buffered cp.async, 2 CTAs/SM.
// ---------------------------------------------------------------------------
#define GBM 128
#define GBN 128
#define GBK 32
#define NCH (KDIM / GBK)         // 64
#define ROWB 80
#define TILE_B (128 * ROWB)      // 10240
#define STAGE_B (4 * TILE_B)     // 40960 : [Ah][Al][Bh][Bl]
#define GEMM_SMEM (2 * STAGE_B)  // 81920

__global__ __launch_bounds__(256, 2)
void gemm_mma(const __nv_bfloat16* __restrict__ Ah0, const __nv_bfloat16* __restrict__ Al0,
              const __nv_bfloat16* __restrict__ Ah1, const __nv_bfloat16* __restrict__ Al1,
              const __nv_bfloat16* __restrict__ Bh, const __nv_bfloat16* __restrict__ Bl,
              const float* __restrict__ bias,
              float* __restrict__ Cf0, int ldc0, float* __restrict__ Cf1, int ldc1,
              __nv_bfloat16* __restrict__ Ch0, __nv_bfloat16* __restrict__ Cl0,
              __nv_bfloat16* __restrict__ Ch1, __nv_bfloat16* __restrict__ Cl1,
              int nsplit, int outmode)
{
    extern __shared__ char sm[];
    const uint32_t sbase = smem_to_u32(sm);
    const int tid  = threadIdx.x;
    const int lane = tid & 31;
    const int wid  = tid >> 5;
    const int wm   = (wid & 3) * 32;
    const int wn   = (wid >> 2) * 64;
    const int n0 = blockIdx.x * GBN;
    const int m0 = blockIdx.y * GBM;

    const __nv_bfloat16* Ah = (n0 < nsplit) ? Ah0 : Ah1;
    const __nv_bfloat16* Al = (n0 < nsplit) ? Al0 : Al1;

    float acc[2][8][4];
#pragma unroll
    for (int i = 0; i < 2; i++)
#pragma unroll
        for (int j = 0; j < 8; j++)
#pragma unroll
            for (int r = 0; r < 4; r++) acc[i][j][r] = 0.f;

    uint32_t aoff[2][2];
#pragma unroll
    for (int mf = 0; mf < 2; mf++)
#pragma unroll
        for (int ks = 0; ks < 2; ks++)
            aoff[mf][ks] = (uint32_t)((wm + mf * 16 + (lane & 15)) * ROWB
                                      + (ks * 16 + 8 * (lane >> 4)) * 2);
    uint32_t boff[4][2];
#pragma unroll
    for (int jj = 0; jj < 4; jj++)
#pragma unroll
        for (int ks = 0; ks < 2; ks++)
            boff[jj][ks] = (uint32_t)((wn + jj * 16 + (lane & 7) + 8 * (lane >> 4)) * ROWB
                                      + (ks * 16 + 8 * ((lane >> 3) & 1)) * 2);

    auto load_chunk = [&](int ic, int s) {
        const int k0 = ic * GBK;
#pragma unroll
        for (int it = 0; it < 8; it++) {
            const int tile   = it >> 1;
            const int within = (it & 1) * 256 + tid;
            const int row    = within >> 2;
            const int seg    = within & 3;
            const __nv_bfloat16* src;
            if (tile == 0)      src = Ah + (size_t)(m0 + row) * KDIM + k0 + seg * 8;
            else if (tile == 1) src = Al + (size_t)(m0 + row) * KDIM + k0 + seg * 8;
            else if (tile == 2) src = Bh + (size_t)(n0 + row) * KDIM + k0 + seg * 8;
            else                src = Bl + (size_t)(n0 + row) * KDIM + k0 + seg * 8;
            uint32_t dst = sbase + s * STAGE_B + tile * TILE_B + row * ROWB + seg * 16;
            CP_ASYNC16(dst, src);
        }
        CP_COMMIT();
    };

    load_chunk(0, 0);

    for (int ic = 0; ic < NCH; ic++) {
        const int s = ic & 1;
        if (ic + 1 < NCH) { load_chunk(ic + 1, s ^ 1); CP_WAIT(1); }
        else              { CP_WAIT(0); }
        __syncthreads();

        const uint32_t stage = sbase + s * STAGE_B;
#pragma unroll
        for (int pass = 0; pass < 3; pass++) {
            const uint32_t Abase = stage + ((pass == 2) ? TILE_B : 0);
            const uint32_t Bbase = stage + 2 * TILE_B + ((pass == 1) ? TILE_B : 0);
#pragma unroll
            for (int ks = 0; ks < 2; ks++) {
                uint32_t a[2][4];
                LDSM_X4(a[0][0], a[0][1], a[0][2], a[0][3], Abase + aoff[0][ks]);
                LDSM_X4(a[1][0], a[1][1], a[1][2], a[1][3], Abase + aoff[1][ks]);
#pragma unroll
                for (int jj = 0; jj < 4; jj++) {
                    uint32_t b0, b1, b2, b3;
                    LDSM_X4(b0, b1, b2, b3, Bbase + boff[jj][ks]);
                    MMA16816(acc[0][jj * 2],     a[0], b0, b1);
                    MMA16816(acc[1][jj * 2],     a[1], b0, b1);
                    MMA16816(acc[0][jj * 2 + 1], a[0], b2, b3);
                    MMA16816(acc[1][jj * 2 + 1], a[1], b2, b3);
                }
            }
        }
        __syncthreads();
    }

    int ld, nc0;
    float* Cf; __nv_bfloat16 *Ch, *Cl;
    if (n0 < nsplit) { Cf = Cf0; Ch = Ch0; Cl = Cl0; ld = ldc0; nc0 = n0; }
    else             { Cf = Cf1; Ch = Ch1; Cl = Cl1; ld = ldc1; nc0 = n0 - nsplit; }

#pragma unroll
    for (int mf = 0; mf < 2; mf++) {
#pragma unroll
        for (int nf = 0; nf < 8; nf++) {
            const int nl = wn + nf * 8 + 2 * (lane & 3);
            const float bx = bias[n0 + nl];
            const float by = bias[n0 + nl + 1];
            const int m_up = m0 + wm + mf * 16 + (lane >> 2);
#pragma unroll
            for (int half = 0; half < 2; half++) {
                const int m = m_up + 8 * half;
                float v0 = acc[mf][nf][2 * half]     + bx;
                float v1 = acc[mf][nf][2 * half + 1] + by;
                if (outmode == 0) {
                    float2 v; v.x = v0; v.y = v1;
                    *(float2*)(Cf + (size_t)m * ld + nc0 + nl) = v;
                } else {
                    uint32_t hi = packbf(v0, v1);
                    uint32_t lo = packbf(v0 - bflo_f(hi), v1 - bfhi_f(hi));
                    *(uint32_t*)(Ch + (size_t)m * ld + nc0 + nl) = hi;
                    *(uint32_t*)(Cl + (size_t)m * ld + nc0 + nl) = lo;
                }
            }
        }
    }
}

// ---------------------------------------------------------------------------
// Tensor-core flash attention, 512 threads (16 warps = 4/SMSP).
// Warp (wr, wc): wr∈0..7 owns 16 q-rows; wc∈0..1 splits k-cols (S phase) and
// head-dim (PV phase). P transits smem (hi/lo). K double-buffered, V single.
// ---------------------------------------------------------------------------
#define NT (LSEQ / 64)     // 32
#define ASTR 272
#define PSTR 144
#define SQH 0
#define SQL 34816
#define SKR 69632          // K ring: 2 stages x 34816 (h at +0, l at +17408)
#define KSTG 34816
#define KHL 17408
#define SVH 139264
#define SVL 156672
#define SPH 174080         // P: 128 x 144 bytes, hi then lo
#define SPL 192512
#define SRED 210944        // float red[512]: max[2][128], sum[2][128]
#define ATT_SMEM 212992

__global__ __launch_bounds__(512, 1)
void attn_mma(const __nv_bfloat16* __restrict__ Qh, const __nv_bfloat16* __restrict__ Ql,
              const __nv_bfloat16* __restrict__ KVh, const __nv_bfloat16* __restrict__ KVl,
              __nv_bfloat16* __restrict__ Oh, __nv_bfloat16* __restrict__ Ol)
{
    extern __shared__ char sm[];
    const uint32_t sb = smem_to_u32(sm);
    const int tid  = threadIdx.x;
    const int lane = tid & 31;
    const int wid  = tid >> 5;
    const int wr   = wid & 7;
    const int wc   = wid >> 3;

    const int qt = blockIdx.x, h = blockIdx.y, b = blockIdx.z;
    const int qrow0 = b * LSEQ + qt * 128;
    const int hcol  = h * HDIM;

    // Q load (hi+lo), one group
#pragma unroll
    for (int i = 0; i < 4; i++) {
        int idx = i * 512 + tid;
        int row = idx >> 4, seg = idx & 15;
        size_t g = (size_t)(qrow0 + row) * DIMSZ + hcol + seg * 8;
        uint32_t d = row * ASTR + seg * 16;
        CP_ASYNC16(sb + SQH + d, Qh + g);
        CP_ASYNC16(sb + SQL + d, Ql + g);
    }
    CP_COMMIT();

    auto load_k = [&](int jt) {
        const uint32_t base = sb + SKR + (jt & 1) * KSTG;
        const int krow0 = b * LSEQ + jt * 64;
#pragma unroll
        for (int i = 0; i < 4; i++) {
            int idx = i * 512 + tid;
            int half = idx >> 10, within = idx & 1023;
            int row = within >> 4, seg = within & 15;
            size_t src = (size_t)(krow0 + row) * (2 * DIMSZ) + hcol + seg * 8;
            CP_ASYNC16(base + half * KHL + row * ASTR + seg * 16,
                       (half ? KVl : KVh) + src);
        }
        CP_COMMIT();
    };
    auto load_v = [&](int jt) {
        const int krow0 = b * LSEQ + jt * 64;
#pragma unroll
        for (int i = 0; i < 4; i++) {
            int idx = i * 512 + tid;
            int half = idx >> 10, within = idx & 1023;
            int row = within >> 4, seg = within & 15;
            size_t src = (size_t)(krow0 + row) * (2 * DIMSZ) + DIMSZ + hcol + seg * 8;
            CP_ASYNC16(sb + (half ? SVL : SVH) + row * ASTR + seg * 16,
                       (half ? KVl : KVh) + src);
        }
        CP_COMMIT();
    };

    load_k(0); load_v(0); load_k(1);

    // fragment offsets
    const uint32_t ab = (uint32_t)((wr * 16 + (lane & 15)) * ASTR + (lane >> 4) * 16);
    const uint32_t kb = (uint32_t)((wc * 32 + (lane & 7) + 8 * (lane >> 4)) * ASTR
                                   + ((lane >> 3) & 1) * 16);
    const uint32_t pb = (uint32_t)((wr * 16 + (lane & 15)) * PSTR + (lane >> 4) * 16);
    const uint32_t vb = (uint32_t)(((lane & 7) + 8 * ((lane >> 3) & 1)) * ASTR
                                   + (lane >> 4) * 16 + wc * 128);
    float* red = (float*)(sm + SRED);
    const int lr = wr * 16 + (lane >> 2);   // local row of this lane's frag row 0

    float oacc[8][4];
#pragma unroll
    for (int f = 0; f < 8; f++)
#pragma unroll
        for (int e = 0; e < 4; e++) oacc[f][e] = 0.f;
    float m_prev[2] = {-3.0e38f, -3.0e38f};
    float l_acc[2]  = {0.f, 0.f};

    for (int jt = 0; jt < NT; jt++) {
        if (jt == NT - 1) { CP_WAIT(0); } else { CP_WAIT(1); }
        __syncthreads();

        const uint32_t sK = sb + SKR + (jt & 1) * KSTG;

        // ---- S = Q K^T (warp: 16 rows x 32 k-cols, 3 passes) ----
        float sacc[4][4];
#pragma unroll
        for (int f = 0; f < 4; f++)
#pragma unroll
            for (int e = 0; e < 4; e++) sacc[f][e] = 0.f;

#pragma unroll
        for (int ks = 0; ks < 8; ks++) {
            uint32_t ah[4], al[4];
            LDSM_X4(ah[0], ah[1], ah[2], ah[3], sb + SQH + ab + ks * 32);
            LDSM_X4(al[0], al[1], al[2], al[3], sb + SQL + ab + ks * 32);
#pragma unroll
            for (int jj = 0; jj < 2; jj++) {
                uint32_t h0, h1, h2, h3, l0, l1, l2, l3;
                LDSM_X4(h0, h1, h2, h3, sK + kb + jj * (16 * ASTR) + ks * 32);
                LDSM_X4(l0, l1, l2, l3, sK + KHL + kb + jj * (16 * ASTR) + ks * 32);
                MMA16816(sacc[2 * jj],     ah, h0, h1);
                MMA16816(sacc[2 * jj + 1], ah, h2, h3);
                MMA16816(sacc[2 * jj],     ah, l0, l1);
                MMA16816(sacc[2 * jj + 1], ah, l2, l3);
                MMA16816(sacc[2 * jj],     al, h0, h1);
                MMA16816(sacc[2 * jj + 1], al, h2, h3);
            }
        }

        // ---- cross-warp online softmax ----
        float mx0 = -3.0e38f, mx1 = -3.0e38f;
#pragma unroll
        for (int f = 0; f < 4; f++) {
            sacc[f][0] *= SCALE_F; sacc[f][1] *= SCALE_F;
            sacc[f][2] *= SCALE_F; sacc[f][3] *= SCALE_F;
            mx0 = fmaxf(mx0, fmaxf(sacc[f][0], sacc[f][1]));
            mx1 = fmaxf(mx1, fmaxf(sacc[f][2], sacc[f][3]));
        }
        mx0 = fmaxf(mx0, __shfl_xor_sync(0xffffffffu, mx0, 1));
        mx0 = fmaxf(mx0, __shfl_xor_sync(0xffffffffu, mx0, 2));
        mx1 = fmaxf(mx1, __shfl_xor_sync(0xffffffffu, mx1, 1));
        mx1 = fmaxf(mx1, __shfl_xor_sync(0xffffffffu, mx1, 2));
        if ((lane & 3) == 0) {
            red[wc * 128 + lr]     = mx0;
            red[wc * 128 + lr + 8] = mx1;
        }
        __syncthreads();
        float gm0 = fmaxf(red[lr],     red[128 + lr]);
        float gm1 = fmaxf(red[lr + 8], red[128 + lr + 8]);
        float mnew0 = fmaxf(m_prev[0], gm0);
        float mnew1 = fmaxf(m_prev[1], gm1);
        float er0 = __expf(m_prev[0] - mnew0);
        float er1 = __expf(m_prev[1] - mnew1);
        m_prev[0] = mnew0; m_prev[1] = mnew1;

        float rs0 = 0.f, rs1 = 0.f;
#pragma unroll
        for (int f = 0; f < 4; f++) {
            sacc[f][0] = __expf(sacc[f][0] - mnew0);
            sacc[f][1] = __expf(sacc[f][1] - mnew0);
            sacc[f][2] = __expf(sacc[f][2] - mnew1);
            sacc[f][3] = __expf(sacc[f][3] - mnew1);
            rs0 += sacc[f][0] + sacc[f][1];
            rs1 += sacc[f][2] + sacc[f][3];
        }
        rs0 += __shfl_xor_sync(0xffffffffu, rs0, 1);
        rs0 += __shfl_xor_sync(0xffffffffu, rs0, 2);
        rs1 += __shfl_xor_sync(0xffffffffu, rs1, 1);
        rs1 += __shfl_xor_sync(0xffffffffu, rs1, 2);
        if ((lane & 3) == 0) {
            red[256 + wc * 128 + lr]     = rs0;
            red[256 + wc * 128 + lr + 8] = rs1;
        }

        // ---- store P (hi/lo bf16) to smem ----
#pragma unroll
        for (int f = 0; f < 4; f++) {
            const uint32_t cb = (uint32_t)((wc * 32 + f * 8 + 2 * (lane & 3)) * 2);
            uint32_t u0 = packbf(sacc[f][0], sacc[f][1]);
            uint32_t u1 = packbf(sacc[f][2], sacc[f][3]);
            *(uint32_t*)(sm + SPH + lr * PSTR + cb)             = u0;
            *(uint32_t*)(sm + SPH + (lr + 8) * PSTR + cb)       = u1;
            *(uint32_t*)(sm + SPL + lr * PSTR + cb) =
                packbf(sacc[f][0] - bflo_f(u0), sacc[f][1] - bfhi_f(u0));
            *(uint32_t*)(sm + SPL + (lr + 8) * PSTR + cb) =
                packbf(sacc[f][2] - bflo_f(u1), sacc[f][3] - bfhi_f(u1));
        }
        __syncthreads();

        float ts0 = red[256 + lr]     + red[256 + 128 + lr];
        float ts1 = red[256 + lr + 8] + red[256 + 128 + lr + 8];
        l_acc[0] = l_acc[0] * er0 + ts0;
        l_acc[1] = l_acc[1] * er1 + ts1;

#pragma unroll
        for (int f = 0; f < 8; f++) {
            oacc[f][0] *= er0; oacc[f][1] *= er0;
            oacc[f][2] *= er1; oacc[f][3] *= er1;
        }

        // ---- O += P V (warp: 16 rows x 64 hd-cols, full 64 k, 3 passes) ----
#pragma unroll
        for (int t = 0; t < 4; t++) {
            uint32_t ph[4], pl[4];
            LDSM_X4(ph[0], ph[1], ph[2], ph[3], sb + SPH + pb + t * 32);
            LDSM_X4(pl[0], pl[1], pl[2], pl[3], sb + SPL + pb + t * 32);
#pragma unroll
            for (int g4 = 0; g4 < 4; g4++) {
                uint32_t vh0, vh1, vh2, vh3, vl0, vl1, vl2, vl3;
                LDSM_X4_T(vh0, vh1, vh2, vh3, sb + SVH + vb + t * (16 * ASTR) + g4 * 32);
                LDSM_X4_T(vl0, vl1, vl2, vl3, sb + SVL + vb + t * (16 * ASTR) + g4 * 32);
                MMA16816(oacc[2 * g4],     ph, vh0, vh1);
                MMA16816(oacc[2 * g4 + 1], ph, vh2, vh3);
                MMA16816(oacc[2 * g4],     ph, vl0, vl1);
                MMA16816(oacc[2 * g4 + 1], ph, vl2, vl3);
                MMA16816(oacc[2 * g4],     pl, vh0, vh1);
                MMA16816(oacc[2 * g4 + 1], pl, vh2, vh3);
            }
        }
        __syncthreads();   // V buffer, P, and K stage free

        if (jt + 1 < NT) load_v(jt + 1);
        if (jt + 2 < NT) load_k(jt + 2);
    }

    // ---- epilogue: normalize, split bf16 hi/lo ----
#pragma unroll
    for (int rs = 0; rs < 2; rs++) {
        const float inv = 1.0f / l_acc[rs];
        const int row = qrow0 + wr * 16 + (lane >> 2) + 8 * rs;
#pragma unroll
        for (int f = 0; f < 8; f++) {
            float v0 = oacc[f][2 * rs]     * inv;
            float v1 = oacc[f][2 * rs + 1] * inv;
            uint32_t hi = packbf(v0, v1);
            uint32_t lo = packbf(v0 - bflo_f(hi), v1 - bfhi_f(hi));
            const int col = hcol + wc * 64 + f * 8 + 2 * (lane & 3);
            *(uint32_t*)(Oh + (size_t)row * DIMSZ + col) = hi;
            *(uint32_t*)(Ol + (size_t)row * DIMSZ + col) = lo;
        }
    }
}

// ---------------------------------------------------------------------------
extern "C" void kernel_launch(void* const* d_in, const int* in_sizes, int n_in,
                              void* d_out, int out_size)
{
    const float* x       = (const float*)d_in[0];
    const float* context = (const float*)d_in[1];
    const float* W_qkv   = (const float*)d_in[2];
    const float* b_qkv   = (const float*)d_in[3];
    const float* W_proj  = (const float*)d_in[4];
    const float* b_proj  = (const float*)d_in[5];
    float* out = (float*)d_out;

    __nv_bfloat16 *xh, *xl, *ch, *cl, *wqh, *wql, *wph, *wpl;
    __nv_bfloat16 *qh, *ql, *kvh, *kvl, *ath, *atl;
    cudaGetSymbolAddress((void**)&xh,  g_xh);  cudaGetSymbolAddress((void**)&xl,  g_xl);
    cudaGetSymbolAddress((void**)&ch,  g_ch);  cudaGetSymbolAddress((void**)&cl,  g_cl);
    cudaGetSymbolAddress((void**)&wqh, g_wqh); cudaGetSymbolAddress((void**)&wql, g_wql);
    cudaGetSymbolAddress((void**)&wph, g_wph); cudaGetSymbolAddress((void**)&wpl, g_wpl);
    cudaGetSymbolAddress((void**)&qh,  g_qh);  cudaGetSymbolAddress((void**)&ql,  g_ql);
    cudaGetSymbolAddress((void**)&kvh, g_kvh); cudaGetSymbolAddress((void**)&kvl, g_kvl);
    cudaGetSymbolAddress((void**)&ath, g_ath); cudaGetSymbolAddress((void**)&atl, g_atl);

    cudaFuncSetAttribute(gemm_mma, cudaFuncAttributeMaxDynamicSharedMemorySize, GEMM_SMEM);
    cudaFuncSetAttribute(attn_mma, cudaFuncAttributeMaxDynamicSharedMemorySize, ATT_SMEM);

    const int n4 = MROWS * DIMSZ / 4;

    split_fp32<<<(n4 + 255) / 256, 256>>>(x, xh, xl, n4);
    split_fp32<<<(n4 + 255) / 256, 256>>>(context, ch, cl, n4);
    transpose_split<<<dim3(3 * DIMSZ / 32, DIMSZ / 32), 256>>>(W_qkv, wqh, wql, DIMSZ, 3 * DIMSZ);
    transpose_split<<<dim3(DIMSZ / 32, DIMSZ / 32), 256>>>(W_proj, wph, wpl, DIMSZ, DIMSZ);

    gemm_mma<<<dim3(3 * DIMSZ / GBN, MROWS / GBM), 256, GEMM_SMEM>>>(
        xh, xl, ch, cl, wqh, wql, b_qkv,
        nullptr, DIMSZ, nullptr, 2 * DIMSZ,
        qh, ql, kvh, kvl, DIMSZ, 1);

    attn_mma<<<dim3(LSEQ / 128, NHEADS, BSZ), 512, ATT_SMEM>>>(qh, ql, kvh, kvl, ath, atl);

    gemm_mma<<<dim3(DIMSZ / GBN, MROWS / GBM), 256, GEMM_SMEM>>>(
        ath, atl, ath, atl, wph, wpl, b_proj,
        out, DIMSZ, out, DIMSZ,
        nullptr, nullptr, nullptr, nullptr, 1 << 30, 0);
}

// round 10
// speedup vs baseline: 1.0837x; 1.0837x over previous
#include <cuda_runtime.h>
#include <cuda_bf16.h>
#include <cstdint>

#define DIMSZ 2048
#define NHEADS 16
#define HDIM 128
#define BSZ 2
#define LSEQ 2048
#define MROWS (BSZ * LSEQ)   // 4096
#define KDIM 2048
#define SCALE_F 0.08838834764831845f

// ---------------------------------------------------------------------------
// Scratch (__device__ globals; no allocation allowed)
// ---------------------------------------------------------------------------
__device__ __nv_bfloat16 g_xh[(size_t)MROWS * DIMSZ];
__device__ __nv_bfloat16 g_xl[(size_t)MROWS * DIMSZ];
__device__ __nv_bfloat16 g_ch[(size_t)MROWS * DIMSZ];
__device__ __nv_bfloat16 g_cl[(size_t)MROWS * DIMSZ];
__device__ __nv_bfloat16 g_wqh[(size_t)3 * DIMSZ * DIMSZ];  // W_qkv^T [6144][2048]
__device__ __nv_bfloat16 g_wql[(size_t)3 * DIMSZ * DIMSZ];
__device__ __nv_bfloat16 g_wph[(size_t)DIMSZ * DIMSZ];      // W_proj^T [2048][2048]
__device__ __nv_bfloat16 g_wpl[(size_t)DIMSZ * DIMSZ];
__device__ __nv_bfloat16 g_qh[(size_t)MROWS * DIMSZ];
__device__ __nv_bfloat16 g_ql[(size_t)MROWS * DIMSZ];
__device__ __nv_bfloat16 g_kvh[(size_t)MROWS * 2 * DIMSZ];
__device__ __nv_bfloat16 g_kvl[(size_t)MROWS * 2 * DIMSZ];
__device__ __nv_bfloat16 g_ath[(size_t)MROWS * DIMSZ];
__device__ __nv_bfloat16 g_atl[(size_t)MROWS * DIMSZ];
// split-KV partials: 2 halves of unnormalized fp32 O + per-row m, l
__device__ float g_opart[(size_t)2 * MROWS * DIMSZ];               // 64 MB
__device__ float g_mpart[(size_t)2 * BSZ * NHEADS * LSEQ];
__device__ float g_lpart[(size_t)2 * BSZ * NHEADS * LSEQ];

// ---------------------------------------------------------------------------
// PTX helpers (baseline ISA: ldmatrix / mma.sync / cp.async)
// ---------------------------------------------------------------------------
__device__ __forceinline__ uint32_t smem_to_u32(const void* p) {
    uint32_t a;
    asm("{ .reg .u64 t; cvta.to.shared.u64 t, %1; cvt.u32.u64 %0, t; }" : "=r"(a) : "l"(p));
    return a;
}

#define CP_ASYNC16(dst, src) \
    asm volatile("cp.async.cg.shared.global [%0], [%1], 16;" :: "r"(dst), "l"(src) : "memory")
#define CP_COMMIT() asm volatile("cp.async.commit_group;" ::: "memory")
#define CP_WAIT(n)  asm volatile("cp.async.wait_group %0;" :: "n"(n) : "memory")

#define LDSM_X4(r0, r1, r2, r3, addr) \
    asm volatile("ldmatrix.sync.aligned.m8n8.x4.shared.b16 {%0,%1,%2,%3}, [%4];" \
                 : "=r"(r0), "=r"(r1), "=r"(r2), "=r"(r3) : "r"(addr))
#define LDSM_X4_T(r0, r1, r2, r3, addr) \
    asm volatile("ldmatrix.sync.aligned.m8n8.x4.trans.shared.b16 {%0,%1,%2,%3}, [%4];" \
                 : "=r"(r0), "=r"(r1), "=r"(r2), "=r"(r3) : "r"(addr))

#define MMA16816(d, a, b0, b1) \
    asm volatile("mma.sync.aligned.m16n8k16.row.col.f32.bf16.bf16.f32 " \
                 "{%0,%1,%2,%3}, {%4,%5,%6,%7}, {%8,%9}, {%0,%1,%2,%3};" \
                 : "+f"((d)[0]), "+f"((d)[1]), "+f"((d)[2]), "+f"((d)[3]) \
                 : "r"((a)[0]), "r"((a)[1]), "r"((a)[2]), "r"((a)[3]), \
                   "r"(b0), "r"(b1))

__device__ __forceinline__ uint32_t packbf(float lo, float hi) {
    uint32_t r;
    asm("cvt.rn.bf16x2.f32 %0, %1, %2;" : "=r"(r) : "f"(hi), "f"(lo));
    return r;
}
__device__ __forceinline__ float bflo_f(uint32_t u) { return __uint_as_float(u << 16); }
__device__ __forceinline__ float bfhi_f(uint32_t u) { return __uint_as_float(u & 0xffff0000u); }

// ---------------------------------------------------------------------------
// Conversion kernels
// ---------------------------------------------------------------------------
__global__ __launch_bounds__(256)
void split_fp32(const float* __restrict__ in, __nv_bfloat16* __restrict__ h,
                __nv_bfloat16* __restrict__ l, int n4)
{
    int i = blockIdx.x * 256 + threadIdx.x;
    if (i >= n4) return;
    float4 v = ((const float4*)in)[i];
    uint32_t h01 = packbf(v.x, v.y), h23 = packbf(v.z, v.w);
    uint32_t l01 = packbf(v.x - bflo_f(h01), v.y - bfhi_f(h01));
    uint32_t l23 = packbf(v.z - bflo_f(h23), v.w - bfhi_f(h23));
    ((uint32_t*)h)[2 * i] = h01; ((uint32_t*)h)[2 * i + 1] = h23;
    ((uint32_t*)l)[2 * i] = l01; ((uint32_t*)l)[2 * i + 1] = l23;
}

__global__ __launch_bounds__(256)
void transpose_split(const float* __restrict__ in, __nv_bfloat16* __restrict__ h,
                     __nv_bfloat16* __restrict__ l, int R, int C)
{
    __shared__ float tile[32][33];
    int c0 = blockIdx.x * 32, r0 = blockIdx.y * 32;
    int tx = threadIdx.x & 31, ty = threadIdx.x >> 5;
#pragma unroll
    for (int i = 0; i < 4; i++)
        tile[ty + 8 * i][tx] = in[(size_t)(r0 + ty + 8 * i) * C + c0 + tx];
    __syncthreads();
#pragma unroll
    for (int i = 0; i < 4; i++) {
        float v = tile[tx][ty + 8 * i];
        __nv_bfloat16 hv = __float2bfloat16(v);
        __nv_bfloat16 lv = __float2bfloat16(v - __bfloat162float(hv));
        size_t o = (size_t)(c0 + ty + 8 * i) * R + r0 + tx;
        h[o] = hv; l[o] = lv;
    }
}

// ---------------------------------------------------------------------------
// mma.sync split-bf16 GEMM (R7 version — proven fastest): C = A @ B^T + bias
// CTA 128x128x32, 8 warps (32m x 64n), double-buffered cp.async, 2 CTAs/SM.
// ---------------------------------------------------------------------------
#define GBM 128
#define GBN 128
#define GBK 32
#define NCH (KDIM / GBK)         // 64
#define ROWB 80
#define TILE_B (128 * ROWB)      // 10240
#define STAGE_B (4 * TILE_B)     // 40960 : [Ah][Al][Bh][Bl]
#define GEMM_SMEM (2 * STAGE_B)  // 81920

__global__ __launch_bounds__(256, 2)
void gemm_mma(const __nv_bfloat16* __restrict__ Ah0, const __nv_bfloat16* __restrict__ Al0,
              const __nv_bfloat16* __restrict__ Ah1, const __nv_bfloat16* __restrict__ Al1,
              const __nv_bfloat16* __restrict__ Bh, const __nv_bfloat16* __restrict__ Bl,
              const float* __restrict__ bias,
              float* __restrict__ Cf0, int ldc0, float* __restrict__ Cf1, int ldc1,
              __nv_bfloat16* __restrict__ Ch0, __nv_bfloat16* __restrict__ Cl0,
              __nv_bfloat16* __restrict__ Ch1, __nv_bfloat16* __restrict__ Cl1,
              int nsplit, int outmode)
{
    extern __shared__ char sm[];
    const uint32_t sbase = smem_to_u32(sm);
    const int tid  = threadIdx.x;
    const int lane = tid & 31;
    const int wid  = tid >> 5;
    const int wm   = (wid & 3) * 32;
    const int wn   = (wid >> 2) * 64;
    const int n0 = blockIdx.x * GBN;
    const int m0 = blockIdx.y * GBM;

    const __nv_bfloat16* Ah = (n0 < nsplit) ? Ah0 : Ah1;
    const __nv_bfloat16* Al = (n0 < nsplit) ? Al0 : Al1;

    float acc[2][8][4];
#pragma unroll
    for (int i = 0; i < 2; i++)
#pragma unroll
        for (int j = 0; j < 8; j++)
#pragma unroll
            for (int r = 0; r < 4; r++) acc[i][j][r] = 0.f;

    uint32_t aoff[2][2];
#pragma unroll
    for (int mf = 0; mf < 2; mf++)
#pragma unroll
        for (int ks = 0; ks < 2; ks++)
            aoff[mf][ks] = (uint32_t)((wm + mf * 16 + (lane & 15)) * ROWB
                                      + (ks * 16 + 8 * (lane >> 4)) * 2);
    uint32_t boff[4][2];
#pragma unroll
    for (int jj = 0; jj < 4; jj++)
#pragma unroll
        for (int ks = 0; ks < 2; ks++)
            boff[jj][ks] = (uint32_t)((wn + jj * 16 + (lane & 7) + 8 * (lane >> 4)) * ROWB
                                      + (ks * 16 + 8 * ((lane >> 3) & 1)) * 2);

    auto load_chunk = [&](int ic, int s) {
        const int k0 = ic * GBK;
#pragma unroll
        for (int it = 0; it < 8; it++) {
            const int tile   = it >> 1;
            const int within = (it & 1) * 256 + tid;
            const int row    = within >> 2;
            const int seg    = within & 3;
            const __nv_bfloat16* src;
            if (tile == 0)      src = Ah + (size_t)(m0 + row) * KDIM + k0 + seg * 8;
            else if (tile == 1) src = Al + (size_t)(m0 + row) * KDIM + k0 + seg * 8;
            else if (tile == 2) src = Bh + (size_t)(n0 + row) * KDIM + k0 + seg * 8;
            else                src = Bl + (size_t)(n0 + row) * KDIM + k0 + seg * 8;
            uint32_t dst = sbase + s * STAGE_B + tile * TILE_B + row * ROWB + seg * 16;
            CP_ASYNC16(dst, src);
        }
        CP_COMMIT();
    };

    load_chunk(0, 0);

    for (int ic = 0; ic < NCH; ic++) {
        const int s = ic & 1;
        if (ic + 1 < NCH) { load_chunk(ic + 1, s ^ 1); CP_WAIT(1); }
        else              { CP_WAIT(0); }
        __syncthreads();

        const uint32_t stage = sbase + s * STAGE_B;
#pragma unroll
        for (int pass = 0; pass < 3; pass++) {
            const uint32_t Abase = stage + ((pass == 2) ? TILE_B : 0);
            const uint32_t Bbase = stage + 2 * TILE_B + ((pass == 1) ? TILE_B : 0);
#pragma unroll
            for (int ks = 0; ks < 2; ks++) {
                uint32_t a[2][4];
                LDSM_X4(a[0][0], a[0][1], a[0][2], a[0][3], Abase + aoff[0][ks]);
                LDSM_X4(a[1][0], a[1][1], a[1][2], a[1][3], Abase + aoff[1][ks]);
#pragma unroll
                for (int jj = 0; jj < 4; jj++) {
                    uint32_t b0, b1, b2, b3;
                    LDSM_X4(b0, b1, b2, b3, Bbase + boff[jj][ks]);
                    MMA16816(acc[0][jj * 2],     a[0], b0, b1);
                    MMA16816(acc[1][jj * 2],     a[1], b0, b1);
                    MMA16816(acc[0][jj * 2 + 1], a[0], b2, b3);
                    MMA16816(acc[1][jj * 2 + 1], a[1], b2, b3);
                }
            }
        }
        __syncthreads();
    }

    int ld, nc0;
    float* Cf; __nv_bfloat16 *Ch, *Cl;
    if (n0 < nsplit) { Cf = Cf0; Ch = Ch0; Cl = Cl0; ld = ldc0; nc0 = n0; }
    else             { Cf = Cf1; Ch = Ch1; Cl = Cl1; ld = ldc1; nc0 = n0 - nsplit; }

#pragma unroll
    for (int mf = 0; mf < 2; mf++) {
#pragma unroll
        for (int nf = 0; nf < 8; nf++) {
            const int nl = wn + nf * 8 + 2 * (lane & 3);
            const float bx = bias[n0 + nl];
            const float by = bias[n0 + nl + 1];
            const int m_up = m0 + wm + mf * 16 + (lane >> 2);
#pragma unroll
            for (int half = 0; half < 2; half++) {
                const int m = m_up + 8 * half;
                float v0 = acc[mf][nf][2 * half]     + bx;
                float v1 = acc[mf][nf][2 * half + 1] + by;
                if (outmode == 0) {
                    float2 v; v.x = v0; v.y = v1;
                    *(float2*)(Cf + (size_t)m * ld + nc0 + nl) = v;
                } else {
                    uint32_t hi = packbf(v0, v1);
                    uint32_t lo = packbf(v0 - bflo_f(hi), v1 - bfhi_f(hi));
                    *(uint32_t*)(Ch + (size_t)m * ld + nc0 + nl) = hi;
                    *(uint32_t*)(Cl + (size_t)m * ld + nc0 + nl) = lo;
                }
            }
        }
    }
}

// ---------------------------------------------------------------------------
// Tensor-core flash attention (split-bf16, 3-pass) — R7 inner loop unchanged.
// Split-KV: blockIdx.z = half*BSZ + b; each CTA covers 1024 keys and writes
// unnormalized fp32 O + per-row (m, l) partials.
// ---------------------------------------------------------------------------
#define ASTR 272
#define Q_TILE (128 * ASTR)
#define KV_TILE (64 * ASTR)
#define KV_STAGE (4 * KV_TILE)
#define ATT_SMEM (2 * Q_TILE + 2 * KV_STAGE)
#define NTT (LSEQ / 64)          // 32 k-tiles total
#define NTH (NTT / 2)            // 16 per half

__global__ __launch_bounds__(256, 1)
void attn_mma(const __nv_bfloat16* __restrict__ Qh, const __nv_bfloat16* __restrict__ Ql,
              const __nv_bfloat16* __restrict__ KVh, const __nv_bfloat16* __restrict__ KVl,
              float* __restrict__ Opart, float* __restrict__ Mpart, float* __restrict__ Lpart)
{
    extern __shared__ char sm[];
    const uint32_t sQh = smem_to_u32(sm);
    const uint32_t sQl = sQh + Q_TILE;
    const uint32_t sKV = sQl + Q_TILE;

    const int tid  = threadIdx.x;
    const int lane = tid & 31;
    const int wid  = tid >> 5;
    const int wm   = wid * 16;

    const int qt = blockIdx.x, h = blockIdx.y;
    const int half = blockIdx.z / BSZ;
    const int b    = blockIdx.z % BSZ;
    const int qrow0 = b * LSEQ + qt * 128;
    const int hcol  = h * HDIM;
    const int jt0 = half * NTH, jtN = jt0 + NTH;

#pragma unroll
    for (int i = 0; i < 8; i++) {
        int idx = i * 256 + tid;
        int row = idx >> 5;
        int seg = idx & 31;
        // 8 segs of 16B per row over 2 iterations of the seg space
        // (row covers 0..63 here; do rows 64..127 in second half of idx)
        (void)row; (void)seg;
    }
    // Q load (identical addressing to R7)
#pragma unroll
    for (int i = 0; i < 8; i++) {
        int idx = i * 256 + tid;
        int row = idx >> 4, seg = idx & 15;
        size_t g = (size_t)(qrow0 + row) * DIMSZ + hcol + seg * 8;
        uint32_t d = row * ASTR + seg * 16;
        CP_ASYNC16(sQh + d, Qh + g);
        CP_ASYNC16(sQl + d, Ql + g);
    }
    CP_COMMIT();

    auto load_kv = [&](int jt, int s) {
        const uint32_t base = sKV + s * KV_STAGE;
        const int krow0 = b * LSEQ + jt * 64;
#pragma unroll
        for (int i = 0; i < 4; i++) {
            int idx = i * 256 + tid;
            int row = idx >> 4, seg = idx & 15;
            size_t roff = (size_t)(krow0 + row) * (2 * DIMSZ);
            uint32_t d = row * ASTR + seg * 16;
            CP_ASYNC16(base + d,               KVh + roff + hcol + seg * 8);
            CP_ASYNC16(base + KV_TILE + d,     KVl + roff + hcol + seg * 8);
            CP_ASYNC16(base + 2 * KV_TILE + d, KVh + roff + DIMSZ + hcol + seg * 8);
            CP_ASYNC16(base + 3 * KV_TILE + d, KVl + roff + DIMSZ + hcol + seg * 8);
        }
        CP_COMMIT();
    };
    load_kv(jt0, 0);

    const uint32_t ab = (uint32_t)((wm + (lane & 15)) * ASTR + (lane >> 4) * 16);
    const uint32_t kb = (uint32_t)(((lane & 7) + 8 * (lane >> 4)) * ASTR
                                   + ((lane >> 3) & 1) * 16);
    const uint32_t vb = (uint32_t)(((lane & 7) + 8 * ((lane >> 3) & 1)) * ASTR
                                   + (lane >> 4) * 16);

    float oacc[16][4];
#pragma unroll
    for (int f = 0; f < 16; f++)
#pragma unroll
        for (int e = 0; e < 4; e++) oacc[f][e] = 0.f;
    float m_prev[2] = {-3.0e38f, -3.0e38f};
    float l_acc[2]  = {0.f, 0.f};

    for (int jt = jt0; jt < jtN; jt++) {
        const int s = jt & 1;
        const bool has_next = (jt + 1 < jtN);
        if (has_next) load_kv(jt + 1, s ^ 1);
        if (has_next) { CP_WAIT(1); } else { CP_WAIT(0); }
        __syncthreads();

        const uint32_t sK  = sKV + s * KV_STAGE;
        const uint32_t sKl = sK + KV_TILE;
        const uint32_t sV  = sK + 2 * KV_TILE;
        const uint32_t sVl = sK + 3 * KV_TILE;

        float sacc[8][4];
#pragma unroll
        for (int f = 0; f < 8; f++)
#pragma unroll
            for (int e = 0; e < 4; e++) sacc[f][e] = 0.f;

#pragma unroll
        for (int ks = 0; ks < 8; ks++) {
            uint32_t ah[4], al[4];
            LDSM_X4(ah[0], ah[1], ah[2], ah[3], sQh + ab + ks * 32);
            LDSM_X4(al[0], al[1], al[2], al[3], sQl + ab + ks * 32);
#pragma unroll
            for (int jj = 0; jj < 4; jj++) {
                uint32_t h0, h1, h2, h3, l0, l1, l2, l3;
                LDSM_X4(h0, h1, h2, h3, sK  + kb + jj * (16 * ASTR) + ks * 32);
                LDSM_X4(l0, l1, l2, l3, sKl + kb + jj * (16 * ASTR) + ks * 32);
                MMA16816(sacc[2 * jj],     ah, h0, h1);
                MMA16816(sacc[2 * jj + 1], ah, h2, h3);
                MMA16816(sacc[2 * jj],     ah, l0, l1);
                MMA16816(sacc[2 * jj + 1], ah, l2, l3);
                MMA16816(sacc[2 * jj],     al, h0, h1);
                MMA16816(sacc[2 * jj + 1], al, h2, h3);
            }
        }

        float mx0 = -3.0e38f, mx1 = -3.0e38f;
#pragma unroll
        for (int f = 0; f < 8; f++) {
            sacc[f][0] *= SCALE_F; sacc[f][1] *= SCALE_F;
            sacc[f][2] *= SCALE_F; sacc[f][3] *= SCALE_F;
            mx0 = fmaxf(mx0, fmaxf(sacc[f][0], sacc[f][1]));
            mx1 = fmaxf(mx1, fmaxf(sacc[f][2], sacc[f][3]));
        }
        mx0 = fmaxf(mx0, __shfl_xor_sync(0xffffffffu, mx0, 1));
        mx0 = fmaxf(mx0, __shfl_xor_sync(0xffffffffu, mx0, 2));
        mx1 = fmaxf(mx1, __shfl_xor_sync(0xffffffffu, mx1, 1));
        mx1 = fmaxf(mx1, __shfl_xor_sync(0xffffffffu, mx1, 2));

        float mnew0 = fmaxf(m_prev[0], mx0);
        float mnew1 = fmaxf(m_prev[1], mx1);
        float er0 = __expf(m_prev[0] - mnew0);
        float er1 = __expf(m_prev[1] - mnew1);
        m_prev[0] = mnew0; m_prev[1] = mnew1;

        float rsum0 = 0.f, rsum1 = 0.f;
#pragma unroll
        for (int f = 0; f < 8; f++) {
            sacc[f][0] = __expf(sacc[f][0] - mnew0);
            sacc[f][1] = __expf(sacc[f][1] - mnew0);
            sacc[f][2] = __expf(sacc[f][2] - mnew1);
            sacc[f][3] = __expf(sacc[f][3] - mnew1);
            rsum0 += sacc[f][0] + sacc[f][1];
            rsum1 += sacc[f][2] + sacc[f][3];
        }
        rsum0 += __shfl_xor_sync(0xffffffffu, rsum0, 1);
        rsum0 += __shfl_xor_sync(0xffffffffu, rsum0, 2);
        rsum1 += __shfl_xor_sync(0xffffffffu, rsum1, 1);
        rsum1 += __shfl_xor_sync(0xffffffffu, rsum1, 2);
        l_acc[0] = l_acc[0] * er0 + rsum0;
        l_acc[1] = l_acc[1] * er1 + rsum1;

#pragma unroll
        for (int f = 0; f < 16; f++) {
            oacc[f][0] *= er0; oacc[f][1] *= er0;
            oacc[f][2] *= er1; oacc[f][3] *= er1;
        }

        uint32_t aph[4][4], apl[4][4];
#pragma unroll
        for (int t = 0; t < 4; t++) {
#pragma unroll
            for (int hh = 0; hh < 2; hh++) {
                const int f = 2 * t + hh;
                uint32_t u0 = packbf(sacc[f][0], sacc[f][1]);
                uint32_t u1 = packbf(sacc[f][2], sacc[f][3]);
                aph[t][2 * hh]     = u0;
                aph[t][2 * hh + 1] = u1;
                apl[t][2 * hh] =
                    packbf(sacc[f][0] - bflo_f(u0), sacc[f][1] - bfhi_f(u0));
                apl[t][2 * hh + 1] =
                    packbf(sacc[f][2] - bflo_f(u1), sacc[f][3] - bfhi_f(u1));
            }
        }

#pragma unroll
        for (int t = 0; t < 4; t++) {
#pragma unroll
            for (int g = 0; g < 8; g++) {
                uint32_t h0, h1, h2, h3, l0, l1, l2, l3;
                LDSM_X4_T(h0, h1, h2, h3, sV  + vb + t * (16 * ASTR) + g * 32);
                LDSM_X4_T(l0, l1, l2, l3, sVl + vb + t * (16 * ASTR) + g * 32);
                MMA16816(oacc[2 * g],     aph[t], h0, h1);
                MMA16816(oacc[2 * g + 1], aph[t], h2, h3);
                MMA16816(oacc[2 * g],     aph[t], l0, l1);
                MMA16816(oacc[2 * g + 1], aph[t], l2, l3);
                MMA16816(oacc[2 * g],     apl[t], h0, h1);
                MMA16816(oacc[2 * g + 1], apl[t], h2, h3);
            }
        }
        __syncthreads();
    }

    // ---- epilogue: write unnormalized fp32 O + per-row m, l partials ----
#pragma unroll
    for (int rs = 0; rs < 2; rs++) {
        const int lrow = qt * 128 + wm + (lane >> 2) + 8 * rs;
        const size_t orow = ((size_t)half * MROWS + b * LSEQ + lrow) * DIMSZ + hcol;
        if ((lane & 3) == 0) {
            size_t mi = (((size_t)half * BSZ + b) * NHEADS + h) * LSEQ + lrow;
            Mpart[mi] = m_prev[rs];
            Lpart[mi] = l_acc[rs];
        }
#pragma unroll
        for (int f = 0; f < 16; f++) {
            float2 v;
            v.x = oacc[f][2 * rs];
            v.y = oacc[f][2 * rs + 1];
            *(float2*)(Opart + orow + f * 8 + 2 * (lane & 3)) = v;
        }
    }
}

// ---------------------------------------------------------------------------
// Combine the two KV-halves: O = (O0*e^{m0-m} + O1*e^{m1-m}) / (l0*e.. + l1*e..)
// then split into bf16 hi/lo for the proj GEMM.
// ---------------------------------------------------------------------------
__global__ __launch_bounds__(256)
void attn_combine(const float* __restrict__ Opart,
                  const float* __restrict__ Mpart, const float* __restrict__ Lpart,
                  __nv_bfloat16* __restrict__ Oh, __nv_bfloat16* __restrict__ Ol)
{
    const size_t i = (size_t)blockIdx.x * 256 + threadIdx.x;   // per float4
    const size_t e = i * 4;
    const int row = (int)(e / DIMSZ);          // b*LSEQ + l
    const int col = (int)(e % DIMSZ);
    const int h = col >> 7;
    const int b = row / LSEQ;
    const int lr = row % LSEQ;

    const size_t mi0 = (((size_t)0 * BSZ + b) * NHEADS + h) * LSEQ + lr;
    const size_t mi1 = (((size_t)1 * BSZ + b) * NHEADS + h) * LSEQ + lr;
    const float m0 = Mpart[mi0], m1 = Mpart[mi1];
    const float l0 = Lpart[mi0], l1 = Lpart[mi1];
    const float m  = fmaxf(m0, m1);
    const float e0 = __expf(m0 - m), e1 = __expf(m1 - m);
    const float inv = 1.0f / (l0 * e0 + l1 * e1);

    float4 a  = ((const float4*)Opart)[i];
    float4 c  = ((const float4*)(Opart + (size_t)MROWS * DIMSZ))[i];
    float v0 = (a.x * e0 + c.x * e1) * inv;
    float v1 = (a.y * e0 + c.y * e1) * inv;
    float v2 = (a.z * e0 + c.z * e1) * inv;
    float v3 = (a.w * e0 + c.w * e1) * inv;

    uint32_t h01 = packbf(v0, v1), h23 = packbf(v2, v3);
    uint32_t l01 = packbf(v0 - bflo_f(h01), v1 - bfhi_f(h01));
    uint32_t l23 = packbf(v2 - bflo_f(h23), v3 - bfhi_f(h23));
    ((uint32_t*)Oh)[2 * i] = h01; ((uint32_t*)Oh)[2 * i + 1] = h23;
    ((uint32_t*)Ol)[2 * i] = l01; ((uint32_t*)Ol)[2 * i + 1] = l23;
}

// ---------------------------------------------------------------------------
extern "C" void kernel_launch(void* const* d_in, const int* in_sizes, int n_in,
                              void* d_out, int out_size)
{
    const float* x       = (const float*)d_in[0];
    const float* context = (const float*)d_in[1];
    const float* W_qkv   = (const float*)d_in[2];
    const float* b_qkv   = (const float*)d_in[3];
    const float* W_proj  = (const float*)d_in[4];
    const float* b_proj  = (const float*)d_in[5];
    float* out = (float*)d_out;

    __nv_bfloat16 *xh, *xl, *ch, *cl, *wqh, *wql, *wph, *wpl;
    __nv_bfloat16 *qh, *ql, *kvh, *kvl, *ath, *atl;
    float *opart, *mpart, *lpart;
    cudaGetSymbolAddress((void**)&xh,  g_xh);  cudaGetSymbolAddress((void**)&xl,  g_xl);
    cudaGetSymbolAddress((void**)&ch,  g_ch);  cudaGetSymbolAddress((void**)&cl,  g_cl);
    cudaGetSymbolAddress((void**)&wqh, g_wqh); cudaGetSymbolAddress((void**)&wql, g_wql);
    cudaGetSymbolAddress((void**)&wph, g_wph); cudaGetSymbolAddress((void**)&wpl, g_wpl);
    cudaGetSymbolAddress((void**)&qh,  g_qh);  cudaGetSymbolAddress((void**)&ql,  g_ql);
    cudaGetSymbolAddress((void**)&kvh, g_kvh); cudaGetSymbolAddress((void**)&kvl, g_kvl);
    cudaGetSymbolAddress((void**)&ath, g_ath); cudaGetSymbolAddress((void**)&atl, g_atl);
    cudaGetSymbolAddress((void**)&opart, g_opart);
    cudaGetSymbolAddress((void**)&mpart, g_mpart);
    cudaGetSymbolAddress((void**)&lpart, g_lpart);

    cudaFuncSetAttribute(gemm_mma, cudaFuncAttributeMaxDynamicSharedMemorySize, GEMM_SMEM);
    cudaFuncSetAttribute(attn_mma, cudaFuncAttributeMaxDynamicSharedMemorySize, ATT_SMEM);

    const int n4 = MROWS * DIMSZ / 4;

    split_fp32<<<(n4 + 255) / 256, 256>>>(x, xh, xl, n4);
    split_fp32<<<(n4 + 255) / 256, 256>>>(context, ch, cl, n4);
    transpose_split<<<dim3(3 * DIMSZ / 32, DIMSZ / 32), 256>>>(W_qkv, wqh, wql, DIMSZ, 3 * DIMSZ);
    transpose_split<<<dim3(DIMSZ / 32, DIMSZ / 32), 256>>>(W_proj, wph, wpl, DIMSZ, DIMSZ);

    gemm_mma<<<dim3(3 * DIMSZ / GBN, MROWS / GBM), 256, GEMM_SMEM>>>(
        xh, xl, ch, cl, wqh, wql, b_qkv,
        nullptr, DIMSZ, nullptr, 2 * DIMSZ,
        qh, ql, kvh, kvl, DIMSZ, 1);

    // split-KV attention: grid (qt=16, h=16, half*BSZ+b=4) = 1024 CTAs
    attn_mma<<<dim3(LSEQ / 128, NHEADS, 2 * BSZ), 256, ATT_SMEM>>>(
        qh, ql, kvh, kvl, opart, mpart, lpart);

    attn_combine<<<(n4 + 255) / 256, 256>>>(opart, mpart, lpart, ath, atl);

    gemm_mma<<<dim3(DIMSZ / GBN, MROWS / GBM), 256, GEMM_SMEM>>>(
        ath, atl, ath, atl, wph, wpl, b_proj,
        out, DIMSZ, out, DIMSZ,
        nullptr, nullptr, nullptr, nullptr, 1 << 30, 0);
}

// round 11
// speedup vs baseline: 1.3949x; 1.2871x over previous
#include <cuda_runtime.h>
#include <cuda_fp16.h>
#include <cstdint>

#define DIMSZ 2048
#define NHEADS 16
#define HDIM 128
#define BSZ 2
#define LSEQ 2048
#define MROWS (BSZ * LSEQ)   // 4096
#define KDIM 2048
#define SCALE_F 0.08838834764831845f

// ---------------------------------------------------------------------------
// Scratch (__device__ globals; no allocation allowed)
// ---------------------------------------------------------------------------
__device__ __half g_xh[(size_t)MROWS * DIMSZ];              // activations: hi only
__device__ __half g_ch[(size_t)MROWS * DIMSZ];
__device__ __half g_wqh[(size_t)3 * DIMSZ * DIMSZ];         // W_qkv^T hi/lo
__device__ __half g_wql[(size_t)3 * DIMSZ * DIMSZ];
__device__ __half g_wph[(size_t)DIMSZ * DIMSZ];             // W_proj^T hi/lo
__device__ __half g_wpl[(size_t)DIMSZ * DIMSZ];
__device__ __half g_qh[(size_t)MROWS * DIMSZ];              // q hi/lo (attention pairs)
__device__ __half g_ql[(size_t)MROWS * DIMSZ];
__device__ __half g_kvh[(size_t)MROWS * 2 * DIMSZ];
__device__ __half g_kvl[(size_t)MROWS * 2 * DIMSZ];
__device__ __half g_ath[(size_t)MROWS * DIMSZ];             // attn out: hi only
// split-KV partials
__device__ float g_opart[(size_t)2 * MROWS * DIMSZ];
__device__ float g_mpart[(size_t)2 * BSZ * NHEADS * LSEQ];
__device__ float g_lpart[(size_t)2 * BSZ * NHEADS * LSEQ];

// ---------------------------------------------------------------------------
// PTX helpers
// ---------------------------------------------------------------------------
__device__ __forceinline__ uint32_t smem_to_u32(const void* p) {
    uint32_t a;
    asm("{ .reg .u64 t; cvta.to.shared.u64 t, %1; cvt.u32.u64 %0, t; }" : "=r"(a) : "l"(p));
    return a;
}

#define CP_ASYNC16(dst, src) \
    asm volatile("cp.async.cg.shared.global [%0], [%1], 16;" :: "r"(dst), "l"(src) : "memory")
#define CP_COMMIT() asm volatile("cp.async.commit_group;" ::: "memory")
#define CP_WAIT(n)  asm volatile("cp.async.wait_group %0;" :: "n"(n) : "memory")

#define LDSM_X4(r0, r1, r2, r3, addr) \
    asm volatile("ldmatrix.sync.aligned.m8n8.x4.shared.b16 {%0,%1,%2,%3}, [%4];" \
                 : "=r"(r0), "=r"(r1), "=r"(r2), "=r"(r3) : "r"(addr))
#define LDSM_X4_T(r0, r1, r2, r3, addr) \
    asm volatile("ldmatrix.sync.aligned.m8n8.x4.trans.shared.b16 {%0,%1,%2,%3}, [%4];" \
                 : "=r"(r0), "=r"(r1), "=r"(r2), "=r"(r3) : "r"(addr))

#define MMA16816(d, a, b0, b1) \
    asm volatile("mma.sync.aligned.m16n8k16.row.col.f32.f16.f16.f32 " \
                 "{%0,%1,%2,%3}, {%4,%5,%6,%7}, {%8,%9}, {%0,%1,%2,%3};" \
                 : "+f"((d)[0]), "+f"((d)[1]), "+f"((d)[2]), "+f"((d)[3]) \
                 : "r"((a)[0]), "r"((a)[1]), "r"((a)[2]), "r"((a)[3]), \
                   "r"(b0), "r"(b1))

// pack two fp32 -> f16x2 {low half: first arg, high half: second arg}
__device__ __forceinline__ uint32_t packh(float lo, float hi) {
    uint32_t r;
    asm("cvt.rn.f16x2.f32 %0, %1, %2;" : "=r"(r) : "f"(hi), "f"(lo));
    return r;
}
__device__ __forceinline__ float hlo_f(uint32_t u) {
    unsigned short s = (unsigned short)(u & 0xffffu);
    float f; asm("cvt.f32.f16 %0, %1;" : "=f"(f) : "h"(s));
    return f;
}
__device__ __forceinline__ float hhi_f(uint32_t u) {
    unsigned short s = (unsigned short)(u >> 16);
    float f; asm("cvt.f32.f16 %0, %1;" : "=f"(f) : "h"(s));
    return f;
}

// ---------------------------------------------------------------------------
// Conversion kernels
// ---------------------------------------------------------------------------
// fp32 -> fp16 (hi only), vectorized
__global__ __launch_bounds__(256)
void split_one(const float* __restrict__ in, __half* __restrict__ h, int n4)
{
    int i = blockIdx.x * 256 + threadIdx.x;
    if (i >= n4) return;
    float4 v = ((const float4*)in)[i];
    ((uint32_t*)h)[2 * i]     = packh(v.x, v.y);
    ((uint32_t*)h)[2 * i + 1] = packh(v.z, v.w);
}

// in [R][C] fp32 row-major -> out [C][R] fp16 hi/lo (transposed)
__global__ __launch_bounds__(256)
void transpose_split(const float* __restrict__ in, __half* __restrict__ h,
                     __half* __restrict__ l, int R, int C)
{
    __shared__ float tile[32][33];
    int c0 = blockIdx.x * 32, r0 = blockIdx.y * 32;
    int tx = threadIdx.x & 31, ty = threadIdx.x >> 5;
#pragma unroll
    for (int i = 0; i < 4; i++)
        tile[ty + 8 * i][tx] = in[(size_t)(r0 + ty + 8 * i) * C + c0 + tx];
    __syncthreads();
#pragma unroll
    for (int i = 0; i < 4; i++) {
        float v = tile[tx][ty + 8 * i];
        __half hv = __float2half(v);
        __half lv = __float2half(v - __half2float(hv));
        size_t o = (size_t)(c0 + ty + 8 * i) * R + r0 + tx;
        h[o] = hv; l[o] = lv;
    }
}

// ---------------------------------------------------------------------------
// fp16 2-pass GEMM: C = A @ B^T + bias,  C ≈ Ah·Bh + Ah·Bl  (A hi-only)
// CTA 128x128x32, 8 warps (32m x 64n), double-buffered cp.async, 2 CTAs/SM.
// ---------------------------------------------------------------------------
#define GBM 128
#define GBN 128
#define GBK 32
#define NCH (KDIM / GBK)         // 64
#define ROWB 80
#define ATB (128 * ROWB)         // 10240 (A hi tile)
#define BTB (128 * ROWB)         // 10240 (each of Bh, Bl)
#define STAGE_B (ATB + 2 * BTB)  // 30720 : [Ah][Bh][Bl]
#define GEMM_SMEM (2 * STAGE_B)  // 61440

__global__ __launch_bounds__(256, 2)
void gemm_mma(const __half* __restrict__ Ah0, const __half* __restrict__ Ah1,
              const __half* __restrict__ Bh, const __half* __restrict__ Bl,
              const float* __restrict__ bias,
              float* __restrict__ Cf0, int ldc0, float* __restrict__ Cf1, int ldc1,
              __half* __restrict__ Ch0, __half* __restrict__ Cl0,
              __half* __restrict__ Ch1, __half* __restrict__ Cl1,
              int nsplit, int outmode)
{
    extern __shared__ char sm[];
    const uint32_t sbase = smem_to_u32(sm);
    const int tid  = threadIdx.x;
    const int lane = tid & 31;
    const int wid  = tid >> 5;
    const int wm   = (wid & 3) * 32;
    const int wn   = (wid >> 2) * 64;
    const int n0 = blockIdx.x * GBN;
    const int m0 = blockIdx.y * GBM;

    const __half* Ah = (n0 < nsplit) ? Ah0 : Ah1;

    float acc[2][8][4];
#pragma unroll
    for (int i = 0; i < 2; i++)
#pragma unroll
        for (int j = 0; j < 8; j++)
#pragma unroll
            for (int r = 0; r < 4; r++) acc[i][j][r] = 0.f;

    uint32_t aoff[2][2];
#pragma unroll
    for (int mf = 0; mf < 2; mf++)
#pragma unroll
        for (int ks = 0; ks < 2; ks++)
            aoff[mf][ks] = (uint32_t)((wm + mf * 16 + (lane & 15)) * ROWB
                                      + (ks * 16 + 8 * (lane >> 4)) * 2);
    uint32_t boff[4][2];
#pragma unroll
    for (int jj = 0; jj < 4; jj++)
#pragma unroll
        for (int ks = 0; ks < 2; ks++)
            boff[jj][ks] = (uint32_t)((wn + jj * 16 + (lane & 7) + 8 * (lane >> 4)) * ROWB
                                      + (ks * 16 + 8 * ((lane >> 3) & 1)) * 2);

    auto load_chunk = [&](int ic, int s) {
        const int k0 = ic * GBK;
#pragma unroll
        for (int it = 0; it < 6; it++) {
            const int idx = (it & 1) * 256 + tid;   // 0..511
            const int row = idx >> 2, seg = idx & 3;
            const __half* src;
            uint32_t dst;
            if (it < 2) {
                src = Ah + (size_t)(m0 + row) * KDIM + k0 + seg * 8;
                dst = sbase + s * STAGE_B + row * ROWB + seg * 16;
            } else if (it < 4) {
                src = Bh + (size_t)(n0 + row) * KDIM + k0 + seg * 8;
                dst = sbase + s * STAGE_B + ATB + row * ROWB + seg * 16;
            } else {
                src = Bl + (size_t)(n0 + row) * KDIM + k0 + seg * 8;
                dst = sbase + s * STAGE_B + ATB + BTB + row * ROWB + seg * 16;
            }
            CP_ASYNC16(dst, src);
        }
        CP_COMMIT();
    };

    load_chunk(0, 0);

    for (int ic = 0; ic < NCH; ic++) {
        const int s = ic & 1;
        if (ic + 1 < NCH) { load_chunk(ic + 1, s ^ 1); CP_WAIT(1); }
        else              { CP_WAIT(0); }
        __syncthreads();

        const uint32_t stage = sbase + s * STAGE_B;
#pragma unroll
        for (int ks = 0; ks < 2; ks++) {
            uint32_t a[2][4];
            LDSM_X4(a[0][0], a[0][1], a[0][2], a[0][3], stage + aoff[0][ks]);
            LDSM_X4(a[1][0], a[1][1], a[1][2], a[1][3], stage + aoff[1][ks]);
#pragma unroll
            for (int pass = 0; pass < 2; pass++) {
                const uint32_t Bbase = stage + ATB + pass * BTB;
#pragma unroll
                for (int jj = 0; jj < 4; jj++) {
                    uint32_t b0, b1, b2, b3;
                    LDSM_X4(b0, b1, b2, b3, Bbase + boff[jj][ks]);
                    MMA16816(acc[0][jj * 2],     a[0], b0, b1);
                    MMA16816(acc[1][jj * 2],     a[1], b0, b1);
                    MMA16816(acc[0][jj * 2 + 1], a[0], b2, b3);
                    MMA16816(acc[1][jj * 2 + 1], a[1], b2, b3);
                }
            }
        }
        __syncthreads();
    }

    int ld, nc0;
    float* Cf; __half *Ch, *Cl;
    if (n0 < nsplit) { Cf = Cf0; Ch = Ch0; Cl = Cl0; ld = ldc0; nc0 = n0; }
    else             { Cf = Cf1; Ch = Ch1; Cl = Cl1; ld = ldc1; nc0 = n0 - nsplit; }

#pragma unroll
    for (int mf = 0; mf < 2; mf++) {
#pragma unroll
        for (int nf = 0; nf < 8; nf++) {
            const int nl = wn + nf * 8 + 2 * (lane & 3);
            const float bx = bias[n0 + nl];
            const float by = bias[n0 + nl + 1];
            const int m_up = m0 + wm + mf * 16 + (lane >> 2);
#pragma unroll
            for (int half = 0; half < 2; half++) {
                const int m = m_up + 8 * half;
                float v0 = acc[mf][nf][2 * half]     + bx;
                float v1 = acc[mf][nf][2 * half + 1] + by;
                if (outmode == 0) {
                    float2 v; v.x = v0; v.y = v1;
                    *(float2*)(Cf + (size_t)m * ld + nc0 + nl) = v;
                } else {
                    uint32_t hi = packh(v0, v1);
                    uint32_t lo = packh(v0 - hlo_f(hi), v1 - hhi_f(hi));
                    *(uint32_t*)(Ch + (size_t)m * ld + nc0 + nl) = hi;
                    *(uint32_t*)(Cl + (size_t)m * ld + nc0 + nl) = lo;
                }
            }
        }
    }
}

// ---------------------------------------------------------------------------
// Tensor-core flash attention (fp16 split, 3-pass) — R10 structure, split-KV.
// ---------------------------------------------------------------------------
#define ASTR 272
#define Q_TILE (128 * ASTR)
#define KV_TILE (64 * ASTR)
#define KV_STAGE (4 * KV_TILE)
#define ATT_SMEM (2 * Q_TILE + 2 * KV_STAGE)
#define NTT (LSEQ / 64)
#define NTH (NTT / 2)

__global__ __launch_bounds__(256, 1)
void attn_mma(const __half* __restrict__ Qh, const __half* __restrict__ Ql,
              const __half* __restrict__ KVh, const __half* __restrict__ KVl,
              float* __restrict__ Opart, float* __restrict__ Mpart, float* __restrict__ Lpart)
{
    extern __shared__ char sm[];
    const uint32_t sQh = smem_to_u32(sm);
    const uint32_t sQl = sQh + Q_TILE;
    const uint32_t sKV = sQl + Q_TILE;

    const int tid  = threadIdx.x;
    const int lane = tid & 31;
    const int wid  = tid >> 5;
    const int wm   = wid * 16;

    const int qt = blockIdx.x, h = blockIdx.y;
    const int half = blockIdx.z / BSZ;
    const int b    = blockIdx.z % BSZ;
    const int qrow0 = b * LSEQ + qt * 128;
    const int hcol  = h * HDIM;
    const int jt0 = half * NTH, jtN = jt0 + NTH;

#pragma unroll
    for (int i = 0; i < 8; i++) {
        int idx = i * 256 + tid;
        int row = idx >> 4, seg = idx & 15;
        size_t g = (size_t)(qrow0 + row) * DIMSZ + hcol + seg * 8;
        uint32_t d = row * ASTR + seg * 16;
        CP_ASYNC16(sQh + d, Qh + g);
        CP_ASYNC16(sQl + d, Ql + g);
    }
    CP_COMMIT();

    auto load_kv = [&](int jt, int s) {
        const uint32_t base = sKV + s * KV_STAGE;
        const int krow0 = b * LSEQ + jt * 64;
#pragma unroll
        for (int i = 0; i < 4; i++) {
            int idx = i * 256 + tid;
            int row = idx >> 4, seg = idx & 15;
            size_t roff = (size_t)(krow0 + row) * (2 * DIMSZ);
            uint32_t d = row * ASTR + seg * 16;
            CP_ASYNC16(base + d,               KVh + roff + hcol + seg * 8);
            CP_ASYNC16(base + KV_TILE + d,     KVl + roff + hcol + seg * 8);
            CP_ASYNC16(base + 2 * KV_TILE + d, KVh + roff + DIMSZ + hcol + seg * 8);
            CP_ASYNC16(base + 3 * KV_TILE + d, KVl + roff + DIMSZ + hcol + seg * 8);
        }
        CP_COMMIT();
    };
    load_kv(jt0, 0);

    const uint32_t ab = (uint32_t)((wm + (lane & 15)) * ASTR + (lane >> 4) * 16);
    const uint32_t kb = (uint32_t)(((lane & 7) + 8 * (lane >> 4)) * ASTR
                                   + ((lane >> 3) & 1) * 16);
    const uint32_t vb = (uint32_t)(((lane & 7) + 8 * ((lane >> 3) & 1)) * ASTR
                                   + (lane >> 4) * 16);

    float oacc[16][4];
#pragma unroll
    for (int f = 0; f < 16; f++)
#pragma unroll
        for (int e = 0; e < 4; e++) oacc[f][e] = 0.f;
    float m_prev[2] = {-3.0e38f, -3.0e38f};
    float l_acc[2]  = {0.f, 0.f};

    for (int jt = jt0; jt < jtN; jt++) {
        const int s = jt & 1;
        const bool has_next = (jt + 1 < jtN);
        if (has_next) load_kv(jt + 1, s ^ 1);
        if (has_next) { CP_WAIT(1); } else { CP_WAIT(0); }
        __syncthreads();

        const uint32_t sK  = sKV + s * KV_STAGE;
        const uint32_t sKl = sK + KV_TILE;
        const uint32_t sV  = sK + 2 * KV_TILE;
        const uint32_t sVl = sK + 3 * KV_TILE;

        float sacc[8][4];
#pragma unroll
        for (int f = 0; f < 8; f++)
#pragma unroll
            for (int e = 0; e < 4; e++) sacc[f][e] = 0.f;

#pragma unroll
        for (int ks = 0; ks < 8; ks++) {
            uint32_t ah[4], al[4];
            LDSM_X4(ah[0], ah[1], ah[2], ah[3], sQh + ab + ks * 32);
            LDSM_X4(al[0], al[1], al[2], al[3], sQl + ab + ks * 32);
#pragma unroll
            for (int jj = 0; jj < 4; jj++) {
                uint32_t h0, h1, h2, h3, l0, l1, l2, l3;
                LDSM_X4(h0, h1, h2, h3, sK  + kb + jj * (16 * ASTR) + ks * 32);
                LDSM_X4(l0, l1, l2, l3, sKl + kb + jj * (16 * ASTR) + ks * 32);
                MMA16816(sacc[2 * jj],     ah, h0, h1);
                MMA16816(sacc[2 * jj + 1], ah, h2, h3);
                MMA16816(sacc[2 * jj],     ah, l0, l1);
                MMA16816(sacc[2 * jj + 1], ah, l2, l3);
                MMA16816(sacc[2 * jj],     al, h0, h1);
                MMA16816(sacc[2 * jj + 1], al, h2, h3);
            }
        }

        float mx0 = -3.0e38f, mx1 = -3.0e38f;
#pragma unroll
        for (int f = 0; f < 8; f++) {
            sacc[f][0] *= SCALE_F; sacc[f][1] *= SCALE_F;
            sacc[f][2] *= SCALE_F; sacc[f][3] *= SCALE_F;
            mx0 = fmaxf(mx0, fmaxf(sacc[f][0], sacc[f][1]));
            mx1 = fmaxf(mx1, fmaxf(sacc[f][2], sacc[f][3]));
        }
        mx0 = fmaxf(mx0, __shfl_xor_sync(0xffffffffu, mx0, 1));
        mx0 = fmaxf(mx0, __shfl_xor_sync(0xffffffffu, mx0, 2));
        mx1 = fmaxf(mx1, __shfl_xor_sync(0xffffffffu, mx1, 1));
        mx1 = fmaxf(mx1, __shfl_xor_sync(0xffffffffu, mx1, 2));

        float mnew0 = fmaxf(m_prev[0], mx0);
        float mnew1 = fmaxf(m_prev[1], mx1);
        float er0 = __expf(m_prev[0] - mnew0);
        float er1 = __expf(m_prev[1] - mnew1);
        m_prev[0] = mnew0; m_prev[1] = mnew1;

        float rsum0 = 0.f, rsum1 = 0.f;
#pragma unroll
        for (int f = 0; f < 8; f++) {
            sacc[f][0] = __expf(sacc[f][0] - mnew0);
            sacc[f][1] = __expf(sacc[f][1] - mnew0);
            sacc[f][2] = __expf(sacc[f][2] - mnew1);
            sacc[f][3] = __expf(sacc[f][3] - mnew1);
            rsum0 += sacc[f][0] + sacc[f][1];
            rsum1 += sacc[f][2] + sacc[f][3];
        }
        rsum0 += __shfl_xor_sync(0xffffffffu, rsum0, 1);
        rsum0 += __shfl_xor_sync(0xffffffffu, rsum0, 2);
        rsum1 += __shfl_xor_sync(0xffffffffu, rsum1, 1);
        rsum1 += __shfl_xor_sync(0xffffffffu, rsum1, 2);
        l_acc[0] = l_acc[0] * er0 + rsum0;
        l_acc[1] = l_acc[1] * er1 + rsum1;

#pragma unroll
        for (int f = 0; f < 16; f++) {
            oacc[f][0] *= er0; oacc[f][1] *= er0;
            oacc[f][2] *= er1; oacc[f][3] *= er1;
        }

        uint32_t aph[4][4], apl[4][4];
#pragma unroll
        for (int t = 0; t < 4; t++) {
#pragma unroll
            for (int hh = 0; hh < 2; hh++) {
                const int f = 2 * t + hh;
                uint32_t u0 = packh(sacc[f][0], sacc[f][1]);
                uint32_t u1 = packh(sacc[f][2], sacc[f][3]);
                aph[t][2 * hh]     = u0;
                aph[t][2 * hh + 1] = u1;
                apl[t][2 * hh] =
                    packh(sacc[f][0] - hlo_f(u0), sacc[f][1] - hhi_f(u0));
                apl[t][2 * hh + 1] =
                    packh(sacc[f][2] - hlo_f(u1), sacc[f][3] - hhi_f(u1));
            }
        }

#pragma unroll
        for (int t = 0; t < 4; t++) {
#pragma unroll
            for (int g = 0; g < 8; g++) {
                uint32_t h0, h1, h2, h3, l0, l1, l2, l3;
                LDSM_X4_T(h0, h1, h2, h3, sV  + vb + t * (16 * ASTR) + g * 32);
                LDSM_X4_T(l0, l1, l2, l3, sVl + vb + t * (16 * ASTR) + g * 32);
                MMA16816(oacc[2 * g],     aph[t], h0, h1);
                MMA16816(oacc[2 * g + 1], aph[t], h2, h3);
                MMA16816(oacc[2 * g],     aph[t], l0, l1);
                MMA16816(oacc[2 * g + 1], aph[t], l2, l3);
                MMA16816(oacc[2 * g],     apl[t], h0, h1);
                MMA16816(oacc[2 * g + 1], apl[t], h2, h3);
            }
        }
        __syncthreads();
    }

#pragma unroll
    for (int rs = 0; rs < 2; rs++) {
        const int lrow = qt * 128 + wm + (lane >> 2) + 8 * rs;
        const size_t orow = ((size_t)half * MROWS + b * LSEQ + lrow) * DIMSZ + hcol;
        if ((lane & 3) == 0) {
            size_t mi = (((size_t)half * BSZ + b) * NHEADS + h) * LSEQ + lrow;
            Mpart[mi] = m_prev[rs];
            Lpart[mi] = l_acc[rs];
        }
#pragma unroll
        for (int f = 0; f < 16; f++) {
            float2 v;
            v.x = oacc[f][2 * rs];
            v.y = oacc[f][2 * rs + 1];
            *(float2*)(Opart + orow + f * 8 + 2 * (lane & 3)) = v;
        }
    }
}

// ---------------------------------------------------------------------------
// Combine KV-halves -> fp16 hi-only output for proj GEMM
// ---------------------------------------------------------------------------
__global__ __launch_bounds__(256)
void attn_combine(const float* __restrict__ Opart,
                  const float* __restrict__ Mpart, const float* __restrict__ Lpart,
                  __half* __restrict__ Oh)
{
    const size_t i = (size_t)blockIdx.x * 256 + threadIdx.x;
    const size_t e = i * 4;
    const int row = (int)(e / DIMSZ);
    const int col = (int)(e % DIMSZ);
    const int h = col >> 7;
    const int b = row / LSEQ;
    const int lr = row % LSEQ;

    const size_t mi0 = (((size_t)0 * BSZ + b) * NHEADS + h) * LSEQ + lr;
    const size_t mi1 = (((size_t)1 * BSZ + b) * NHEADS + h) * LSEQ + lr;
    const float m0 = Mpart[mi0], m1 = Mpart[mi1];
    const float l0 = Lpart[mi0], l1 = Lpart[mi1];
    const float m  = fmaxf(m0, m1);
    const float e0 = __expf(m0 - m), e1 = __expf(m1 - m);
    const float inv = 1.0f / (l0 * e0 + l1 * e1);

    float4 a = ((const float4*)Opart)[i];
    float4 c = ((const float4*)(Opart + (size_t)MROWS * DIMSZ))[i];
    float v0 = (a.x * e0 + c.x * e1) * inv;
    float v1 = (a.y * e0 + c.y * e1) * inv;
    float v2 = (a.z * e0 + c.z * e1) * inv;
    float v3 = (a.w * e0 + c.w * e1) * inv;

    ((uint32_t*)Oh)[2 * i]     = packh(v0, v1);
    ((uint32_t*)Oh)[2 * i + 1] = packh(v2, v3);
}

// ---------------------------------------------------------------------------
extern "C" void kernel_launch(void* const* d_in, const int* in_sizes, int n_in,
                              void* d_out, int out_size)
{
    const float* x       = (const float*)d_in[0];
    const float* context = (const float*)d_in[1];
    const float* W_qkv   = (const float*)d_in[2];
    const float* b_qkv   = (const float*)d_in[3];
    const float* W_proj  = (const float*)d_in[4];
    const float* b_proj  = (const float*)d_in[5];
    float* out = (float*)d_out;

    __half *xh, *ch, *wqh, *wql, *wph, *wpl;
    __half *qh, *ql, *kvh, *kvl, *ath;
    float *opart, *mpart, *lpart;
    cudaGetSymbolAddress((void**)&xh,  g_xh);
    cudaGetSymbolAddress((void**)&ch,  g_ch);
    cudaGetSymbolAddress((void**)&wqh, g_wqh); cudaGetSymbolAddress((void**)&wql, g_wql);
    cudaGetSymbolAddress((void**)&wph, g_wph); cudaGetSymbolAddress((void**)&wpl, g_wpl);
    cudaGetSymbolAddress((void**)&qh,  g_qh);  cudaGetSymbolAddress((void**)&ql,  g_ql);
    cudaGetSymbolAddress((void**)&kvh, g_kvh); cudaGetSymbolAddress((void**)&kvl, g_kvl);
    cudaGetSymbolAddress((void**)&ath, g_ath);
    cudaGetSymbolAddress((void**)&opart, g_opart);
    cudaGetSymbolAddress((void**)&mpart, g_mpart);
    cudaGetSymbolAddress((void**)&lpart, g_lpart);

    cudaFuncSetAttribute(gemm_mma, cudaFuncAttributeMaxDynamicSharedMemorySize, GEMM_SMEM);
    cudaFuncSetAttribute(attn_mma, cudaFuncAttributeMaxDynamicSharedMemorySize, ATT_SMEM);

    const int n4 = MROWS * DIMSZ / 4;

    split_one<<<(n4 + 255) / 256, 256>>>(x, xh, n4);
    split_one<<<(n4 + 255) / 256, 256>>>(context, ch, n4);
    transpose_split<<<dim3(3 * DIMSZ / 32, DIMSZ / 32), 256>>>(W_qkv, wqh, wql, DIMSZ, 3 * DIMSZ);
    transpose_split<<<dim3(DIMSZ / 32, DIMSZ / 32), 256>>>(W_proj, wph, wpl, DIMSZ, DIMSZ);

    // qkv GEMM (fp16 2-pass): q/kv written as fp16 hi/lo pairs
    gemm_mma<<<dim3(3 * DIMSZ / GBN, MROWS / GBM), 256, GEMM_SMEM>>>(
        xh, ch, wqh, wql, b_qkv,
        nullptr, DIMSZ, nullptr, 2 * DIMSZ,
        qh, ql, kvh, kvl, DIMSZ, 1);

    // split-KV attention (fp16 3-pass)
    attn_mma<<<dim3(LSEQ / 128, NHEADS, 2 * BSZ), 256, ATT_SMEM>>>(
        qh, ql, kvh, kvl, opart, mpart, lpart);

    attn_combine<<<(n4 + 255) / 256, 256>>>(opart, mpart, lpart, ath);

    // proj GEMM (fp16 2-pass, fp32 out)
    gemm_mma<<<dim3(DIMSZ / GBN, MROWS / GBM), 256, GEMM_SMEM>>>(
        ath, ath, wph, wpl, b_proj,
        out, DIMSZ, out, DIMSZ,
        nullptr, nullptr, nullptr, nullptr, 1 << 30, 0);
}

// round 12
// speedup vs baseline: 1.5139x; 1.0853x over previous
#include <cuda_runtime.h>
#include <cuda_fp16.h>
#include <cstdint>

#define DIMSZ 2048
#define NHEADS 16
#define HDIM 128
#define BSZ 2
#define LSEQ 2048
#define MROWS (BSZ * LSEQ)   // 4096
#define KDIM 2048
#define SCALE_F 0.08838834764831845f

// ---------------------------------------------------------------------------
// Scratch (__device__ globals; no allocation allowed)
// ---------------------------------------------------------------------------
__device__ __half g_xh[(size_t)MROWS * DIMSZ];              // activations: hi only
__device__ __half g_ch[(size_t)MROWS * DIMSZ];
__device__ __half g_wqh[(size_t)3 * DIMSZ * DIMSZ];         // W_qkv^T hi/lo
__device__ __half g_wql[(size_t)3 * DIMSZ * DIMSZ];
__device__ __half g_wph[(size_t)DIMSZ * DIMSZ];             // W_proj^T hi/lo
__device__ __half g_wpl[(size_t)DIMSZ * DIMSZ];
__device__ __half g_qh[(size_t)MROWS * DIMSZ];              // q hi (lo unused)
__device__ __half g_ql[(size_t)MROWS * DIMSZ];
__device__ __half g_kvh[(size_t)MROWS * 2 * DIMSZ];
__device__ __half g_kvl[(size_t)MROWS * 2 * DIMSZ];
__device__ __half g_ath[(size_t)MROWS * DIMSZ];             // attn out: hi only
// split-KV partials
__device__ float g_opart[(size_t)2 * MROWS * DIMSZ];
__device__ float g_mpart[(size_t)2 * BSZ * NHEADS * LSEQ];
__device__ float g_lpart[(size_t)2 * BSZ * NHEADS * LSEQ];

// ---------------------------------------------------------------------------
// PTX helpers
// ---------------------------------------------------------------------------
__device__ __forceinline__ uint32_t smem_to_u32(const void* p) {
    uint32_t a;
    asm("{ .reg .u64 t; cvta.to.shared.u64 t, %1; cvt.u32.u64 %0, t; }" : "=r"(a) : "l"(p));
    return a;
}

#define CP_ASYNC16(dst, src) \
    asm volatile("cp.async.cg.shared.global [%0], [%1], 16;" :: "r"(dst), "l"(src) : "memory")
#define CP_COMMIT() asm volatile("cp.async.commit_group;" ::: "memory")
#define CP_WAIT(n)  asm volatile("cp.async.wait_group %0;" :: "n"(n) : "memory")

#define LDSM_X4(r0, r1, r2, r3, addr) \
    asm volatile("ldmatrix.sync.aligned.m8n8.x4.shared.b16 {%0,%1,%2,%3}, [%4];" \
                 : "=r"(r0), "=r"(r1), "=r"(r2), "=r"(r3) : "r"(addr))
#define LDSM_X4_T(r0, r1, r2, r3, addr) \
    asm volatile("ldmatrix.sync.aligned.m8n8.x4.trans.shared.b16 {%0,%1,%2,%3}, [%4];" \
                 : "=r"(r0), "=r"(r1), "=r"(r2), "=r"(r3) : "r"(addr))

#define MMA16816(d, a, b0, b1) \
    asm volatile("mma.sync.aligned.m16n8k16.row.col.f32.f16.f16.f32 " \
                 "{%0,%1,%2,%3}, {%4,%5,%6,%7}, {%8,%9}, {%0,%1,%2,%3};" \
                 : "+f"((d)[0]), "+f"((d)[1]), "+f"((d)[2]), "+f"((d)[3]) \
                 : "r"((a)[0]), "r"((a)[1]), "r"((a)[2]), "r"((a)[3]), \
                   "r"(b0), "r"(b1))

__device__ __forceinline__ uint32_t packh(float lo, float hi) {
    uint32_t r;
    asm("cvt.rn.f16x2.f32 %0, %1, %2;" : "=r"(r) : "f"(hi), "f"(lo));
    return r;
}
__device__ __forceinline__ float hlo_f(uint32_t u) {
    unsigned short s = (unsigned short)(u & 0xffffu);
    float f; asm("cvt.f32.f16 %0, %1;" : "=f"(f) : "h"(s));
    return f;
}
__device__ __forceinline__ float hhi_f(uint32_t u) {
    unsigned short s = (unsigned short)(u >> 16);
    float f; asm("cvt.f32.f16 %0, %1;" : "=f"(f) : "h"(s));
    return f;
}

// ---------------------------------------------------------------------------
// Conversion kernels
// ---------------------------------------------------------------------------
__global__ __launch_bounds__(256)
void split_one(const float* __restrict__ in, __half* __restrict__ h, int n4)
{
    int i = blockIdx.x * 256 + threadIdx.x;
    if (i >= n4) return;
    float4 v = ((const float4*)in)[i];
    ((uint32_t*)h)[2 * i]     = packh(v.x, v.y);
    ((uint32_t*)h)[2 * i + 1] = packh(v.z, v.w);
}

__global__ __launch_bounds__(256)
void transpose_split(const float* __restrict__ in, __half* __restrict__ h,
                     __half* __restrict__ l, int R, int C)
{
    __shared__ float tile[32][33];
    int c0 = blockIdx.x * 32, r0 = blockIdx.y * 32;
    int tx = threadIdx.x & 31, ty = threadIdx.x >> 5;
#pragma unroll
    for (int i = 0; i < 4; i++)
        tile[ty + 8 * i][tx] = in[(size_t)(r0 + ty + 8 * i) * C + c0 + tx];
    __syncthreads();
#pragma unroll
    for (int i = 0; i < 4; i++) {
        float v = tile[tx][ty + 8 * i];
        __half hv = __float2half(v);
        __half lv = __float2half(v - __half2float(hv));
        size_t o = (size_t)(c0 + ty + 8 * i) * R + r0 + tx;
        h[o] = hv; l[o] = lv;
    }
}

// ---------------------------------------------------------------------------
// fp16 2-pass GEMM: C = A @ B^T + bias,  C ≈ Ah·Bh + Ah·Bl  (A hi-only)
// CTA 128x128x32, 8 warps (32m x 64n), double-buffered cp.async, 2 CTAs/SM.
// ---------------------------------------------------------------------------
#define GBM 128
#define GBN 128
#define GBK 32
#define NCH (KDIM / GBK)         // 64
#define ROWB 80
#define ATB (128 * ROWB)         // 10240
#define BTB (128 * ROWB)         // 10240
#define STAGE_B (ATB + 2 * BTB)  // 30720 : [Ah][Bh][Bl]
#define GEMM_SMEM (2 * STAGE_B)  // 61440

__global__ __launch_bounds__(256, 2)
void gemm_mma(const __half* __restrict__ Ah0, const __half* __restrict__ Ah1,
              const __half* __restrict__ Bh, const __half* __restrict__ Bl,
              const float* __restrict__ bias,
              float* __restrict__ Cf0, int ldc0, float* __restrict__ Cf1, int ldc1,
              __half* __restrict__ Ch0, __half* __restrict__ Cl0,
              __half* __restrict__ Ch1, __half* __restrict__ Cl1,
              int nsplit, int outmode)
{
    extern __shared__ char sm[];
    const uint32_t sbase = smem_to_u32(sm);
    const int tid  = threadIdx.x;
    const int lane = tid & 31;
    const int wid  = tid >> 5;
    const int wm   = (wid & 3) * 32;
    const int wn   = (wid >> 2) * 64;
    const int n0 = blockIdx.x * GBN;
    const int m0 = blockIdx.y * GBM;

    const __half* Ah = (n0 < nsplit) ? Ah0 : Ah1;

    float acc[2][8][4];
#pragma unroll
    for (int i = 0; i < 2; i++)
#pragma unroll
        for (int j = 0; j < 8; j++)
#pragma unroll
            for (int r = 0; r < 4; r++) acc[i][j][r] = 0.f;

    uint32_t aoff[2][2];
#pragma unroll
    for (int mf = 0; mf < 2; mf++)
#pragma unroll
        for (int ks = 0; ks < 2; ks++)
            aoff[mf][ks] = (uint32_t)((wm + mf * 16 + (lane & 15)) * ROWB
                                      + (ks * 16 + 8 * (lane >> 4)) * 2);
    uint32_t boff[4][2];
#pragma unroll
    for (int jj = 0; jj < 4; jj++)
#pragma unroll
        for (int ks = 0; ks < 2; ks++)
            boff[jj][ks] = (uint32_t)((wn + jj * 16 + (lane & 7) + 8 * (lane >> 4)) * ROWB
                                      + (ks * 16 + 8 * ((lane >> 3) & 1)) * 2);

    auto load_chunk = [&](int ic, int s) {
        const int k0 = ic * GBK;
#pragma unroll
        for (int it = 0; it < 6; it++) {
            const int idx = (it & 1) * 256 + tid;
            const int row = idx >> 2, seg = idx & 3;
            const __half* src;
            uint32_t dst;
            if (it < 2) {
                src = Ah + (size_t)(m0 + row) * KDIM + k0 + seg * 8;
                dst = sbase + s * STAGE_B + row * ROWB + seg * 16;
            } else if (it < 4) {
                src = Bh + (size_t)(n0 + row) * KDIM + k0 + seg * 8;
                dst = sbase + s * STAGE_B + ATB + row * ROWB + seg * 16;
            } else {
                src = Bl + (size_t)(n0 + row) * KDIM + k0 + seg * 8;
                dst = sbase + s * STAGE_B + ATB + BTB + row * ROWB + seg * 16;
            }
            CP_ASYNC16(dst, src);
        }
        CP_COMMIT();
    };

    load_chunk(0, 0);

    for (int ic = 0; ic < NCH; ic++) {
        const int s = ic & 1;
        if (ic + 1 < NCH) { load_chunk(ic + 1, s ^ 1); CP_WAIT(1); }
        else              { CP_WAIT(0); }
        __syncthreads();

        const uint32_t stage = sbase + s * STAGE_B;
#pragma unroll
        for (int ks = 0; ks < 2; ks++) {
            uint32_t a[2][4];
            LDSM_X4(a[0][0], a[0][1], a[0][2], a[0][3], stage + aoff[0][ks]);
            LDSM_X4(a[1][0], a[1][1], a[1][2], a[1][3], stage + aoff[1][ks]);
#pragma unroll
            for (int pass = 0; pass < 2; pass++) {
                const uint32_t Bbase = stage + ATB + pass * BTB;
#pragma unroll
                for (int jj = 0; jj < 4; jj++) {
                    uint32_t b0, b1, b2, b3;
                    LDSM_X4(b0, b1, b2, b3, Bbase + boff[jj][ks]);
                    MMA16816(acc[0][jj * 2],     a[0], b0, b1);
                    MMA16816(acc[1][jj * 2],     a[1], b0, b1);
                    MMA16816(acc[0][jj * 2 + 1], a[0], b2, b3);
                    MMA16816(acc[1][jj * 2 + 1], a[1], b2, b3);
                }
            }
        }
        __syncthreads();
    }

    int ld, nc0;
    float* Cf; __half *Ch, *Cl;
    if (n0 < nsplit) { Cf = Cf0; Ch = Ch0; Cl = Cl0; ld = ldc0; nc0 = n0; }
    else             { Cf = Cf1; Ch = Ch1; Cl = Cl1; ld = ldc1; nc0 = n0 - nsplit; }

#pragma unroll
    for (int mf = 0; mf < 2; mf++) {
#pragma unroll
        for (int nf = 0; nf < 8; nf++) {
            const int nl = wn + nf * 8 + 2 * (lane & 3);
            const float bx = bias[n0 + nl];
            const float by = bias[n0 + nl + 1];
            const int m_up = m0 + wm + mf * 16 + (lane >> 2);
#pragma unroll
            for (int half = 0; half < 2; half++) {
                const int m = m_up + 8 * half;
                float v0 = acc[mf][nf][2 * half]     + bx;
                float v1 = acc[mf][nf][2 * half + 1] + by;
                if (outmode == 0) {
                    float2 v; v.x = v0; v.y = v1;
                    *(float2*)(Cf + (size_t)m * ld + nc0 + nl) = v;
                } else {
                    uint32_t hi = packh(v0, v1);
                    uint32_t lo = packh(v0 - hlo_f(hi), v1 - hhi_f(hi));
                    *(uint32_t*)(Ch + (size_t)m * ld + nc0 + nl) = hi;
                    *(uint32_t*)(Cl + (size_t)m * ld + nc0 + nl) = lo;
                }
            }
        }
    }
}

// ---------------------------------------------------------------------------
// Tensor-core flash attention (fp16, 2-pass), split-KV.
//   S = Qh (Kh + Kl);  O = Ph (Vh + Vl).  Q hi-only, P hi-only.
// ---------------------------------------------------------------------------
#define ASTR 272
#define Q_TILE (128 * ASTR)
#define KV_TILE (64 * ASTR)
#define KV_STAGE (4 * KV_TILE)
#define ATT_SMEM (Q_TILE + 2 * KV_STAGE)   // 174080
#define NTT (LSEQ / 64)
#define NTH (NTT / 2)

__global__ __launch_bounds__(256, 1)
void attn_mma(const __half* __restrict__ Qh,
              const __half* __restrict__ KVh, const __half* __restrict__ KVl,
              float* __restrict__ Opart, float* __restrict__ Mpart, float* __restrict__ Lpart)
{
    extern __shared__ char sm[];
    const uint32_t sQh = smem_to_u32(sm);
    const uint32_t sKV = sQh + Q_TILE;

    const int tid  = threadIdx.x;
    const int lane = tid & 31;
    const int wid  = tid >> 5;
    const int wm   = wid * 16;

    const int qt = blockIdx.x, h = blockIdx.y;
    const int half = blockIdx.z / BSZ;
    const int b    = blockIdx.z % BSZ;
    const int qrow0 = b * LSEQ + qt * 128;
    const int hcol  = h * HDIM;
    const int jt0 = half * NTH, jtN = jt0 + NTH;

    // Q load (hi only)
#pragma unroll
    for (int i = 0; i < 8; i++) {
        int idx = i * 256 + tid;
        int row = idx >> 4, seg = idx & 15;
        size_t g = (size_t)(qrow0 + row) * DIMSZ + hcol + seg * 8;
        CP_ASYNC16(sQh + row * ASTR + seg * 16, Qh + g);
    }
    CP_COMMIT();

    auto load_kv = [&](int jt, int s) {
        const uint32_t base = sKV + s * KV_STAGE;
        const int krow0 = b * LSEQ + jt * 64;
#pragma unroll
        for (int i = 0; i < 4; i++) {
            int idx = i * 256 + tid;
            int row = idx >> 4, seg = idx & 15;
            size_t roff = (size_t)(krow0 + row) * (2 * DIMSZ);
            uint32_t d = row * ASTR + seg * 16;
            CP_ASYNC16(base + d,               KVh + roff + hcol + seg * 8);
            CP_ASYNC16(base + KV_TILE + d,     KVl + roff + hcol + seg * 8);
            CP_ASYNC16(base + 2 * KV_TILE + d, KVh + roff + DIMSZ + hcol + seg * 8);
            CP_ASYNC16(base + 3 * KV_TILE + d, KVl + roff + DIMSZ + hcol + seg * 8);
        }
        CP_COMMIT();
    };
    load_kv(jt0, 0);

    const uint32_t ab = (uint32_t)((wm + (lane & 15)) * ASTR + (lane >> 4) * 16);
    const uint32_t kb = (uint32_t)(((lane & 7) + 8 * (lane >> 4)) * ASTR
                                   + ((lane >> 3) & 1) * 16);
    const uint32_t vb = (uint32_t)(((lane & 7) + 8 * ((lane >> 3) & 1)) * ASTR
                                   + (lane >> 4) * 16);

    float oacc[16][4];
#pragma unroll
    for (int f = 0; f < 16; f++)
#pragma unroll
        for (int e = 0; e < 4; e++) oacc[f][e] = 0.f;
    float m_prev[2] = {-3.0e38f, -3.0e38f};
    float l_acc[2]  = {0.f, 0.f};

    for (int jt = jt0; jt < jtN; jt++) {
        const int s = jt & 1;
        const bool has_next = (jt + 1 < jtN);
        if (has_next) load_kv(jt + 1, s ^ 1);
        if (has_next) { CP_WAIT(1); } else { CP_WAIT(0); }
        __syncthreads();

        const uint32_t sK  = sKV + s * KV_STAGE;
        const uint32_t sKl = sK + KV_TILE;
        const uint32_t sV  = sK + 2 * KV_TILE;
        const uint32_t sVl = sK + 3 * KV_TILE;

        // ---- S = Qh (Kh + Kl) ----
        float sacc[8][4];
#pragma unroll
        for (int f = 0; f < 8; f++)
#pragma unroll
            for (int e = 0; e < 4; e++) sacc[f][e] = 0.f;

#pragma unroll
        for (int ks = 0; ks < 8; ks++) {
            uint32_t ah[4];
            LDSM_X4(ah[0], ah[1], ah[2], ah[3], sQh + ab + ks * 32);
#pragma unroll
            for (int jj = 0; jj < 4; jj++) {
                uint32_t h0, h1, h2, h3, l0, l1, l2, l3;
                LDSM_X4(h0, h1, h2, h3, sK  + kb + jj * (16 * ASTR) + ks * 32);
                LDSM_X4(l0, l1, l2, l3, sKl + kb + jj * (16 * ASTR) + ks * 32);
                MMA16816(sacc[2 * jj],     ah, h0, h1);
                MMA16816(sacc[2 * jj + 1], ah, h2, h3);
                MMA16816(sacc[2 * jj],     ah, l0, l1);
                MMA16816(sacc[2 * jj + 1], ah, l2, l3);
            }
        }

        float mx0 = -3.0e38f, mx1 = -3.0e38f;
#pragma unroll
        for (int f = 0; f < 8; f++) {
            sacc[f][0] *= SCALE_F; sacc[f][1] *= SCALE_F;
            sacc[f][2] *= SCALE_F; sacc[f][3] *= SCALE_F;
            mx0 = fmaxf(mx0, fmaxf(sacc[f][0], sacc[f][1]));
            mx1 = fmaxf(mx1, fmaxf(sacc[f][2], sacc[f][3]));
        }
        mx0 = fmaxf(mx0, __shfl_xor_sync(0xffffffffu, mx0, 1));
        mx0 = fmaxf(mx0, __shfl_xor_sync(0xffffffffu, mx0, 2));
        mx1 = fmaxf(mx1, __shfl_xor_sync(0xffffffffu, mx1, 1));
        mx1 = fmaxf(mx1, __shfl_xor_sync(0xffffffffu, mx1, 2));

        float mnew0 = fmaxf(m_prev[0], mx0);
        float mnew1 = fmaxf(m_prev[1], mx1);
        float er0 = __expf(m_prev[0] - mnew0);
        float er1 = __expf(m_prev[1] - mnew1);
        m_prev[0] = mnew0; m_prev[1] = mnew1;

        float rsum0 = 0.f, rsum1 = 0.f;
#pragma unroll
        for (int f = 0; f < 8; f++) {
            sacc[f][0] = __expf(sacc[f][0] - mnew0);
            sacc[f][1] = __expf(sacc[f][1] - mnew0);
            sacc[f][2] = __expf(sacc[f][2] - mnew1);
            sacc[f][3] = __expf(sacc[f][3] - mnew1);
            rsum0 += sacc[f][0] + sacc[f][1];
            rsum1 += sacc[f][2] + sacc[f][3];
        }
        rsum0 += __shfl_xor_sync(0xffffffffu, rsum0, 1);
        rsum0 += __shfl_xor_sync(0xffffffffu, rsum0, 2);
        rsum1 += __shfl_xor_sync(0xffffffffu, rsum1, 1);
        rsum1 += __shfl_xor_sync(0xffffffffu, rsum1, 2);
        l_acc[0] = l_acc[0] * er0 + rsum0;
        l_acc[1] = l_acc[1] * er1 + rsum1;

#pragma unroll
        for (int f = 0; f < 16; f++) {
            oacc[f][0] *= er0; oacc[f][1] *= er0;
            oacc[f][2] *= er1; oacc[f][3] *= er1;
        }

        // ---- pack P (hi only) ----
        uint32_t aph[4][4];
#pragma unroll
        for (int t = 0; t < 4; t++) {
#pragma unroll
            for (int hh = 0; hh < 2; hh++) {
                const int f = 2 * t + hh;
                aph[t][2 * hh]     = packh(sacc[f][0], sacc[f][1]);
                aph[t][2 * hh + 1] = packh(sacc[f][2], sacc[f][3]);
            }
        }

        // ---- O += Ph (Vh + Vl) ----
#pragma unroll
        for (int t = 0; t < 4; t++) {
#pragma unroll
            for (int g = 0; g < 8; g++) {
                uint32_t h0, h1, h2, h3, l0, l1, l2, l3;
                LDSM_X4_T(h0, h1, h2, h3, sV  + vb + t * (16 * ASTR) + g * 32);
                LDSM_X4_T(l0, l1, l2, l3, sVl + vb + t * (16 * ASTR) + g * 32);
                MMA16816(oacc[2 * g],     aph[t], h0, h1);
                MMA16816(oacc[2 * g + 1], aph[t], h2, h3);
                MMA16816(oacc[2 * g],     aph[t], l0, l1);
                MMA16816(oacc[2 * g + 1], aph[t], l2, l3);
            }
        }
        __syncthreads();
    }

#pragma unroll
    for (int rs = 0; rs < 2; rs++) {
        const int lrow = qt * 128 + wm + (lane >> 2) + 8 * rs;
        const size_t orow = ((size_t)half * MROWS + b * LSEQ + lrow) * DIMSZ + hcol;
        if ((lane & 3) == 0) {
            size_t mi = (((size_t)half * BSZ + b) * NHEADS + h) * LSEQ + lrow;
            Mpart[mi] = m_prev[rs];
            Lpart[mi] = l_acc[rs];
        }
#pragma unroll
        for (int f = 0; f < 16; f++) {
            float2 v;
            v.x = oacc[f][2 * rs];
            v.y = oacc[f][2 * rs + 1];
            *(float2*)(Opart + orow + f * 8 + 2 * (lane & 3)) = v;
        }
    }
}

// ---------------------------------------------------------------------------
// Combine KV-halves -> fp16 hi-only output for proj GEMM
// ---------------------------------------------------------------------------
__global__ __launch_bounds__(256)
void attn_combine(const float* __restrict__ Opart,
                  const float* __restrict__ Mpart, const float* __restrict__ Lpart,
                  __half* __restrict__ Oh)
{
    const size_t i = (size_t)blockIdx.x * 256 + threadIdx.x;
    const size_t e = i * 4;
    const int row = (int)(e / DIMSZ);
    const int col = (int)(e % DIMSZ);
    const int h = col >> 7;
    const int b = row / LSEQ;
    const int lr = row % LSEQ;

    const size_t mi0 = (((size_t)0 * BSZ + b) * NHEADS + h) * LSEQ + lr;
    const size_t mi1 = (((size_t)1 * BSZ + b) * NHEADS + h) * LSEQ + lr;
    const float m0 = Mpart[mi0], m1 = Mpart[mi1];
    const float l0 = Lpart[mi0], l1 = Lpart[mi1];
    const float m  = fmaxf(m0, m1);
    const float e0 = __expf(m0 - m), e1 = __expf(m1 - m);
    const float inv = 1.0f / (l0 * e0 + l1 * e1);

    float4 a = ((const float4*)Opart)[i];
    float4 c = ((const float4*)(Opart + (size_t)MROWS * DIMSZ))[i];
    float v0 = (a.x * e0 + c.x * e1) * inv;
    float v1 = (a.y * e0 + c.y * e1) * inv;
    float v2 = (a.z * e0 + c.z * e1) * inv;
    float v3 = (a.w * e0 + c.w * e1) * inv;

    ((uint32_t*)Oh)[2 * i]     = packh(v0, v1);
    ((uint32_t*)Oh)[2 * i + 1] = packh(v2, v3);
}

// ---------------------------------------------------------------------------
extern "C" void kernel_launch(void* const* d_in, const int* in_sizes, int n_in,
                              void* d_out, int out_size)
{
    const float* x       = (const float*)d_in[0];
    const float* context = (const float*)d_in[1];
    const float* W_qkv   = (const float*)d_in[2];
    const float* b_qkv   = (const float*)d_in[3];
    const float* W_proj  = (const float*)d_in[4];
    const float* b_proj  = (const float*)d_in[5];
    float* out = (float*)d_out;

    __half *xh, *ch, *wqh, *wql, *wph, *wpl;
    __half *qh, *ql, *kvh, *kvl, *ath;
    float *opart, *mpart, *lpart;
    cudaGetSymbolAddress((void**)&xh,  g_xh);
    cudaGetSymbolAddress((void**)&ch,  g_ch);
    cudaGetSymbolAddress((void**)&wqh, g_wqh); cudaGetSymbolAddress((void**)&wql, g_wql);
    cudaGetSymbolAddress((void**)&wph, g_wph); cudaGetSymbolAddress((void**)&wpl, g_wpl);
    cudaGetSymbolAddress((void**)&qh,  g_qh);  cudaGetSymbolAddress((void**)&ql,  g_ql);
    cudaGetSymbolAddress((void**)&kvh, g_kvh); cudaGetSymbolAddress((void**)&kvl, g_kvl);
    cudaGetSymbolAddress((void**)&ath, g_ath);
    cudaGetSymbolAddress((void**)&opart, g_opart);
    cudaGetSymbolAddress((void**)&mpart, g_mpart);
    cudaGetSymbolAddress((void**)&lpart, g_lpart);

    cudaFuncSetAttribute(gemm_mma, cudaFuncAttributeMaxDynamicSharedMemorySize, GEMM_SMEM);
    cudaFuncSetAttribute(attn_mma, cudaFuncAttributeMaxDynamicSharedMemorySize, ATT_SMEM);

    const int n4 = MROWS * DIMSZ / 4;

    split_one<<<(n4 + 255) / 256, 256>>>(x, xh, n4);
    split_one<<<(n4 + 255) / 256, 256>>>(context, ch, n4);
    transpose_split<<<dim3(3 * DIMSZ / 32, DIMSZ / 32), 256>>>(W_qkv, wqh, wql, DIMSZ, 3 * DIMSZ);
    transpose_split<<<dim3(DIMSZ / 32, DIMSZ / 32), 256>>>(W_proj, wph, wpl, DIMSZ, DIMSZ);

    // qkv GEMM (fp16 2-pass): q/kv written as fp16 hi/lo pairs
    gemm_mma<<<dim3(3 * DIMSZ / GBN, MROWS / GBM), 256, GEMM_SMEM>>>(
        xh, ch, wqh, wql, b_qkv,
        nullptr, DIMSZ, nullptr, 2 * DIMSZ,
        qh, ql, kvh, kvl, DIMSZ, 1);

    // split-KV attention (fp16 2-pass)
    attn_mma<<<dim3(LSEQ / 128, NHEADS, 2 * BSZ), 256, ATT_SMEM>>>(
        qh, kvh, kvl, opart, mpart, lpart);

    attn_combine<<<(n4 + 255) / 256, 256>>>(opart, mpart, lpart, ath);

    // proj GEMM (fp16 2-pass, fp32 out)
    gemm_mma<<<dim3(DIMSZ / GBN, MROWS / GBM), 256, GEMM_SMEM>>>(
        ath, ath, wph, wpl, b_proj,
        out, DIMSZ, out, DIMSZ,
        nullptr, nullptr, nullptr, nullptr, 1 << 30, 0);
}

// round 13
// speedup vs baseline: 1.7488x; 1.1552x over previous
#include <cuda_runtime.h>
#include <cuda_fp16.h>
#include <cstdint>

#define DIMSZ 2048
#define NHEADS 16
#define HDIM 128
#define BSZ 2
#define LSEQ 2048
#define MROWS (BSZ * LSEQ)   // 4096
#define KDIM 2048
#define SCALE_F 0.08838834764831845f

// ---------------------------------------------------------------------------
// Scratch (__device__ globals; no allocation allowed)
// ---------------------------------------------------------------------------
__device__ __half g_xh[(size_t)MROWS * DIMSZ];              // activations: hi only
__device__ __half g_ch[(size_t)MROWS * DIMSZ];
__device__ __half g_wqh[(size_t)3 * DIMSZ * DIMSZ];         // W_qkv^T hi/lo
__device__ __half g_wql[(size_t)3 * DIMSZ * DIMSZ];
__device__ __half g_wph[(size_t)DIMSZ * DIMSZ];             // W_proj^T hi/lo
__device__ __half g_wpl[(size_t)DIMSZ * DIMSZ];
__device__ __half g_qh[(size_t)MROWS * DIMSZ];              // q fp16
__device__ __half g_kvh[(size_t)MROWS * 2 * DIMSZ];         // k|v fp16
__device__ __half g_ath[(size_t)MROWS * DIMSZ];             // attn out fp16
// split-KV partials
__device__ float g_opart[(size_t)2 * MROWS * DIMSZ];
__device__ float g_mpart[(size_t)2 * BSZ * NHEADS * LSEQ];
__device__ float g_lpart[(size_t)2 * BSZ * NHEADS * LSEQ];

// ---------------------------------------------------------------------------
// PTX helpers
// ---------------------------------------------------------------------------
__device__ __forceinline__ uint32_t smem_to_u32(const void* p) {
    uint32_t a;
    asm("{ .reg .u64 t; cvta.to.shared.u64 t, %1; cvt.u32.u64 %0, t; }" : "=r"(a) : "l"(p));
    return a;
}

#define CP_ASYNC16(dst, src) \
    asm volatile("cp.async.cg.shared.global [%0], [%1], 16;" :: "r"(dst), "l"(src) : "memory")
#define CP_COMMIT() asm volatile("cp.async.commit_group;" ::: "memory")
#define CP_WAIT(n)  asm volatile("cp.async.wait_group %0;" :: "n"(n) : "memory")

#define LDSM_X4(r0, r1, r2, r3, addr) \
    asm volatile("ldmatrix.sync.aligned.m8n8.x4.shared.b16 {%0,%1,%2,%3}, [%4];" \
                 : "=r"(r0), "=r"(r1), "=r"(r2), "=r"(r3) : "r"(addr))
#define LDSM_X4_T(r0, r1, r2, r3, addr) \
    asm volatile("ldmatrix.sync.aligned.m8n8.x4.trans.shared.b16 {%0,%1,%2,%3}, [%4];" \
                 : "=r"(r0), "=r"(r1), "=r"(r2), "=r"(r3) : "r"(addr))

#define MMA16816(d, a, b0, b1) \
    asm volatile("mma.sync.aligned.m16n8k16.row.col.f32.f16.f16.f32 " \
                 "{%0,%1,%2,%3}, {%4,%5,%6,%7}, {%8,%9}, {%0,%1,%2,%3};" \
                 : "+f"((d)[0]), "+f"((d)[1]), "+f"((d)[2]), "+f"((d)[3]) \
                 : "r"((a)[0]), "r"((a)[1]), "r"((a)[2]), "r"((a)[3]), \
                   "r"(b0), "r"(b1))

__device__ __forceinline__ uint32_t packh(float lo, float hi) {
    uint32_t r;
    asm("cvt.rn.f16x2.f32 %0, %1, %2;" : "=r"(r) : "f"(hi), "f"(lo));
    return r;
}
__device__ __forceinline__ float hlo_f(uint32_t u) {
    unsigned short s = (unsigned short)(u & 0xffffu);
    float f; asm("cvt.f32.f16 %0, %1;" : "=f"(f) : "h"(s));
    return f;
}
__device__ __forceinline__ float hhi_f(uint32_t u) {
    unsigned short s = (unsigned short)(u >> 16);
    float f; asm("cvt.f32.f16 %0, %1;" : "=f"(f) : "h"(s));
    return f;
}

// ---------------------------------------------------------------------------
// Conversion kernels
// ---------------------------------------------------------------------------
__global__ __launch_bounds__(256)
void split_one(const float* __restrict__ in, __half* __restrict__ h, int n4)
{
    int i = blockIdx.x * 256 + threadIdx.x;
    if (i >= n4) return;
    float4 v = ((const float4*)in)[i];
    ((uint32_t*)h)[2 * i]     = packh(v.x, v.y);
    ((uint32_t*)h)[2 * i + 1] = packh(v.z, v.w);
}

__global__ __launch_bounds__(256)
void transpose_split(const float* __restrict__ in, __half* __restrict__ h,
                     __half* __restrict__ l, int R, int C)
{
    __shared__ float tile[32][33];
    int c0 = blockIdx.x * 32, r0 = blockIdx.y * 32;
    int tx = threadIdx.x & 31, ty = threadIdx.x >> 5;
#pragma unroll
    for (int i = 0; i < 4; i++)
        tile[ty + 8 * i][tx] = in[(size_t)(r0 + ty + 8 * i) * C + c0 + tx];
    __syncthreads();
#pragma unroll
    for (int i = 0; i < 4; i++) {
        float v = tile[tx][ty + 8 * i];
        __half hv = __float2half(v);
        __half lv = __float2half(v - __half2float(hv));
        size_t o = (size_t)(c0 + ty + 8 * i) * R + r0 + tx;
        h[o] = hv; l[o] = lv;
    }
}

// ---------------------------------------------------------------------------
// fp16 2-pass GEMM: C = A @ B^T + bias,  C ≈ Ah·Bh + Ah·Bl  (A hi-only)
// outmode 0: fp32 C;  outmode 2: fp16 hi-only C.
// CTA 128x128x32, 8 warps (32m x 64n), double-buffered cp.async, 2 CTAs/SM.
// ---------------------------------------------------------------------------
#define GBM 128
#define GBN 128
#define GBK 32
#define NCH (KDIM / GBK)         // 64
#define ROWB 80
#define ATB (128 * ROWB)         // 10240
#define BTB (128 * ROWB)         // 10240
#define STAGE_B (ATB + 2 * BTB)  // 30720 : [Ah][Bh][Bl]
#define GEMM_SMEM (2 * STAGE_B)  // 61440

__global__ __launch_bounds__(256, 2)
void gemm_mma(const __half* __restrict__ Ah0, const __half* __restrict__ Ah1,
              const __half* __restrict__ Bh, const __half* __restrict__ Bl,
              const float* __restrict__ bias,
              float* __restrict__ Cf0, int ldc0, float* __restrict__ Cf1, int ldc1,
              __half* __restrict__ Ch0, __half* __restrict__ Ch1,
              int nsplit, int outmode)
{
    extern __shared__ char sm[];
    const uint32_t sbase = smem_to_u32(sm);
    const int tid  = threadIdx.x;
    const int lane = tid & 31;
    const int wid  = tid >> 5;
    const int wm   = (wid & 3) * 32;
    const int wn   = (wid >> 2) * 64;
    const int n0 = blockIdx.x * GBN;
    const int m0 = blockIdx.y * GBM;

    const __half* Ah = (n0 < nsplit) ? Ah0 : Ah1;

    float acc[2][8][4];
#pragma unroll
    for (int i = 0; i < 2; i++)
#pragma unroll
        for (int j = 0; j < 8; j++)
#pragma unroll
            for (int r = 0; r < 4; r++) acc[i][j][r] = 0.f;

    uint32_t aoff[2][2];
#pragma unroll
    for (int mf = 0; mf < 2; mf++)
#pragma unroll
        for (int ks = 0; ks < 2; ks++)
            aoff[mf][ks] = (uint32_t)((wm + mf * 16 + (lane & 15)) * ROWB
                                      + (ks * 16 + 8 * (lane >> 4)) * 2);
    uint32_t boff[4][2];
#pragma unroll
    for (int jj = 0; jj < 4; jj++)
#pragma unroll
        for (int ks = 0; ks < 2; ks++)
            boff[jj][ks] = (uint32_t)((wn + jj * 16 + (lane & 7) + 8 * (lane >> 4)) * ROWB
                                      + (ks * 16 + 8 * ((lane >> 3) & 1)) * 2);

    auto load_chunk = [&](int ic, int s) {
        const int k0 = ic * GBK;
#pragma unroll
        for (int it = 0; it < 6; it++) {
            const int idx = (it & 1) * 256 + tid;
            const int row = idx >> 2, seg = idx & 3;
            const __half* src;
            uint32_t dst;
            if (it < 2) {
                src = Ah + (size_t)(m0 + row) * KDIM + k0 + seg * 8;
                dst = sbase + s * STAGE_B + row * ROWB + seg * 16;
            } else if (it < 4) {
                src = Bh + (size_t)(n0 + row) * KDIM + k0 + seg * 8;
                dst = sbase + s * STAGE_B + ATB + row * ROWB + seg * 16;
            } else {
                src = Bl + (size_t)(n0 + row) * KDIM + k0 + seg * 8;
                dst = sbase + s * STAGE_B + ATB + BTB + row * ROWB + seg * 16;
            }
            CP_ASYNC16(dst, src);
        }
        CP_COMMIT();
    };

    load_chunk(0, 0);

    for (int ic = 0; ic < NCH; ic++) {
        const int s = ic & 1;
        if (ic + 1 < NCH) { load_chunk(ic + 1, s ^ 1); CP_WAIT(1); }
        else              { CP_WAIT(0); }
        __syncthreads();

        const uint32_t stage = sbase + s * STAGE_B;
#pragma unroll
        for (int ks = 0; ks < 2; ks++) {
            uint32_t a[2][4];
            LDSM_X4(a[0][0], a[0][1], a[0][2], a[0][3], stage + aoff[0][ks]);
            LDSM_X4(a[1][0], a[1][1], a[1][2], a[1][3], stage + aoff[1][ks]);
#pragma unroll
            for (int pass = 0; pass < 2; pass++) {
                const uint32_t Bbase = stage + ATB + pass * BTB;
#pragma unroll
                for (int jj = 0; jj < 4; jj++) {
                    uint32_t b0, b1, b2, b3;
                    LDSM_X4(b0, b1, b2, b3, Bbase + boff[jj][ks]);
                    MMA16816(acc[0][jj * 2],     a[0], b0, b1);
                    MMA16816(acc[1][jj * 2],     a[1], b0, b1);
                    MMA16816(acc[0][jj * 2 + 1], a[0], b2, b3);
                    MMA16816(acc[1][jj * 2 + 1], a[1], b2, b3);
                }
            }
        }
        __syncthreads();
    }

    int ld, nc0;
    float* Cf; __half* Ch;
    if (n0 < nsplit) { Cf = Cf0; Ch = Ch0; ld = ldc0; nc0 = n0; }
    else             { Cf = Cf1; Ch = Ch1; ld = ldc1; nc0 = n0 - nsplit; }

#pragma unroll
    for (int mf = 0; mf < 2; mf++) {
#pragma unroll
        for (int nf = 0; nf < 8; nf++) {
            const int nl = wn + nf * 8 + 2 * (lane & 3);
            const float bx = bias[n0 + nl];
            const float by = bias[n0 + nl + 1];
            const int m_up = m0 + wm + mf * 16 + (lane >> 2);
#pragma unroll
            for (int half = 0; half < 2; half++) {
                const int m = m_up + 8 * half;
                float v0 = acc[mf][nf][2 * half]     + bx;
                float v1 = acc[mf][nf][2 * half + 1] + by;
                if (outmode == 0) {
                    float2 v; v.x = v0; v.y = v1;
                    *(float2*)(Cf + (size_t)m * ld + nc0 + nl) = v;
                } else {
                    *(uint32_t*)(Ch + (size_t)m * ld + nc0 + nl) = packh(v0, v1);
                }
            }
        }
    }
}

// ---------------------------------------------------------------------------
// Tensor-core flash attention (pure fp16, single-pass S and PV), split-KV.
// ---------------------------------------------------------------------------
#define ASTR 272
#define Q_TILE (128 * ASTR)
#define KV_TILE (64 * ASTR)
#define KV_STAGE (2 * KV_TILE)             // [K][V] hi only
#define ATT_SMEM (Q_TILE + 2 * KV_STAGE)   // 104448
#define NTT (LSEQ / 64)
#define NTH (NTT / 2)

__global__ __launch_bounds__(256, 1)
void attn_mma(const __half* __restrict__ Qh, const __half* __restrict__ KVh,
              float* __restrict__ Opart, float* __restrict__ Mpart, float* __restrict__ Lpart)
{
    extern __shared__ char sm[];
    const uint32_t sQh = smem_to_u32(sm);
    const uint32_t sKV = sQh + Q_TILE;

    const int tid  = threadIdx.x;
    const int lane = tid & 31;
    const int wid  = tid >> 5;
    const int wm   = wid * 16;

    const int qt = blockIdx.x, h = blockIdx.y;
    const int half = blockIdx.z / BSZ;
    const int b    = blockIdx.z % BSZ;
    const int qrow0 = b * LSEQ + qt * 128;
    const int hcol  = h * HDIM;
    const int jt0 = half * NTH, jtN = jt0 + NTH;

    // Q load
#pragma unroll
    for (int i = 0; i < 8; i++) {
        int idx = i * 256 + tid;
        int row = idx >> 4, seg = idx & 15;
        size_t g = (size_t)(qrow0 + row) * DIMSZ + hcol + seg * 8;
        CP_ASYNC16(sQh + row * ASTR + seg * 16, Qh + g);
    }
    CP_COMMIT();

    auto load_kv = [&](int jt, int s) {
        const uint32_t base = sKV + s * KV_STAGE;
        const int krow0 = b * LSEQ + jt * 64;
#pragma unroll
        for (int i = 0; i < 4; i++) {
            int idx = i * 256 + tid;
            int row = idx >> 4, seg = idx & 15;
            size_t roff = (size_t)(krow0 + row) * (2 * DIMSZ);
            uint32_t d = row * ASTR + seg * 16;
            CP_ASYNC16(base + d,           KVh + roff + hcol + seg * 8);
            CP_ASYNC16(base + KV_TILE + d, KVh + roff + DIMSZ + hcol + seg * 8);
        }
        CP_COMMIT();
    };
    load_kv(jt0, 0);

    const uint32_t ab = (uint32_t)((wm + (lane & 15)) * ASTR + (lane >> 4) * 16);
    const uint32_t kb = (uint32_t)(((lane & 7) + 8 * (lane >> 4)) * ASTR
                                   + ((lane >> 3) & 1) * 16);
    const uint32_t vb = (uint32_t)(((lane & 7) + 8 * ((lane >> 3) & 1)) * ASTR
                                   + (lane >> 4) * 16);

    float oacc[16][4];
#pragma unroll
    for (int f = 0; f < 16; f++)
#pragma unroll
        for (int e = 0; e < 4; e++) oacc[f][e] = 0.f;
    float m_prev[2] = {-3.0e38f, -3.0e38f};
    float l_acc[2]  = {0.f, 0.f};

    for (int jt = jt0; jt < jtN; jt++) {
        const int s = jt & 1;
        const bool has_next = (jt + 1 < jtN);
        if (has_next) load_kv(jt + 1, s ^ 1);
        if (has_next) { CP_WAIT(1); } else { CP_WAIT(0); }
        __syncthreads();

        const uint32_t sK = sKV + s * KV_STAGE;
        const uint32_t sV = sK + KV_TILE;

        // ---- S = Qh Kh^T ----
        float sacc[8][4];
#pragma unroll
        for (int f = 0; f < 8; f++)
#pragma unroll
            for (int e = 0; e < 4; e++) sacc[f][e] = 0.f;

#pragma unroll
        for (int ks = 0; ks < 8; ks++) {
            uint32_t ah[4];
            LDSM_X4(ah[0], ah[1], ah[2], ah[3], sQh + ab + ks * 32);
#pragma unroll
            for (int jj = 0; jj < 4; jj++) {
                uint32_t h0, h1, h2, h3;
                LDSM_X4(h0, h1, h2, h3, sK + kb + jj * (16 * ASTR) + ks * 32);
                MMA16816(sacc[2 * jj],     ah, h0, h1);
                MMA16816(sacc[2 * jj + 1], ah, h2, h3);
            }
        }

        float mx0 = -3.0e38f, mx1 = -3.0e38f;
#pragma unroll
        for (int f = 0; f < 8; f++) {
            sacc[f][0] *= SCALE_F; sacc[f][1] *= SCALE_F;
            sacc[f][2] *= SCALE_F; sacc[f][3] *= SCALE_F;
            mx0 = fmaxf(mx0, fmaxf(sacc[f][0], sacc[f][1]));
            mx1 = fmaxf(mx1, fmaxf(sacc[f][2], sacc[f][3]));
        }
        mx0 = fmaxf(mx0, __shfl_xor_sync(0xffffffffu, mx0, 1));
        mx0 = fmaxf(mx0, __shfl_xor_sync(0xffffffffu, mx0, 2));
        mx1 = fmaxf(mx1, __shfl_xor_sync(0xffffffffu, mx1, 1));
        mx1 = fmaxf(mx1, __shfl_xor_sync(0xffffffffu, mx1, 2));

        float mnew0 = fmaxf(m_prev[0], mx0);
        float mnew1 = fmaxf(m_prev[1], mx1);
        float er0 = __expf(m_prev[0] - mnew0);
        float er1 = __expf(m_prev[1] - mnew1);
        m_prev[0] = mnew0; m_prev[1] = mnew1;

        float rsum0 = 0.f, rsum1 = 0.f;
#pragma unroll
        for (int f = 0; f < 8; f++) {
            sacc[f][0] = __expf(sacc[f][0] - mnew0);
            sacc[f][1] = __expf(sacc[f][1] - mnew0);
            sacc[f][2] = __expf(sacc[f][2] - mnew1);
            sacc[f][3] = __expf(sacc[f][3] - mnew1);
            rsum0 += sacc[f][0] + sacc[f][1];
            rsum1 += sacc[f][2] + sacc[f][3];
        }
        rsum0 += __shfl_xor_sync(0xffffffffu, rsum0, 1);
        rsum0 += __shfl_xor_sync(0xffffffffu, rsum0, 2);
        rsum1 += __shfl_xor_sync(0xffffffffu, rsum1, 1);
        rsum1 += __shfl_xor_sync(0xffffffffu, rsum1, 2);
        l_acc[0] = l_acc[0] * er0 + rsum0;
        l_acc[1] = l_acc[1] * er1 + rsum1;

#pragma unroll
        for (int f = 0; f < 16; f++) {
            oacc[f][0] *= er0; oacc[f][1] *= er0;
            oacc[f][2] *= er1; oacc[f][3] *= er1;
        }

        // ---- pack P (fp16) ----
        uint32_t aph[4][4];
#pragma unroll
        for (int t = 0; t < 4; t++) {
#pragma unroll
            for (int hh = 0; hh < 2; hh++) {
                const int f = 2 * t + hh;
                aph[t][2 * hh]     = packh(sacc[f][0], sacc[f][1]);
                aph[t][2 * hh + 1] = packh(sacc[f][2], sacc[f][3]);
            }
        }

        // ---- O += Ph Vh ----
#pragma unroll
        for (int t = 0; t < 4; t++) {
#pragma unroll
            for (int g = 0; g < 8; g++) {
                uint32_t h0, h1, h2, h3;
                LDSM_X4_T(h0, h1, h2, h3, sV + vb + t * (16 * ASTR) + g * 32);
                MMA16816(oacc[2 * g],     aph[t], h0, h1);
                MMA16816(oacc[2 * g + 1], aph[t], h2, h3);
            }
        }
        __syncthreads();
    }

#pragma unroll
    for (int rs = 0; rs < 2; rs++) {
        const int lrow = qt * 128 + wm + (lane >> 2) + 8 * rs;
        const size_t orow = ((size_t)half * MROWS + b * LSEQ + lrow) * DIMSZ + hcol;
        if ((lane & 3) == 0) {
            size_t mi = (((size_t)half * BSZ + b) * NHEADS + h) * LSEQ + lrow;
            Mpart[mi] = m_prev[rs];
            Lpart[mi] = l_acc[rs];
        }
#pragma unroll
        for (int f = 0; f < 16; f++) {
            float2 v;
            v.x = oacc[f][2 * rs];
            v.y = oacc[f][2 * rs + 1];
            *(float2*)(Opart + orow + f * 8 + 2 * (lane & 3)) = v;
        }
    }
}

// ---------------------------------------------------------------------------
// Combine KV-halves -> fp16 output for proj GEMM
// ---------------------------------------------------------------------------
__global__ __launch_bounds__(256)
void attn_combine(const float* __restrict__ Opart,
                  const float* __restrict__ Mpart, const float* __restrict__ Lpart,
                  __half* __restrict__ Oh)
{
    const size_t i = (size_t)blockIdx.x * 256 + threadIdx.x;
    const size_t e = i * 4;
    const int row = (int)(e / DIMSZ);
    const int col = (int)(e % DIMSZ);
    const int h = col >> 7;
    const int b = row / LSEQ;
    const int lr = row % LSEQ;

    const size_t mi0 = (((size_t)0 * BSZ + b) * NHEADS + h) * LSEQ + lr;
    const size_t mi1 = (((size_t)1 * BSZ + b) * NHEADS + h) * LSEQ + lr;
    const float m0 = Mpart[mi0], m1 = Mpart[mi1];
    const float l0 = Lpart[mi0], l1 = Lpart[mi1];
    const float m  = fmaxf(m0, m1);
    const float e0 = __expf(m0 - m), e1 = __expf(m1 - m);
    const float inv = 1.0f / (l0 * e0 + l1 * e1);

    float4 a = ((const float4*)Opart)[i];
    float4 c = ((const float4*)(Opart + (size_t)MROWS * DIMSZ))[i];
    float v0 = (a.x * e0 + c.x * e1) * inv;
    float v1 = (a.y * e0 + c.y * e1) * inv;
    float v2 = (a.z * e0 + c.z * e1) * inv;
    float v3 = (a.w * e0 + c.w * e1) * inv;

    ((uint32_t*)Oh)[2 * i]     = packh(v0, v1);
    ((uint32_t*)Oh)[2 * i + 1] = packh(v2, v3);
}

// ---------------------------------------------------------------------------
extern "C" void kernel_launch(void* const* d_in, const int* in_sizes, int n_in,
                              void* d_out, int out_size)
{
    const float* x       = (const float*)d_in[0];
    const float* context = (const float*)d_in[1];
    const float* W_qkv   = (const float*)d_in[2];
    const float* b_qkv   = (const float*)d_in[3];
    const float* W_proj  = (const float*)d_in[4];
    const float* b_proj  = (const float*)d_in[5];
    float* out = (float*)d_out;

    __half *xh, *ch, *wqh, *wql, *wph, *wpl;
    __half *qh, *kvh, *ath;
    float *opart, *mpart, *lpart;
    cudaGetSymbolAddress((void**)&xh,  g_xh);
    cudaGetSymbolAddress((void**)&ch,  g_ch);
    cudaGetSymbolAddress((void**)&wqh, g_wqh); cudaGetSymbolAddress((void**)&wql, g_wql);
    cudaGetSymbolAddress((void**)&wph, g_wph); cudaGetSymbolAddress((void**)&wpl, g_wpl);
    cudaGetSymbolAddress((void**)&qh,  g_qh);
    cudaGetSymbolAddress((void**)&kvh, g_kvh);
    cudaGetSymbolAddress((void**)&ath, g_ath);
    cudaGetSymbolAddress((void**)&opart, g_opart);
    cudaGetSymbolAddress((void**)&mpart, g_mpart);
    cudaGetSymbolAddress((void**)&lpart, g_lpart);

    cudaFuncSetAttribute(gemm_mma, cudaFuncAttributeMaxDynamicSharedMemorySize, GEMM_SMEM);
    cudaFuncSetAttribute(attn_mma, cudaFuncAttributeMaxDynamicSharedMemorySize, ATT_SMEM);

    const int n4 = MROWS * DIMSZ / 4;

    split_one<<<(n4 + 255) / 256, 256>>>(x, xh, n4);
    split_one<<<(n4 + 255) / 256, 256>>>(context, ch, n4);
    transpose_split<<<dim3(3 * DIMSZ / 32, DIMSZ / 32), 256>>>(W_qkv, wqh, wql, DIMSZ, 3 * DIMSZ);
    transpose_split<<<dim3(DIMSZ / 32, DIMSZ / 32), 256>>>(W_proj, wph, wpl, DIMSZ, DIMSZ);

    // qkv GEMM (fp16 2-pass), fp16 hi-only outputs
    gemm_mma<<<dim3(3 * DIMSZ / GBN, MROWS / GBM), 256, GEMM_SMEM>>>(
        xh, ch, wqh, wql, b_qkv,
        nullptr, DIMSZ, nullptr, 2 * DIMSZ,
        qh, kvh, DIMSZ, 2);

    // split-KV attention (pure fp16)
    attn_mma<<<dim3(LSEQ / 128, NHEADS, 2 * BSZ), 256, ATT_SMEM>>>(
        qh, kvh, opart, mpart, lpart);

    attn_combine<<<(n4 + 255) / 256, 256>>>(opart, mpart, lpart, ath);

    // proj GEMM (fp16 2-pass, fp32 out)
    gemm_mma<<<dim3(DIMSZ / GBN, MROWS / GBM), 256, GEMM_SMEM>>>(
        ath, ath, wph, wpl, b_proj,
        out, DIMSZ, out, DIMSZ,
        nullptr, nullptr, 1 << 30, 0);
}

// round 14
// speedup vs baseline: 2.2600x; 1.2924x over previous
#include <cuda_runtime.h>
#include <cuda_fp16.h>
#include <cstdint>

#define DIMSZ 2048
#define NHEADS 16
#define HDIM 128
#define BSZ 2
#define LSEQ 2048
#define MROWS (BSZ * LSEQ)   // 4096
#define KDIM 2048
#define SCALE_F 0.08838834764831845f

// ---------------------------------------------------------------------------
// Scratch (__device__ globals; no allocation allowed)
// ---------------------------------------------------------------------------
__device__ __half g_xh[(size_t)MROWS * DIMSZ];              // activations fp16
__device__ __half g_ch[(size_t)MROWS * DIMSZ];
__device__ __half g_wqh[(size_t)3 * DIMSZ * DIMSZ];         // W_qkv^T fp16 (hi only used)
__device__ __half g_wph[(size_t)DIMSZ * DIMSZ];             // W_proj^T hi/lo
__device__ __half g_wpl[(size_t)DIMSZ * DIMSZ];
__device__ __half g_qh[(size_t)MROWS * DIMSZ];              // q fp16
__device__ __half g_kvh[(size_t)MROWS * 2 * DIMSZ];         // k|v fp16
__device__ __half g_ath[(size_t)MROWS * DIMSZ];             // attn out fp16
// split-KV partials
__device__ float g_opart[(size_t)2 * MROWS * DIMSZ];
__device__ float g_mpart[(size_t)2 * BSZ * NHEADS * LSEQ];
__device__ float g_lpart[(size_t)2 * BSZ * NHEADS * LSEQ];

// ---------------------------------------------------------------------------
// PTX helpers
// ---------------------------------------------------------------------------
__device__ __forceinline__ uint32_t smem_to_u32(const void* p) {
    uint32_t a;
    asm("{ .reg .u64 t; cvta.to.shared.u64 t, %1; cvt.u32.u64 %0, t; }" : "=r"(a) : "l"(p));
    return a;
}

#define CP_ASYNC16(dst, src) \
    asm volatile("cp.async.cg.shared.global [%0], [%1], 16;" :: "r"(dst), "l"(src) : "memory")
#define CP_COMMIT() asm volatile("cp.async.commit_group;" ::: "memory")
#define CP_WAIT(n)  asm volatile("cp.async.wait_group %0;" :: "n"(n) : "memory")

#define LDSM_X4(r0, r1, r2, r3, addr) \
    asm volatile("ldmatrix.sync.aligned.m8n8.x4.shared.b16 {%0,%1,%2,%3}, [%4];" \
                 : "=r"(r0), "=r"(r1), "=r"(r2), "=r"(r3) : "r"(addr))
#define LDSM_X4_T(r0, r1, r2, r3, addr) \
    asm volatile("ldmatrix.sync.aligned.m8n8.x4.trans.shared.b16 {%0,%1,%2,%3}, [%4];" \
                 : "=r"(r0), "=r"(r1), "=r"(r2), "=r"(r3) : "r"(addr))

#define MMA16816(d, a, b0, b1) \
    asm volatile("mma.sync.aligned.m16n8k16.row.col.f32.f16.f16.f32 " \
                 "{%0,%1,%2,%3}, {%4,%5,%6,%7}, {%8,%9}, {%0,%1,%2,%3};" \
                 : "+f"((d)[0]), "+f"((d)[1]), "+f"((d)[2]), "+f"((d)[3]) \
                 : "r"((a)[0]), "r"((a)[1]), "r"((a)[2]), "r"((a)[3]), \
                   "r"(b0), "r"(b1))

__device__ __forceinline__ uint32_t packh(float lo, float hi) {
    uint32_t r;
    asm("cvt.rn.f16x2.f32 %0, %1, %2;" : "=r"(r) : "f"(hi), "f"(lo));
    return r;
}
__device__ __forceinline__ float hlo_f(uint32_t u) {
    unsigned short s = (unsigned short)(u & 0xffffu);
    float f; asm("cvt.f32.f16 %0, %1;" : "=f"(f) : "h"(s));
    return f;
}
__device__ __forceinline__ float hhi_f(uint32_t u) {
    unsigned short s = (unsigned short)(u >> 16);
    float f; asm("cvt.f32.f16 %0, %1;" : "=f"(f) : "h"(s));
    return f;
}

// ---------------------------------------------------------------------------
// Conversion kernels
// ---------------------------------------------------------------------------
__global__ __launch_bounds__(256)
void split_one(const float* __restrict__ in, __half* __restrict__ h, int n4)
{
    int i = blockIdx.x * 256 + threadIdx.x;
    if (i >= n4) return;
    float4 v = ((const float4*)in)[i];
    ((uint32_t*)h)[2 * i]     = packh(v.x, v.y);
    ((uint32_t*)h)[2 * i + 1] = packh(v.z, v.w);
}

// transpose to fp16 hi only
__global__ __launch_bounds__(256)
void transpose_one(const float* __restrict__ in, __half* __restrict__ h, int R, int C)
{
    __shared__ float tile[32][33];
    int c0 = blockIdx.x * 32, r0 = blockIdx.y * 32;
    int tx = threadIdx.x & 31, ty = threadIdx.x >> 5;
#pragma unroll
    for (int i = 0; i < 4; i++)
        tile[ty + 8 * i][tx] = in[(size_t)(r0 + ty + 8 * i) * C + c0 + tx];
    __syncthreads();
#pragma unroll
    for (int i = 0; i < 4; i++) {
        float v = tile[tx][ty + 8 * i];
        h[(size_t)(c0 + ty + 8 * i) * R + r0 + tx] = __float2half(v);
    }
}

// transpose to fp16 hi/lo
__global__ __launch_bounds__(256)
void transpose_split(const float* __restrict__ in, __half* __restrict__ h,
                     __half* __restrict__ l, int R, int C)
{
    __shared__ float tile[32][33];
    int c0 = blockIdx.x * 32, r0 = blockIdx.y * 32;
    int tx = threadIdx.x & 31, ty = threadIdx.x >> 5;
#pragma unroll
    for (int i = 0; i < 4; i++)
        tile[ty + 8 * i][tx] = in[(size_t)(r0 + ty + 8 * i) * C + c0 + tx];
    __syncthreads();
#pragma unroll
    for (int i = 0; i < 4; i++) {
        float v = tile[tx][ty + 8 * i];
        __half hv = __float2half(v);
        __half lv = __float2half(v - __half2float(hv));
        size_t o = (size_t)(c0 + ty + 8 * i) * R + r0 + tx;
        h[o] = hv; l[o] = lv;
    }
}

// ---------------------------------------------------------------------------
// fp16 GEMM, NPASS passes: C = Ah·Bh (+ Ah·Bl if NPASS=2) + bias
// outmode 0: fp32 C;  outmode 2: fp16 C.
// CTA 128x128x32, 8 warps (32m x 64n), double-buffered cp.async, 2 CTAs/SM.
// ---------------------------------------------------------------------------
#define GBM 128
#define GBN 128
#define GBK 32
#define NCH (KDIM / GBK)         // 64
#define ROWB 80
#define ATB (128 * ROWB)         // 10240
#define BTB (128 * ROWB)         // 10240
#define STAGE_B (ATB + 2 * BTB)  // 30720 : [Ah][Bh][Bl]
#define GEMM_SMEM (2 * STAGE_B)  // 61440

template<int NPASS>
__global__ __launch_bounds__(256, 2)
void gemm_mma(const __half* __restrict__ Ah0, const __half* __restrict__ Ah1,
              const __half* __restrict__ Bh, const __half* __restrict__ Bl,
              const float* __restrict__ bias,
              float* __restrict__ Cf0, int ldc0, float* __restrict__ Cf1, int ldc1,
              __half* __restrict__ Ch0, __half* __restrict__ Ch1,
              int nsplit, int outmode)
{
    extern __shared__ char sm[];
    const uint32_t sbase = smem_to_u32(sm);
    const int tid  = threadIdx.x;
    const int lane = tid & 31;
    const int wid  = tid >> 5;
    const int wm   = (wid & 3) * 32;
    const int wn   = (wid >> 2) * 64;
    const int n0 = blockIdx.x * GBN;
    const int m0 = blockIdx.y * GBM;

    const __half* Ah = (n0 < nsplit) ? Ah0 : Ah1;

    float acc[2][8][4];
#pragma unroll
    for (int i = 0; i < 2; i++)
#pragma unroll
        for (int j = 0; j < 8; j++)
#pragma unroll
            for (int r = 0; r < 4; r++) acc[i][j][r] = 0.f;

    uint32_t aoff[2][2];
#pragma unroll
    for (int mf = 0; mf < 2; mf++)
#pragma unroll
        for (int ks = 0; ks < 2; ks++)
            aoff[mf][ks] = (uint32_t)((wm + mf * 16 + (lane & 15)) * ROWB
                                      + (ks * 16 + 8 * (lane >> 4)) * 2);
    uint32_t boff[4][2];
#pragma unroll
    for (int jj = 0; jj < 4; jj++)
#pragma unroll
        for (int ks = 0; ks < 2; ks++)
            boff[jj][ks] = (uint32_t)((wn + jj * 16 + (lane & 7) + 8 * (lane >> 4)) * ROWB
                                      + (ks * 16 + 8 * ((lane >> 3) & 1)) * 2);

    auto load_chunk = [&](int ic, int s) {
        const int k0 = ic * GBK;
#pragma unroll
        for (int it = 0; it < 2 + 2 * NPASS; it++) {
            const int idx = (it & 1) * 256 + tid;
            const int row = idx >> 2, seg = idx & 3;
            const __half* src;
            uint32_t dst;
            if (it < 2) {
                src = Ah + (size_t)(m0 + row) * KDIM + k0 + seg * 8;
                dst = sbase + s * STAGE_B + row * ROWB + seg * 16;
            } else if (it < 4) {
                src = Bh + (size_t)(n0 + row) * KDIM + k0 + seg * 8;
                dst = sbase + s * STAGE_B + ATB + row * ROWB + seg * 16;
            } else {
                src = Bl + (size_t)(n0 + row) * KDIM + k0 + seg * 8;
                dst = sbase + s * STAGE_B + ATB + BTB + row * ROWB + seg * 16;
            }
            CP_ASYNC16(dst, src);
        }
        CP_COMMIT();
    };

    load_chunk(0, 0);

    for (int ic = 0; ic < NCH; ic++) {
        const int s = ic & 1;
        if (ic + 1 < NCH) { load_chunk(ic + 1, s ^ 1); CP_WAIT(1); }
        else              { CP_WAIT(0); }
        __syncthreads();

        const uint32_t stage = sbase + s * STAGE_B;
#pragma unroll
        for (int ks = 0; ks < 2; ks++) {
            uint32_t a[2][4];
            LDSM_X4(a[0][0], a[0][1], a[0][2], a[0][3], stage + aoff[0][ks]);
            LDSM_X4(a[1][0], a[1][1], a[1][2], a[1][3], stage + aoff[1][ks]);
#pragma unroll
            for (int pass = 0; pass < NPASS; pass++) {
                const uint32_t Bbase = stage + ATB + pass * BTB;
#pragma unroll
                for (int jj = 0; jj < 4; jj++) {
                    uint32_t b0, b1, b2, b3;
                    LDSM_X4(b0, b1, b2, b3, Bbase + boff[jj][ks]);
                    MMA16816(acc[0][jj * 2],     a[0], b0, b1);
                    MMA16816(acc[1][jj * 2],     a[1], b0, b1);
                    MMA16816(acc[0][jj * 2 + 1], a[0], b2, b3);
                    MMA16816(acc[1][jj * 2 + 1], a[1], b2, b3);
                }
            }
        }
        __syncthreads();
    }

    int ld, nc0;
    float* Cf; __half* Ch;
    if (n0 < nsplit) { Cf = Cf0; Ch = Ch0; ld = ldc0; nc0 = n0; }
    else             { Cf = Cf1; Ch = Ch1; ld = ldc1; nc0 = n0 - nsplit; }

#pragma unroll
    for (int mf = 0; mf < 2; mf++) {
#pragma unroll
        for (int nf = 0; nf < 8; nf++) {
            const int nl = wn + nf * 8 + 2 * (lane & 3);
            const float bx = bias[n0 + nl];
            const float by = bias[n0 + nl + 1];
            const int m_up = m0 + wm + mf * 16 + (lane >> 2);
#pragma unroll
            for (int half = 0; half < 2; half++) {
                const int m = m_up + 8 * half;
                float v0 = acc[mf][nf][2 * half]     + bx;
                float v1 = acc[mf][nf][2 * half + 1] + by;
                if (outmode == 0) {
                    float2 v; v.x = v0; v.y = v1;
                    *(float2*)(Cf + (size_t)m * ld + nc0 + nl) = v;
                } else {
                    *(uint32_t*)(Ch + (size_t)m * ld + nc0 + nl) = packh(v0, v1);
                }
            }
        }
    }
}

// ---------------------------------------------------------------------------
// Tensor-core flash attention (pure fp16), split-KV — unchanged from R13.
// ---------------------------------------------------------------------------
#define ASTR 272
#define Q_TILE (128 * ASTR)
#define KV_TILE (64 * ASTR)
#define KV_STAGE (2 * KV_TILE)
#define ATT_SMEM (Q_TILE + 2 * KV_STAGE)   // 104448
#define NTT (LSEQ / 64)
#define NTH (NTT / 2)

__global__ __launch_bounds__(256, 1)
void attn_mma(const __half* __restrict__ Qh, const __half* __restrict__ KVh,
              float* __restrict__ Opart, float* __restrict__ Mpart, float* __restrict__ Lpart)
{
    extern __shared__ char sm[];
    const uint32_t sQh = smem_to_u32(sm);
    const uint32_t sKV = sQh + Q_TILE;

    const int tid  = threadIdx.x;
    const int lane = tid & 31;
    const int wid  = tid >> 5;
    const int wm   = wid * 16;

    const int qt = blockIdx.x, h = blockIdx.y;
    const int half = blockIdx.z / BSZ;
    const int b    = blockIdx.z % BSZ;
    const int qrow0 = b * LSEQ + qt * 128;
    const int hcol  = h * HDIM;
    const int jt0 = half * NTH, jtN = jt0 + NTH;

#pragma unroll
    for (int i = 0; i < 8; i++) {
        int idx = i * 256 + tid;
        int row = idx >> 4, seg = idx & 15;
        size_t g = (size_t)(qrow0 + row) * DIMSZ + hcol + seg * 8;
        CP_ASYNC16(sQh + row * ASTR + seg * 16, Qh + g);
    }
    CP_COMMIT();

    auto load_kv = [&](int jt, int s) {
        const uint32_t base = sKV + s * KV_STAGE;
        const int krow0 = b * LSEQ + jt * 64;
#pragma unroll
        for (int i = 0; i < 4; i++) {
            int idx = i * 256 + tid;
            int row = idx >> 4, seg = idx & 15;
            size_t roff = (size_t)(krow0 + row) * (2 * DIMSZ);
            uint32_t d = row * ASTR + seg * 16;
            CP_ASYNC16(base + d,           KVh + roff + hcol + seg * 8);
            CP_ASYNC16(base + KV_TILE + d, KVh + roff + DIMSZ + hcol + seg * 8);
        }
        CP_COMMIT();
    };
    load_kv(jt0, 0);

    const uint32_t ab = (uint32_t)((wm + (lane & 15)) * ASTR + (lane >> 4) * 16);
    const uint32_t kb = (uint32_t)(((lane & 7) + 8 * (lane >> 4)) * ASTR
                                   + ((lane >> 3) & 1) * 16);
    const uint32_t vb = (uint32_t)(((lane & 7) + 8 * ((lane >> 3) & 1)) * ASTR
                                   + (lane >> 4) * 16);

    float oacc[16][4];
#pragma unroll
    for (int f = 0; f < 16; f++)
#pragma unroll
        for (int e = 0; e < 4; e++) oacc[f][e] = 0.f;
    float m_prev[2] = {-3.0e38f, -3.0e38f};
    float l_acc[2]  = {0.f, 0.f};

    for (int jt = jt0; jt < jtN; jt++) {
        const int s = jt & 1;
        const bool has_next = (jt + 1 < jtN);
        if (has_next) load_kv(jt + 1, s ^ 1);
        if (has_next) { CP_WAIT(1); } else { CP_WAIT(0); }
        __syncthreads();

        const uint32_t sK = sKV + s * KV_STAGE;
        const uint32_t sV = sK + KV_TILE;

        float sacc[8][4];
#pragma unroll
        for (int f = 0; f < 8; f++)
#pragma unroll
            for (int e = 0; e < 4; e++) sacc[f][e] = 0.f;

#pragma unroll
        for (int ks = 0; ks < 8; ks++) {
            uint32_t ah[4];
            LDSM_X4(ah[0], ah[1], ah[2], ah[3], sQh + ab + ks * 32);
#pragma unroll
            for (int jj = 0; jj < 4; jj++) {
                uint32_t h0, h1, h2, h3;
                LDSM_X4(h0, h1, h2, h3, sK + kb + jj * (16 * ASTR) + ks * 32);
                MMA16816(sacc[2 * jj],     ah, h0, h1);
                MMA16816(sacc[2 * jj + 1], ah, h2, h3);
            }
        }

        float mx0 = -3.0e38f, mx1 = -3.0e38f;
#pragma unroll
        for (int f = 0; f < 8; f++) {
            sacc[f][0] *= SCALE_F; sacc[f][1] *= SCALE_F;
            sacc[f][2] *= SCALE_F; sacc[f][3] *= SCALE_F;
            mx0 = fmaxf(mx0, fmaxf(sacc[f][0], sacc[f][1]));
            mx1 = fmaxf(mx1, fmaxf(sacc[f][2], sacc[f][3]));
        }
        mx0 = fmaxf(mx0, __shfl_xor_sync(0xffffffffu, mx0, 1));
        mx0 = fmaxf(mx0, __shfl_xor_sync(0xffffffffu, mx0, 2));
        mx1 = fmaxf(mx1, __shfl_xor_sync(0xffffffffu, mx1, 1));
        mx1 = fmaxf(mx1, __shfl_xor_sync(0xffffffffu, mx1, 2));

        float mnew0 = fmaxf(m_prev[0], mx0);
        float mnew1 = fmaxf(m_prev[1], mx1);
        float er0 = __expf(m_prev[0] - mnew0);
        float er1 = __expf(m_prev[1] - mnew1);
        m_prev[0] = mnew0; m_prev[1] = mnew1;

        float rsum0 = 0.f, rsum1 = 0.f;
#pragma unroll
        for (int f = 0; f < 8; f++) {
            sacc[f][0] = __expf(sacc[f][0] - mnew0);
            sacc[f][1] = __expf(sacc[f][1] - mnew0);
            sacc[f][2] = __expf(sacc[f][2] - mnew1);
            sacc[f][3] = __expf(sacc[f][3] - mnew1);
            rsum0 += sacc[f][0] + sacc[f][1];
            rsum1 += sacc[f][2] + sacc[f][3];
        }
        rsum0 += __shfl_xor_sync(0xffffffffu, rsum0, 1);
        rsum0 += __shfl_xor_sync(0xffffffffu, rsum0, 2);
        rsum1 += __shfl_xor_sync(0xffffffffu, rsum1, 1);
        rsum1 += __shfl_xor_sync(0xffffffffu, rsum1, 2);
        l_acc[0] = l_acc[0] * er0 + rsum0;
        l_acc[1] = l_acc[1] * er1 + rsum1;

#pragma unroll
        for (int f = 0; f < 16; f++) {
            oacc[f][0] *= er0; oacc[f][1] *= er0;
            oacc[f][2] *= er1; oacc[f][3] *= er1;
        }

        uint32_t aph[4][4];
#pragma unroll
        for (int t = 0; t < 4; t++) {
#pragma unroll
            for (int hh = 0; hh < 2; hh++) {
                const int f = 2 * t + hh;
                aph[t][2 * hh]     = packh(sacc[f][0], sacc[f][1]);
                aph[t][2 * hh + 1] = packh(sacc[f][2], sacc[f][3]);
            }
        }

#pragma unroll
        for (int t = 0; t < 4; t++) {
#pragma unroll
            for (int g = 0; g < 8; g++) {
                uint32_t h0, h1, h2, h3;
                LDSM_X4_T(h0, h1, h2, h3, sV + vb + t * (16 * ASTR) + g * 32);
                MMA16816(oacc[2 * g],     aph[t], h0, h1);
                MMA16816(oacc[2 * g + 1], aph[t], h2, h3);
            }
        }
        __syncthreads();
    }

#pragma unroll
    for (int rs = 0; rs < 2; rs++) {
        const int lrow = qt * 128 + wm + (lane >> 2) + 8 * rs;
        const size_t orow = ((size_t)half * MROWS + b * LSEQ + lrow) * DIMSZ + hcol;
        if ((lane & 3) == 0) {
            size_t mi = (((size_t)half * BSZ + b) * NHEADS + h) * LSEQ + lrow;
            Mpart[mi] = m_prev[rs];
            Lpart[mi] = l_acc[rs];
        }
#pragma unroll
        for (int f = 0; f < 16; f++) {
            float2 v;
            v.x = oacc[f][2 * rs];
            v.y = oacc[f][2 * rs + 1];
            *(float2*)(Opart + orow + f * 8 + 2 * (lane & 3)) = v;
        }
    }
}

// ---------------------------------------------------------------------------
// Combine KV-halves -> fp16 output for proj GEMM
// ---------------------------------------------------------------------------
__global__ __launch_bounds__(256)
void attn_combine(const float* __restrict__ Opart,
                  const float* __restrict__ Mpart, const float* __restrict__ Lpart,
                  __half* __restrict__ Oh)
{
    const size_t i = (size_t)blockIdx.x * 256 + threadIdx.x;
    const size_t e = i * 4;
    const int row = (int)(e / DIMSZ);
    const int col = (int)(e % DIMSZ);
    const int h = col >> 7;
    const int b = row / LSEQ;
    const int lr = row % LSEQ;

    const size_t mi0 = (((size_t)0 * BSZ + b) * NHEADS + h) * LSEQ + lr;
    const size_t mi1 = (((size_t)1 * BSZ + b) * NHEADS + h) * LSEQ + lr;
    const float m0 = Mpart[mi0], m1 = Mpart[mi1];
    const float l0 = Lpart[mi0], l1 = Lpart[mi1];
    const float m  = fmaxf(m0, m1);
    const float e0 = __expf(m0 - m), e1 = __expf(m1 - m);
    const float inv = 1.0f / (l0 * e0 + l1 * e1);

    float4 a = ((const float4*)Opart)[i];
    float4 c = ((const float4*)(Opart + (size_t)MROWS * DIMSZ))[i];
    float v0 = (a.x * e0 + c.x * e1) * inv;
    float v1 = (a.y * e0 + c.y * e1) * inv;
    float v2 = (a.z * e0 + c.z * e1) * inv;
    float v3 = (a.w * e0 + c.w * e1) * inv;

    ((uint32_t*)Oh)[2 * i]     = packh(v0, v1);
    ((uint32_t*)Oh)[2 * i + 1] = packh(v2, v3);
}

// ---------------------------------------------------------------------------
extern "C" void kernel_launch(void* const* d_in, const int* in_sizes, int n_in,
                              void* d_out, int out_size)
{
    const float* x       = (const float*)d_in[0];
    const float* context = (const float*)d_in[1];
    const float* W_qkv   = (const float*)d_in[2];
    const float* b_qkv   = (const float*)d_in[3];
    const float* W_proj  = (const float*)d_in[4];
    const float* b_proj  = (const float*)d_in[5];
    float* out = (float*)d_out;

    __half *xh, *ch, *wqh, *wph, *wpl;
    __half *qh, *kvh, *ath;
    float *opart, *mpart, *lpart;
    cudaGetSymbolAddress((void**)&xh,  g_xh);
    cudaGetSymbolAddress((void**)&ch,  g_ch);
    cudaGetSymbolAddress((void**)&wqh, g_wqh);
    cudaGetSymbolAddress((void**)&wph, g_wph); cudaGetSymbolAddress((void**)&wpl, g_wpl);
    cudaGetSymbolAddress((void**)&qh,  g_qh);
    cudaGetSymbolAddress((void**)&kvh, g_kvh);
    cudaGetSymbolAddress((void**)&ath, g_ath);
    cudaGetSymbolAddress((void**)&opart, g_opart);
    cudaGetSymbolAddress((void**)&mpart, g_mpart);
    cudaGetSymbolAddress((void**)&lpart, g_lpart);

    cudaFuncSetAttribute(gemm_mma<1>, cudaFuncAttributeMaxDynamicSharedMemorySize, GEMM_SMEM);
    cudaFuncSetAttribute(gemm_mma<2>, cudaFuncAttributeMaxDynamicSharedMemorySize, GEMM_SMEM);
    cudaFuncSetAttribute(attn_mma, cudaFuncAttributeMaxDynamicSharedMemorySize, ATT_SMEM);

    const int n4 = MROWS * DIMSZ / 4;

    split_one<<<(n4 + 255) / 256, 256>>>(x, xh, n4);
    split_one<<<(n4 + 255) / 256, 256>>>(context, ch, n4);
    transpose_one<<<dim3(3 * DIMSZ / 32, DIMSZ / 32), 256>>>(W_qkv, wqh, DIMSZ, 3 * DIMSZ);
    transpose_split<<<dim3(DIMSZ / 32, DIMSZ / 32), 256>>>(W_proj, wph, wpl, DIMSZ, DIMSZ);

    // qkv GEMM: pure fp16, 1 pass
    gemm_mma<1><<<dim3(3 * DIMSZ / GBN, MROWS / GBM), 256, GEMM_SMEM>>>(
        xh, ch, wqh, nullptr, b_qkv,
        nullptr, DIMSZ, nullptr, 2 * DIMSZ,
        qh, kvh, DIMSZ, 2);

    // split-KV attention (pure fp16)
    attn_mma<<<dim3(LSEQ / 128, NHEADS, 2 * BSZ), 256, ATT_SMEM>>>(
        qh, kvh, opart, mpart, lpart);

    attn_combine<<<(n4 + 255) / 256, 256>>>(opart, mpart, lpart, ath);

    // proj GEMM: fp16 2-pass (error-margin reserve), fp32 out
    gemm_mma<2><<<dim3(DIMSZ / GBN, MROWS / GBM), 256, GEMM_SMEM>>>(
        ath, ath, wph, wpl, b_proj,
        out, DIMSZ, out, DIMSZ,
        nullptr, nullptr, 1 << 30, 0);
}

// round 15
// speedup vs baseline: 2.5430x; 1.1252x over previous
#include <cuda_runtime.h>
#include <cuda_fp16.h>
#include <cstdint>

#define DIMSZ 2048
#define NHEADS 16
#define HDIM 128
#define BSZ 2
#define LSEQ 2048
#define MROWS (BSZ * LSEQ)   // 4096
#define KDIM 2048
#define SCALE_F 0.08838834764831845f

// ---------------------------------------------------------------------------
// Scratch (__device__ globals; no allocation allowed)
// ---------------------------------------------------------------------------
__device__ __half g_xh[(size_t)MROWS * DIMSZ];              // activations fp16
__device__ __half g_ch[(size_t)MROWS * DIMSZ];
__device__ __half g_wqh[(size_t)3 * DIMSZ * DIMSZ];         // W_qkv^T fp16
__device__ __half g_wph[(size_t)DIMSZ * DIMSZ];             // W_proj^T fp16
__device__ __half g_qh[(size_t)MROWS * DIMSZ];              // q fp16
__device__ __half g_kvh[(size_t)MROWS * 2 * DIMSZ];         // k|v fp16
__device__ __half g_ath[(size_t)MROWS * DIMSZ];             // attn out fp16
// split-KV partials (normalized fp16 O + fp32 m, l)
__device__ __half g_oparth[(size_t)2 * MROWS * DIMSZ];      // 32 MB
__device__ float g_mpart[(size_t)2 * BSZ * NHEADS * LSEQ];
__device__ float g_lpart[(size_t)2 * BSZ * NHEADS * LSEQ];

// ---------------------------------------------------------------------------
// PTX helpers
// ---------------------------------------------------------------------------
__device__ __forceinline__ uint32_t smem_to_u32(const void* p) {
    uint32_t a;
    asm("{ .reg .u64 t; cvta.to.shared.u64 t, %1; cvt.u32.u64 %0, t; }" : "=r"(a) : "l"(p));
    return a;
}

#define CP_ASYNC16(dst, src) \
    asm volatile("cp.async.cg.shared.global [%0], [%1], 16;" :: "r"(dst), "l"(src) : "memory")
#define CP_COMMIT() asm volatile("cp.async.commit_group;" ::: "memory")
#define CP_WAIT(n)  asm volatile("cp.async.wait_group %0;" :: "n"(n) : "memory")

#define LDSM_X4(r0, r1, r2, r3, addr) \
    asm volatile("ldmatrix.sync.aligned.m8n8.x4.shared.b16 {%0,%1,%2,%3}, [%4];" \
                 : "=r"(r0), "=r"(r1), "=r"(r2), "=r"(r3) : "r"(addr))
#define LDSM_X4_T(r0, r1, r2, r3, addr) \
    asm volatile("ldmatrix.sync.aligned.m8n8.x4.trans.shared.b16 {%0,%1,%2,%3}, [%4];" \
                 : "=r"(r0), "=r"(r1), "=r"(r2), "=r"(r3) : "r"(addr))

#define MMA16816(d, a, b0, b1) \
    asm volatile("mma.sync.aligned.m16n8k16.row.col.f32.f16.f16.f32 " \
                 "{%0,%1,%2,%3}, {%4,%5,%6,%7}, {%8,%9}, {%0,%1,%2,%3};" \
                 : "+f"((d)[0]), "+f"((d)[1]), "+f"((d)[2]), "+f"((d)[3]) \
                 : "r"((a)[0]), "r"((a)[1]), "r"((a)[2]), "r"((a)[3]), \
                   "r"(b0), "r"(b1))

__device__ __forceinline__ uint32_t packh(float lo, float hi) {
    uint32_t r;
    asm("cvt.rn.f16x2.f32 %0, %1, %2;" : "=r"(r) : "f"(hi), "f"(lo));
    return r;
}
__device__ __forceinline__ float hlo_f(uint32_t u) {
    unsigned short s = (unsigned short)(u & 0xffffu);
    float f; asm("cvt.f32.f16 %0, %1;" : "=f"(f) : "h"(s));
    return f;
}
__device__ __forceinline__ float hhi_f(uint32_t u) {
    unsigned short s = (unsigned short)(u >> 16);
    float f; asm("cvt.f32.f16 %0, %1;" : "=f"(f) : "h"(s));
    return f;
}

// ---------------------------------------------------------------------------
// Conversion kernels
// ---------------------------------------------------------------------------
__global__ __launch_bounds__(256)
void split_one(const float* __restrict__ in, __half* __restrict__ h, int n4)
{
    int i = blockIdx.x * 256 + threadIdx.x;
    if (i >= n4) return;
    float4 v = ((const float4*)in)[i];
    ((uint32_t*)h)[2 * i]     = packh(v.x, v.y);
    ((uint32_t*)h)[2 * i + 1] = packh(v.z, v.w);
}

__global__ __launch_bounds__(256)
void transpose_one(const float* __restrict__ in, __half* __restrict__ h, int R, int C)
{
    __shared__ float tile[32][33];
    int c0 = blockIdx.x * 32, r0 = blockIdx.y * 32;
    int tx = threadIdx.x & 31, ty = threadIdx.x >> 5;
#pragma unroll
    for (int i = 0; i < 4; i++)
        tile[ty + 8 * i][tx] = in[(size_t)(r0 + ty + 8 * i) * C + c0 + tx];
    __syncthreads();
#pragma unroll
    for (int i = 0; i < 4; i++) {
        float v = tile[tx][ty + 8 * i];
        h[(size_t)(c0 + ty + 8 * i) * R + r0 + tx] = __float2half(v);
    }
}

// ---------------------------------------------------------------------------
// fp16 GEMM, NPASS passes: C = Ah·Bh (+ Ah·Bl if NPASS=2) + bias
// outmode 0: fp32 C;  outmode 2: fp16 C.
// ---------------------------------------------------------------------------
#define GBM 128
#define GBN 128
#define GBK 32
#define NCH (KDIM / GBK)         // 64
#define ROWB 80
#define ATB (128 * ROWB)
#define BTB (128 * ROWB)
#define STAGE_B (ATB + 2 * BTB)  // 30720
#define GEMM_SMEM (2 * STAGE_B)  // 61440

template<int NPASS>
__global__ __launch_bounds__(256, 2)
void gemm_mma(const __half* __restrict__ Ah0, const __half* __restrict__ Ah1,
              const __half* __restrict__ Bh, const __half* __restrict__ Bl,
              const float* __restrict__ bias,
              float* __restrict__ Cf0, int ldc0, float* __restrict__ Cf1, int ldc1,
              __half* __restrict__ Ch0, __half* __restrict__ Ch1,
              int nsplit, int outmode)
{
    extern __shared__ char sm[];
    const uint32_t sbase = smem_to_u32(sm);
    const int tid  = threadIdx.x;
    const int lane = tid & 31;
    const int wid  = tid >> 5;
    const int wm   = (wid & 3) * 32;
    const int wn   = (wid >> 2) * 64;
    const int n0 = blockIdx.x * GBN;
    const int m0 = blockIdx.y * GBM;

    const __half* Ah = (n0 < nsplit) ? Ah0 : Ah1;

    float acc[2][8][4];
#pragma unroll
    for (int i = 0; i < 2; i++)
#pragma unroll
        for (int j = 0; j < 8; j++)
#pragma unroll
            for (int r = 0; r < 4; r++) acc[i][j][r] = 0.f;

    uint32_t aoff[2][2];
#pragma unroll
    for (int mf = 0; mf < 2; mf++)
#pragma unroll
        for (int ks = 0; ks < 2; ks++)
            aoff[mf][ks] = (uint32_t)((wm + mf * 16 + (lane & 15)) * ROWB
                                      + (ks * 16 + 8 * (lane >> 4)) * 2);
    uint32_t boff[4][2];
#pragma unroll
    for (int jj = 0; jj < 4; jj++)
#pragma unroll
        for (int ks = 0; ks < 2; ks++)
            boff[jj][ks] = (uint32_t)((wn + jj * 16 + (lane & 7) + 8 * (lane >> 4)) * ROWB
                                      + (ks * 16 + 8 * ((lane >> 3) & 1)) * 2);

    auto load_chunk = [&](int ic, int s) {
        const int k0 = ic * GBK;
#pragma unroll
        for (int it = 0; it < 2 + 2 * NPASS; it++) {
            const int idx = (it & 1) * 256 + tid;
            const int row = idx >> 2, seg = idx & 3;
            const __half* src;
            uint32_t dst;
            if (it < 2) {
                src = Ah + (size_t)(m0 + row) * KDIM + k0 + seg * 8;
                dst = sbase + s * STAGE_B + row * ROWB + seg * 16;
            } else if (it < 4) {
                src = Bh + (size_t)(n0 + row) * KDIM + k0 + seg * 8;
                dst = sbase + s * STAGE_B + ATB + row * ROWB + seg * 16;
            } else {
                src = Bl + (size_t)(n0 + row) * KDIM + k0 + seg * 8;
                dst = sbase + s * STAGE_B + ATB + BTB + row * ROWB + seg * 16;
            }
            CP_ASYNC16(dst, src);
        }
        CP_COMMIT();
    };

    load_chunk(0, 0);

    for (int ic = 0; ic < NCH; ic++) {
        const int s = ic & 1;
        if (ic + 1 < NCH) { load_chunk(ic + 1, s ^ 1); CP_WAIT(1); }
        else              { CP_WAIT(0); }
        __syncthreads();

        const uint32_t stage = sbase + s * STAGE_B;
#pragma unroll
        for (int ks = 0; ks < 2; ks++) {
            uint32_t a[2][4];
            LDSM_X4(a[0][0], a[0][1], a[0][2], a[0][3], stage + aoff[0][ks]);
            LDSM_X4(a[1][0], a[1][1], a[1][2], a[1][3], stage + aoff[1][ks]);
#pragma unroll
            for (int pass = 0; pass < NPASS; pass++) {
                const uint32_t Bbase = stage + ATB + pass * BTB;
#pragma unroll
                for (int jj = 0; jj < 4; jj++) {
                    uint32_t b0, b1, b2, b3;
                    LDSM_X4(b0, b1, b2, b3, Bbase + boff[jj][ks]);
                    MMA16816(acc[0][jj * 2],     a[0], b0, b1);
                    MMA16816(acc[1][jj * 2],     a[1], b0, b1);
                    MMA16816(acc[0][jj * 2 + 1], a[0], b2, b3);
                    MMA16816(acc[1][jj * 2 + 1], a[1], b2, b3);
                }
            }
        }
        __syncthreads();
    }

    int ld, nc0;
    float* Cf; __half* Ch;
    if (n0 < nsplit) { Cf = Cf0; Ch = Ch0; ld = ldc0; nc0 = n0; }
    else             { Cf = Cf1; Ch = Ch1; ld = ldc1; nc0 = n0 - nsplit; }

#pragma unroll
    for (int mf = 0; mf < 2; mf++) {
#pragma unroll
        for (int nf = 0; nf < 8; nf++) {
            const int nl = wn + nf * 8 + 2 * (lane & 3);
            const float bx = bias[n0 + nl];
            const float by = bias[n0 + nl + 1];
            const int m_up = m0 + wm + mf * 16 + (lane >> 2);
#pragma unroll
            for (int half = 0; half < 2; half++) {
                const int m = m_up + 8 * half;
                float v0 = acc[mf][nf][2 * half]     + bx;
                float v1 = acc[mf][nf][2 * half + 1] + by;
                if (outmode == 0) {
                    float2 v; v.x = v0; v.y = v1;
                    *(float2*)(Cf + (size_t)m * ld + nc0 + nl) = v;
                } else {
                    *(uint32_t*)(Ch + (size_t)m * ld + nc0 + nl) = packh(v0, v1);
                }
            }
        }
    }
}

// ---------------------------------------------------------------------------
// Tensor-core flash attention (pure fp16), split-KV.
// Epilogue writes locally-NORMALIZED fp16 O partials + per-row (m, l).
// ---------------------------------------------------------------------------
#define ASTR 272
#define Q_TILE (128 * ASTR)
#define KV_TILE (64 * ASTR)
#define KV_STAGE (2 * KV_TILE)
#define ATT_SMEM (Q_TILE + 2 * KV_STAGE)   // 104448
#define NTT (LSEQ / 64)
#define NTH (NTT / 2)

__global__ __launch_bounds__(256, 1)
void attn_mma(const __half* __restrict__ Qh, const __half* __restrict__ KVh,
              __half* __restrict__ Opart, float* __restrict__ Mpart, float* __restrict__ Lpart)
{
    extern __shared__ char sm[];
    const uint32_t sQh = smem_to_u32(sm);
    const uint32_t sKV = sQh + Q_TILE;

    const int tid  = threadIdx.x;
    const int lane = tid & 31;
    const int wid  = tid >> 5;
    const int wm   = wid * 16;

    const int qt = blockIdx.x, h = blockIdx.y;
    const int half = blockIdx.z / BSZ;
    const int b    = blockIdx.z % BSZ;
    const int qrow0 = b * LSEQ + qt * 128;
    const int hcol  = h * HDIM;
    const int jt0 = half * NTH, jtN = jt0 + NTH;

#pragma unroll
    for (int i = 0; i < 8; i++) {
        int idx = i * 256 + tid;
        int row = idx >> 4, seg = idx & 15;
        size_t g = (size_t)(qrow0 + row) * DIMSZ + hcol + seg * 8;
        CP_ASYNC16(sQh + row * ASTR + seg * 16, Qh + g);
    }
    CP_COMMIT();

    auto load_kv = [&](int jt, int s) {
        const uint32_t base = sKV + s * KV_STAGE;
        const int krow0 = b * LSEQ + jt * 64;
#pragma unroll
        for (int i = 0; i < 4; i++) {
            int idx = i * 256 + tid;
            int row = idx >> 4, seg = idx & 15;
            size_t roff = (size_t)(krow0 + row) * (2 * DIMSZ);
            uint32_t d = row * ASTR + seg * 16;
            CP_ASYNC16(base + d,           KVh + roff + hcol + seg * 8);
            CP_ASYNC16(base + KV_TILE + d, KVh + roff + DIMSZ + hcol + seg * 8);
        }
        CP_COMMIT();
    };
    load_kv(jt0, 0);

    const uint32_t ab = (uint32_t)((wm + (lane & 15)) * ASTR + (lane >> 4) * 16);
    const uint32_t kb = (uint32_t)(((lane & 7) + 8 * (lane >> 4)) * ASTR
                                   + ((lane >> 3) & 1) * 16);
    const uint32_t vb = (uint32_t)(((lane & 7) + 8 * ((lane >> 3) & 1)) * ASTR
                                   + (lane >> 4) * 16);

    float oacc[16][4];
#pragma unroll
    for (int f = 0; f < 16; f++)
#pragma unroll
        for (int e = 0; e < 4; e++) oacc[f][e] = 0.f;
    float m_prev[2] = {-3.0e38f, -3.0e38f};
    float l_acc[2]  = {0.f, 0.f};

    for (int jt = jt0; jt < jtN; jt++) {
        const int s = jt & 1;
        const bool has_next = (jt + 1 < jtN);
        if (has_next) load_kv(jt + 1, s ^ 1);
        if (has_next) { CP_WAIT(1); } else { CP_WAIT(0); }
        __syncthreads();

        const uint32_t sK = sKV + s * KV_STAGE;
        const uint32_t sV = sK + KV_TILE;

        float sacc[8][4];
#pragma unroll
        for (int f = 0; f < 8; f++)
#pragma unroll
            for (int e = 0; e < 4; e++) sacc[f][e] = 0.f;

#pragma unroll
        for (int ks = 0; ks < 8; ks++) {
            uint32_t ah[4];
            LDSM_X4(ah[0], ah[1], ah[2], ah[3], sQh + ab + ks * 32);
#pragma unroll
            for (int jj = 0; jj < 4; jj++) {
                uint32_t h0, h1, h2, h3;
                LDSM_X4(h0, h1, h2, h3, sK + kb + jj * (16 * ASTR) + ks * 32);
                MMA16816(sacc[2 * jj],     ah, h0, h1);
                MMA16816(sacc[2 * jj + 1], ah, h2, h3);
            }
        }

        float mx0 = -3.0e38f, mx1 = -3.0e38f;
#pragma unroll
        for (int f = 0; f < 8; f++) {
            sacc[f][0] *= SCALE_F; sacc[f][1] *= SCALE_F;
            sacc[f][2] *= SCALE_F; sacc[f][3] *= SCALE_F;
            mx0 = fmaxf(mx0, fmaxf(sacc[f][0], sacc[f][1]));
            mx1 = fmaxf(mx1, fmaxf(sacc[f][2], sacc[f][3]));
        }
        mx0 = fmaxf(mx0, __shfl_xor_sync(0xffffffffu, mx0, 1));
        mx0 = fmaxf(mx0, __shfl_xor_sync(0xffffffffu, mx0, 2));
        mx1 = fmaxf(mx1, __shfl_xor_sync(0xffffffffu, mx1, 1));
        mx1 = fmaxf(mx1, __shfl_xor_sync(0xffffffffu, mx1, 2));

        float mnew0 = fmaxf(m_prev[0], mx0);
        float mnew1 = fmaxf(m_prev[1], mx1);
        float er0 = __expf(m_prev[0] - mnew0);
        float er1 = __expf(m_prev[1] - mnew1);
        m_prev[0] = mnew0; m_prev[1] = mnew1;

        float rsum0 = 0.f, rsum1 = 0.f;
#pragma unroll
        for (int f = 0; f < 8; f++) {
            sacc[f][0] = __expf(sacc[f][0] - mnew0);
            sacc[f][1] = __expf(sacc[f][1] - mnew0);
            sacc[f][2] = __expf(sacc[f][2] - mnew1);
            sacc[f][3] = __expf(sacc[f][3] - mnew1);
            rsum0 += sacc[f][0] + sacc[f][1];
            rsum1 += sacc[f][2] + sacc[f][3];
        }
        rsum0 += __shfl_xor_sync(0xffffffffu, rsum0, 1);
        rsum0 += __shfl_xor_sync(0xffffffffu, rsum0, 2);
        rsum1 += __shfl_xor_sync(0xffffffffu, rsum1, 1);
        rsum1 += __shfl_xor_sync(0xffffffffu, rsum1, 2);
        l_acc[0] = l_acc[0] * er0 + rsum0;
        l_acc[1] = l_acc[1] * er1 + rsum1;

#pragma unroll
        for (int f = 0; f < 16; f++) {
            oacc[f][0] *= er0; oacc[f][1] *= er0;
            oacc[f][2] *= er1; oacc[f][3] *= er1;
        }

        uint32_t aph[4][4];
#pragma unroll
        for (int t = 0; t < 4; t++) {
#pragma unroll
            for (int hh = 0; hh < 2; hh++) {
                const int f = 2 * t + hh;
                aph[t][2 * hh]     = packh(sacc[f][0], sacc[f][1]);
                aph[t][2 * hh + 1] = packh(sacc[f][2], sacc[f][3]);
            }
        }

#pragma unroll
        for (int t = 0; t < 4; t++) {
#pragma unroll
            for (int g = 0; g < 8; g++) {
                uint32_t h0, h1, h2, h3;
                LDSM_X4_T(h0, h1, h2, h3, sV + vb + t * (16 * ASTR) + g * 32);
                MMA16816(oacc[2 * g],     aph[t], h0, h1);
                MMA16816(oacc[2 * g + 1], aph[t], h2, h3);
            }
        }
        __syncthreads();
    }

    // ---- epilogue: locally-normalized fp16 partials + (m, l) ----
#pragma unroll
    for (int rs = 0; rs < 2; rs++) {
        const float inv = 1.0f / l_acc[rs];
        const int lrow = qt * 128 + wm + (lane >> 2) + 8 * rs;
        const size_t orow = ((size_t)half * MROWS + b * LSEQ + lrow) * DIMSZ + hcol;
        if ((lane & 3) == 0) {
            size_t mi = (((size_t)half * BSZ + b) * NHEADS + h) * LSEQ + lrow;
            Mpart[mi] = m_prev[rs];
            Lpart[mi] = l_acc[rs];
        }
#pragma unroll
        for (int f = 0; f < 16; f++) {
            *(uint32_t*)(Opart + orow + f * 8 + 2 * (lane & 3)) =
                packh(oacc[f][2 * rs] * inv, oacc[f][2 * rs + 1] * inv);
        }
    }
}

// ---------------------------------------------------------------------------
// Combine normalized KV-halves: O = w0*O0 + w1*O1, wi = li e^{mi-m} / Σ
// ---------------------------------------------------------------------------
__global__ __launch_bounds__(256)
void attn_combine(const __half* __restrict__ Opart,
                  const float* __restrict__ Mpart, const float* __restrict__ Lpart,
                  __half* __restrict__ Oh)
{
    const size_t i = (size_t)blockIdx.x * 256 + threadIdx.x;   // per 4 elems
    const size_t e = i * 4;
    const int row = (int)(e / DIMSZ);
    const int col = (int)(e % DIMSZ);
    const int h = col >> 7;
    const int b = row / LSEQ;
    const int lr = row % LSEQ;

    const size_t mi0 = (((size_t)0 * BSZ + b) * NHEADS + h) * LSEQ + lr;
    const size_t mi1 = (((size_t)1 * BSZ + b) * NHEADS + h) * LSEQ + lr;
    const float m0 = Mpart[mi0], m1 = Mpart[mi1];
    const float l0 = Lpart[mi0], l1 = Lpart[mi1];
    const float m  = fmaxf(m0, m1);
    const float s0 = l0 * __expf(m0 - m), s1 = l1 * __expf(m1 - m);
    const float inv = 1.0f / (s0 + s1);
    const float w0 = s0 * inv, w1 = s1 * inv;

    uint2 a = ((const uint2*)Opart)[i];
    uint2 c = ((const uint2*)(Opart + (size_t)MROWS * DIMSZ))[i];
    float v0 = hlo_f(a.x) * w0 + hlo_f(c.x) * w1;
    float v1 = hhi_f(a.x) * w0 + hhi_f(c.x) * w1;
    float v2 = hlo_f(a.y) * w0 + hlo_f(c.y) * w1;
    float v3 = hhi_f(a.y) * w0 + hhi_f(c.y) * w1;

    uint2 o;
    o.x = packh(v0, v1);
    o.y = packh(v2, v3);
    ((uint2*)Oh)[i] = o;
}

// ---------------------------------------------------------------------------
extern "C" void kernel_launch(void* const* d_in, const int* in_sizes, int n_in,
                              void* d_out, int out_size)
{
    const float* x       = (const float*)d_in[0];
    const float* context = (const float*)d_in[1];
    const float* W_qkv   = (const float*)d_in[2];
    const float* b_qkv   = (const float*)d_in[3];
    const float* W_proj  = (const float*)d_in[4];
    const float* b_proj  = (const float*)d_in[5];
    float* out = (float*)d_out;

    __half *xh, *ch, *wqh, *wph;
    __half *qh, *kvh, *ath, *oparth;
    float *mpart, *lpart;
    cudaGetSymbolAddress((void**)&xh,  g_xh);
    cudaGetSymbolAddress((void**)&ch,  g_ch);
    cudaGetSymbolAddress((void**)&wqh, g_wqh);
    cudaGetSymbolAddress((void**)&wph, g_wph);
    cudaGetSymbolAddress((void**)&qh,  g_qh);
    cudaGetSymbolAddress((void**)&kvh, g_kvh);
    cudaGetSymbolAddress((void**)&ath, g_ath);
    cudaGetSymbolAddress((void**)&oparth, g_oparth);
    cudaGetSymbolAddress((void**)&mpart, g_mpart);
    cudaGetSymbolAddress((void**)&lpart, g_lpart);

    cudaFuncSetAttribute(gemm_mma<1>, cudaFuncAttributeMaxDynamicSharedMemorySize, GEMM_SMEM);
    cudaFuncSetAttribute(attn_mma, cudaFuncAttributeMaxDynamicSharedMemorySize, ATT_SMEM);

    const int n4 = MROWS * DIMSZ / 4;

    split_one<<<(n4 + 255) / 256, 256>>>(x, xh, n4);
    split_one<<<(n4 + 255) / 256, 256>>>(context, ch, n4);
    transpose_one<<<dim3(3 * DIMSZ / 32, DIMSZ / 32), 256>>>(W_qkv, wqh, DIMSZ, 3 * DIMSZ);
    transpose_one<<<dim3(DIMSZ / 32, DIMSZ / 32), 256>>>(W_proj, wph, DIMSZ, DIMSZ);

    // qkv GEMM: pure fp16, 1 pass
    gemm_mma<1><<<dim3(3 * DIMSZ / GBN, MROWS / GBM), 256, GEMM_SMEM>>>(
        xh, ch, wqh, nullptr, b_qkv,
        nullptr, DIMSZ, nullptr, 2 * DIMSZ,
        qh, kvh, DIMSZ, 2);

    // split-KV attention (pure fp16, normalized fp16 partials)
    attn_mma<<<dim3(LSEQ / 128, NHEADS, 2 * BSZ), 256, ATT_SMEM>>>(
        qh, kvh, oparth, mpart, lpart);

    attn_combine<<<(n4 + 255) / 256, 256>>>(oparth, mpart, lpart, ath);

    // proj GEMM: pure fp16, 1 pass, fp32 out
    gemm_mma<1><<<dim3(DIMSZ / GBN, MROWS / GBM), 256, GEMM_SMEM>>>(
        ath, ath, wph, nullptr, b_proj,
        out, DIMSZ, out, DIMSZ,
        nullptr, nullptr, 1 << 30, 0);
}

// round 16
// speedup vs baseline: 2.6196x; 1.0301x over previous
#include <cuda_runtime.h>
#include <cuda_fp16.h>
#include <cstdint>

#define DIMSZ 2048
#define NHEADS 16
#define HDIM 128
#define BSZ 2
#define LSEQ 2048
#define MROWS (BSZ * LSEQ)   // 4096
#define KDIM 2048
#define SCALE_L2E 0.1275477292f   // (1/sqrt(128)) * log2(e)

// ---------------------------------------------------------------------------
// Scratch (__device__ globals; no allocation allowed)
// ---------------------------------------------------------------------------
__device__ __half g_xh[(size_t)MROWS * DIMSZ];
__device__ __half g_ch[(size_t)MROWS * DIMSZ];
__device__ __half g_wqh[(size_t)3 * DIMSZ * DIMSZ];
__device__ __half g_wph[(size_t)DIMSZ * DIMSZ];
__device__ __half g_qh[(size_t)MROWS * DIMSZ];              // q fp16 (pre-scaled by SCALE_L2E)
__device__ __half g_kvh[(size_t)MROWS * 2 * DIMSZ];
__device__ __half g_ath[(size_t)MROWS * DIMSZ];
__device__ __half g_oparth[(size_t)2 * MROWS * DIMSZ];
__device__ float g_mpart[(size_t)2 * BSZ * NHEADS * LSEQ];  // log2-domain m
__device__ float g_lpart[(size_t)2 * BSZ * NHEADS * LSEQ];

// ---------------------------------------------------------------------------
// PTX helpers
// ---------------------------------------------------------------------------
__device__ __forceinline__ uint32_t smem_to_u32(const void* p) {
    uint32_t a;
    asm("{ .reg .u64 t; cvta.to.shared.u64 t, %1; cvt.u32.u64 %0, t; }" : "=r"(a) : "l"(p));
    return a;
}

#define CP_ASYNC16(dst, src) \
    asm volatile("cp.async.cg.shared.global [%0], [%1], 16;" :: "r"(dst), "l"(src) : "memory")
#define CP_COMMIT() asm volatile("cp.async.commit_group;" ::: "memory")
#define CP_WAIT(n)  asm volatile("cp.async.wait_group %0;" :: "n"(n) : "memory")

#define LDSM_X4(r0, r1, r2, r3, addr) \
    asm volatile("ldmatrix.sync.aligned.m8n8.x4.shared.b16 {%0,%1,%2,%3}, [%4];" \
                 : "=r"(r0), "=r"(r1), "=r"(r2), "=r"(r3) : "r"(addr))
#define LDSM_X4_T(r0, r1, r2, r3, addr) \
    asm volatile("ldmatrix.sync.aligned.m8n8.x4.trans.shared.b16 {%0,%1,%2,%3}, [%4];" \
                 : "=r"(r0), "=r"(r1), "=r"(r2), "=r"(r3) : "r"(addr))

#define MMA16816(d, a, b0, b1) \
    asm volatile("mma.sync.aligned.m16n8k16.row.col.f32.f16.f16.f32 " \
                 "{%0,%1,%2,%3}, {%4,%5,%6,%7}, {%8,%9}, {%0,%1,%2,%3};" \
                 : "+f"((d)[0]), "+f"((d)[1]), "+f"((d)[2]), "+f"((d)[3]) \
                 : "r"((a)[0]), "r"((a)[1]), "r"((a)[2]), "r"((a)[3]), \
                   "r"(b0), "r"(b1))

__device__ __forceinline__ uint32_t packh(float lo, float hi) {
    uint32_t r;
    asm("cvt.rn.f16x2.f32 %0, %1, %2;" : "=r"(r) : "f"(hi), "f"(lo));
    return r;
}
__device__ __forceinline__ float hlo_f(uint32_t u) {
    unsigned short s = (unsigned short)(u & 0xffffu);
    float f; asm("cvt.f32.f16 %0, %1;" : "=f"(f) : "h"(s));
    return f;
}
__device__ __forceinline__ float hhi_f(uint32_t u) {
    unsigned short s = (unsigned short)(u >> 16);
    float f; asm("cvt.f32.f16 %0, %1;" : "=f"(f) : "h"(s));
    return f;
}
__device__ __forceinline__ float ex2f(float x) {
    float r; asm("ex2.approx.f32 %0, %1;" : "=f"(r) : "f"(x)); return r;
}

// ---------------------------------------------------------------------------
// Conversion kernels
// ---------------------------------------------------------------------------
__global__ __launch_bounds__(256)
void split_one(const float* __restrict__ in, __half* __restrict__ h, int n4)
{
    int i = blockIdx.x * 256 + threadIdx.x;
    if (i >= n4) return;
    float4 v = ((const float4*)in)[i];
    ((uint32_t*)h)[2 * i]     = packh(v.x, v.y);
    ((uint32_t*)h)[2 * i + 1] = packh(v.z, v.w);
}

__global__ __launch_bounds__(256)
void transpose_one(const float* __restrict__ in, __half* __restrict__ h, int R, int C)
{
    __shared__ float tile[32][33];
    int c0 = blockIdx.x * 32, r0 = blockIdx.y * 32;
    int tx = threadIdx.x & 31, ty = threadIdx.x >> 5;
#pragma unroll
    for (int i = 0; i < 4; i++)
        tile[ty + 8 * i][tx] = in[(size_t)(r0 + ty + 8 * i) * C + c0 + tx];
    __syncthreads();
#pragma unroll
    for (int i = 0; i < 4; i++) {
        float v = tile[tx][ty + 8 * i];
        h[(size_t)(c0 + ty + 8 * i) * R + r0 + tx] = __float2half(v);
    }
}

// ---------------------------------------------------------------------------
// fp16 1-pass GEMM: C = Ah·Bh + bias  (optionally scaled in outmode 2)
// outmode 0: fp32 C;  outmode 2: fp16 C scaled by csc (per-region).
// ---------------------------------------------------------------------------
#define GBM 128
#define GBN 128
#define GBK 32
#define NCH (KDIM / GBK)
#define ROWB 80
#define ATB (128 * ROWB)
#define BTB (128 * ROWB)
#define STAGE_B (ATB + 2 * BTB)
#define GEMM_SMEM (2 * STAGE_B)

template<int NPASS>
__global__ __launch_bounds__(256, 2)
void gemm_mma(const __half* __restrict__ Ah0, const __half* __restrict__ Ah1,
              const __half* __restrict__ Bh, const __half* __restrict__ Bl,
              const float* __restrict__ bias,
              float* __restrict__ Cf0, int ldc0, float* __restrict__ Cf1, int ldc1,
              __half* __restrict__ Ch0, __half* __restrict__ Ch1,
              int nsplit, int outmode, float csc0, float csc1)
{
    extern __shared__ char sm[];
    const uint32_t sbase = smem_to_u32(sm);
    const int tid  = threadIdx.x;
    const int lane = tid & 31;
    const int wid  = tid >> 5;
    const int wm   = (wid & 3) * 32;
    const int wn   = (wid >> 2) * 64;
    const int n0 = blockIdx.x * GBN;
    const int m0 = blockIdx.y * GBM;

    const __half* Ah = (n0 < nsplit) ? Ah0 : Ah1;

    float acc[2][8][4];
#pragma unroll
    for (int i = 0; i < 2; i++)
#pragma unroll
        for (int j = 0; j < 8; j++)
#pragma unroll
            for (int r = 0; r < 4; r++) acc[i][j][r] = 0.f;

    uint32_t aoff[2][2];
#pragma unroll
    for (int mf = 0; mf < 2; mf++)
#pragma unroll
        for (int ks = 0; ks < 2; ks++)
            aoff[mf][ks] = (uint32_t)((wm + mf * 16 + (lane & 15)) * ROWB
                                      + (ks * 16 + 8 * (lane >> 4)) * 2);
    uint32_t boff[4][2];
#pragma unroll
    for (int jj = 0; jj < 4; jj++)
#pragma unroll
        for (int ks = 0; ks < 2; ks++)
            boff[jj][ks] = (uint32_t)((wn + jj * 16 + (lane & 7) + 8 * (lane >> 4)) * ROWB
                                      + (ks * 16 + 8 * ((lane >> 3) & 1)) * 2);

    auto load_chunk = [&](int ic, int s) {
        const int k0 = ic * GBK;
#pragma unroll
        for (int it = 0; it < 2 + 2 * NPASS; it++) {
            const int idx = (it & 1) * 256 + tid;
            const int row = idx >> 2, seg = idx & 3;
            const __half* src;
            uint32_t dst;
            if (it < 2) {
                src = Ah + (size_t)(m0 + row) * KDIM + k0 + seg * 8;
                dst = sbase + s * STAGE_B + row * ROWB + seg * 16;
            } else if (it < 4) {
                src = Bh + (size_t)(n0 + row) * KDIM + k0 + seg * 8;
                dst = sbase + s * STAGE_B + ATB + row * ROWB + seg * 16;
            } else {
                src = Bl + (size_t)(n0 + row) * KDIM + k0 + seg * 8;
                dst = sbase + s * STAGE_B + ATB + BTB + row * ROWB + seg * 16;
            }
            CP_ASYNC16(dst, src);
        }
        CP_COMMIT();
    };

    load_chunk(0, 0);

    for (int ic = 0; ic < NCH; ic++) {
        const int s = ic & 1;
        if (ic + 1 < NCH) { load_chunk(ic + 1, s ^ 1); CP_WAIT(1); }
        else              { CP_WAIT(0); }
        __syncthreads();

        const uint32_t stage = sbase + s * STAGE_B;
#pragma unroll
        for (int ks = 0; ks < 2; ks++) {
            uint32_t a[2][4];
            LDSM_X4(a[0][0], a[0][1], a[0][2], a[0][3], stage + aoff[0][ks]);
            LDSM_X4(a[1][0], a[1][1], a[1][2], a[1][3], stage + aoff[1][ks]);
#pragma unroll
            for (int pass = 0; pass < NPASS; pass++) {
                const uint32_t Bbase = stage + ATB + pass * BTB;
#pragma unroll
                for (int jj = 0; jj < 4; jj++) {
                    uint32_t b0, b1, b2, b3;
                    LDSM_X4(b0, b1, b2, b3, Bbase + boff[jj][ks]);
                    MMA16816(acc[0][jj * 2],     a[0], b0, b1);
                    MMA16816(acc[1][jj * 2],     a[1], b0, b1);
                    MMA16816(acc[0][jj * 2 + 1], a[0], b2, b3);
                    MMA16816(acc[1][jj * 2 + 1], a[1], b2, b3);
                }
            }
        }
        __syncthreads();
    }

    int ld, nc0;
    float* Cf; __half* Ch; float csc;
    if (n0 < nsplit) { Cf = Cf0; Ch = Ch0; ld = ldc0; nc0 = n0; csc = csc0; }
    else             { Cf = Cf1; Ch = Ch1; ld = ldc1; nc0 = n0 - nsplit; csc = csc1; }

#pragma unroll
    for (int mf = 0; mf < 2; mf++) {
#pragma unroll
        for (int nf = 0; nf < 8; nf++) {
            const int nl = wn + nf * 8 + 2 * (lane & 3);
            const float bx = bias[n0 + nl];
            const float by = bias[n0 + nl + 1];
            const int m_up = m0 + wm + mf * 16 + (lane >> 2);
#pragma unroll
            for (int half = 0; half < 2; half++) {
                const int m = m_up + 8 * half;
                float v0 = acc[mf][nf][2 * half]     + bx;
                float v1 = acc[mf][nf][2 * half + 1] + by;
                if (outmode == 0) {
                    float2 v; v.x = v0; v.y = v1;
                    *(float2*)(Cf + (size_t)m * ld + nc0 + nl) = v;
                } else {
                    *(uint32_t*)(Ch + (size_t)m * ld + nc0 + nl) = packh(v0 * csc, v1 * csc);
                }
            }
        }
    }
}

// ---------------------------------------------------------------------------
// Tensor-core flash attention (pure fp16, log2-domain softmax, BK=128),
// split-KV with normalized fp16 partials.
// ---------------------------------------------------------------------------
#define ASTR 272
#define Q_TILE (128 * ASTR)
#define KV_TILE (128 * ASTR)               // 128 k-rows per tile
#define KV_STAGE (2 * KV_TILE)             // [K][V]
#define ATT_SMEM (Q_TILE + 2 * KV_STAGE)   // 174080
#define NTT (LSEQ / 128)                   // 16
#define NTH (NTT / 2)                      // 8 per half

__global__ __launch_bounds__(256, 1)
void attn_mma(const __half* __restrict__ Qh, const __half* __restrict__ KVh,
              __half* __restrict__ Opart, float* __restrict__ Mpart, float* __restrict__ Lpart)
{
    extern __shared__ char sm[];
    const uint32_t sQh = smem_to_u32(sm);
    const uint32_t sKV = sQh + Q_TILE;

    const int tid  = threadIdx.x;
    const int lane = tid & 31;
    const int wid  = tid >> 5;
    const int wm   = wid * 16;

    const int qt = blockIdx.x, h = blockIdx.y;
    const int half = blockIdx.z / BSZ;
    const int b    = blockIdx.z % BSZ;
    const int qrow0 = b * LSEQ + qt * 128;
    const int hcol  = h * HDIM;
    const int jt0 = half * NTH, jtN = jt0 + NTH;

#pragma unroll
    for (int i = 0; i < 8; i++) {
        int idx = i * 256 + tid;
        int row = idx >> 4, seg = idx & 15;
        size_t g = (size_t)(qrow0 + row) * DIMSZ + hcol + seg * 8;
        CP_ASYNC16(sQh + row * ASTR + seg * 16, Qh + g);
    }
    CP_COMMIT();

    auto load_kv = [&](int jt, int s) {
        const uint32_t base = sKV + s * KV_STAGE;
        const int krow0 = b * LSEQ + jt * 128;
#pragma unroll
        for (int i = 0; i < 8; i++) {
            int idx = i * 256 + tid;
            int row = idx >> 4, seg = idx & 15;
            size_t roff = (size_t)(krow0 + row) * (2 * DIMSZ);
            uint32_t d = row * ASTR + seg * 16;
            CP_ASYNC16(base + d,           KVh + roff + hcol + seg * 8);
            CP_ASYNC16(base + KV_TILE + d, KVh + roff + DIMSZ + hcol + seg * 8);
        }
        CP_COMMIT();
    };
    load_kv(jt0, 0);

    const uint32_t ab = (uint32_t)((wm + (lane & 15)) * ASTR + (lane >> 4) * 16);
    const uint32_t kb = (uint32_t)(((lane & 7) + 8 * (lane >> 4)) * ASTR
                                   + ((lane >> 3) & 1) * 16);
    const uint32_t vb = (uint32_t)(((lane & 7) + 8 * ((lane >> 3) & 1)) * ASTR
                                   + (lane >> 4) * 16);

    float oacc[16][4];
#pragma unroll
    for (int f = 0; f < 16; f++)
#pragma unroll
        for (int e = 0; e < 4; e++) oacc[f][e] = 0.f;
    float m_prev[2] = {-3.0e38f, -3.0e38f};
    float l_acc[2]  = {0.f, 0.f};

    for (int jt = jt0; jt < jtN; jt++) {
        const int s = jt & 1;
        const bool has_next = (jt + 1 < jtN);
        if (has_next) load_kv(jt + 1, s ^ 1);
        if (has_next) { CP_WAIT(1); } else { CP_WAIT(0); }
        __syncthreads();

        const uint32_t sK = sKV + s * KV_STAGE;
        const uint32_t sV = sK + KV_TILE;

        // ---- S = Qh Kh^T  (scores already in log2 domain; q pre-scaled) ----
        float sacc[16][4];
#pragma unroll
        for (int f = 0; f < 16; f++)
#pragma unroll
            for (int e = 0; e < 4; e++) sacc[f][e] = 0.f;

#pragma unroll
        for (int ks = 0; ks < 8; ks++) {
            uint32_t ah[4];
            LDSM_X4(ah[0], ah[1], ah[2], ah[3], sQh + ab + ks * 32);
#pragma unroll
            for (int jj = 0; jj < 8; jj++) {
                uint32_t h0, h1, h2, h3;
                LDSM_X4(h0, h1, h2, h3, sK + kb + jj * (16 * ASTR) + ks * 32);
                MMA16816(sacc[2 * jj],     ah, h0, h1);
                MMA16816(sacc[2 * jj + 1], ah, h2, h3);
            }
        }

        // ---- log2-domain online softmax ----
        float mx0 = -3.0e38f, mx1 = -3.0e38f;
#pragma unroll
        for (int f = 0; f < 16; f++) {
            mx0 = fmaxf(mx0, fmaxf(sacc[f][0], sacc[f][1]));
            mx1 = fmaxf(mx1, fmaxf(sacc[f][2], sacc[f][3]));
        }
        mx0 = fmaxf(mx0, __shfl_xor_sync(0xffffffffu, mx0, 1));
        mx0 = fmaxf(mx0, __shfl_xor_sync(0xffffffffu, mx0, 2));
        mx1 = fmaxf(mx1, __shfl_xor_sync(0xffffffffu, mx1, 1));
        mx1 = fmaxf(mx1, __shfl_xor_sync(0xffffffffu, mx1, 2));

        float mnew0 = fmaxf(m_prev[0], mx0);
        float mnew1 = fmaxf(m_prev[1], mx1);
        float er0 = ex2f(m_prev[0] - mnew0);
        float er1 = ex2f(m_prev[1] - mnew1);
        m_prev[0] = mnew0; m_prev[1] = mnew1;

        float rsum0 = 0.f, rsum1 = 0.f;
#pragma unroll
        for (int f = 0; f < 16; f++) {
            sacc[f][0] = ex2f(sacc[f][0] - mnew0);
            sacc[f][1] = ex2f(sacc[f][1] - mnew0);
            sacc[f][2] = ex2f(sacc[f][2] - mnew1);
            sacc[f][3] = ex2f(sacc[f][3] - mnew1);
            rsum0 += sacc[f][0] + sacc[f][1];
            rsum1 += sacc[f][2] + sacc[f][3];
        }
        rsum0 += __shfl_xor_sync(0xffffffffu, rsum0, 1);
        rsum0 += __shfl_xor_sync(0xffffffffu, rsum0, 2);
        rsum1 += __shfl_xor_sync(0xffffffffu, rsum1, 1);
        rsum1 += __shfl_xor_sync(0xffffffffu, rsum1, 2);
        l_acc[0] = l_acc[0] * er0 + rsum0;
        l_acc[1] = l_acc[1] * er1 + rsum1;

#pragma unroll
        for (int f = 0; f < 16; f++) {
            oacc[f][0] *= er0; oacc[f][1] *= er0;
            oacc[f][2] *= er1; oacc[f][3] *= er1;
        }

        // ---- pack P (fp16) ----
        uint32_t aph[8][4];
#pragma unroll
        for (int t = 0; t < 8; t++) {
#pragma unroll
            for (int hh = 0; hh < 2; hh++) {
                const int f = 2 * t + hh;
                aph[t][2 * hh]     = packh(sacc[f][0], sacc[f][1]);
                aph[t][2 * hh + 1] = packh(sacc[f][2], sacc[f][3]);
            }
        }

        // ---- O += Ph Vh ----
#pragma unroll
        for (int t = 0; t < 8; t++) {
#pragma unroll
            for (int g = 0; g < 8; g++) {
                uint32_t h0, h1, h2, h3;
                LDSM_X4_T(h0, h1, h2, h3, sV + vb + t * (16 * ASTR) + g * 32);
                MMA16816(oacc[2 * g],     aph[t], h0, h1);
                MMA16816(oacc[2 * g + 1], aph[t], h2, h3);
            }
        }
        __syncthreads();
    }

    // ---- epilogue: locally-normalized fp16 partials + (m, l) ----
#pragma unroll
    for (int rs = 0; rs < 2; rs++) {
        const float inv = 1.0f / l_acc[rs];
        const int lrow = qt * 128 + wm + (lane >> 2) + 8 * rs;
        const size_t orow = ((size_t)half * MROWS + b * LSEQ + lrow) * DIMSZ + hcol;
        if ((lane & 3) == 0) {
            size_t mi = (((size_t)half * BSZ + b) * NHEADS + h) * LSEQ + lrow;
            Mpart[mi] = m_prev[rs];
            Lpart[mi] = l_acc[rs];
        }
#pragma unroll
        for (int f = 0; f < 16; f++) {
            *(uint32_t*)(Opart + orow + f * 8 + 2 * (lane & 3)) =
                packh(oacc[f][2 * rs] * inv, oacc[f][2 * rs + 1] * inv);
        }
    }
}

// ---------------------------------------------------------------------------
// Combine normalized KV-halves (log2-domain m): wi = li·2^(mi−m) / Σ
// ---------------------------------------------------------------------------
__global__ __launch_bounds__(256)
void attn_combine(const __half* __restrict__ Opart,
                  const float* __restrict__ Mpart, const float* __restrict__ Lpart,
                  __half* __restrict__ Oh)
{
    const size_t i = (size_t)blockIdx.x * 256 + threadIdx.x;
    const size_t e = i * 4;
    const int row = (int)(e / DIMSZ);
    const int col = (int)(e % DIMSZ);
    const int h = col >> 7;
    const int b = row / LSEQ;
    const int lr = row % LSEQ;

    const size_t mi0 = (((size_t)0 * BSZ + b) * NHEADS + h) * LSEQ + lr;
    const size_t mi1 = (((size_t)1 * BSZ + b) * NHEADS + h) * LSEQ + lr;
    const float m0 = Mpart[mi0], m1 = Mpart[mi1];
    const float l0 = Lpart[mi0], l1 = Lpart[mi1];
    const float m  = fmaxf(m0, m1);
    const float s0 = l0 * ex2f(m0 - m), s1 = l1 * ex2f(m1 - m);
    const float inv = 1.0f / (s0 + s1);
    const float w0 = s0 * inv, w1 = s1 * inv;

    uint2 a = ((const uint2*)Opart)[i];
    uint2 c = ((const uint2*)(Opart + (size_t)MROWS * DIMSZ))[i];
    float v0 = hlo_f(a.x) * w0 + hlo_f(c.x) * w1;
    float v1 = hhi_f(a.x) * w0 + hhi_f(c.x) * w1;
    float v2 = hlo_f(a.y) * w0 + hlo_f(c.y) * w1;
    float v3 = hhi_f(a.y) * w0 + hhi_f(c.y) * w1;

    uint2 o;
    o.x = packh(v0, v1);
    o.y = packh(v2, v3);
    ((uint2*)Oh)[i] = o;
}

// ---------------------------------------------------------------------------
extern "C" void kernel_launch(void* const* d_in, const int* in_sizes, int n_in,
                              void* d_out, int out_size)
{
    const float* x       = (const float*)d_in[0];
    const float* context = (const float*)d_in[1];
    const float* W_qkv   = (const float*)d_in[2];
    const float* b_qkv   = (const float*)d_in[3];
    const float* W_proj  = (const float*)d_in[4];
    const float* b_proj  = (const float*)d_in[5];
    float* out = (float*)d_out;

    __half *xh, *ch, *wqh, *wph;
    __half *qh, *kvh, *ath, *oparth;
    float *mpart, *lpart;
    cudaGetSymbolAddress((void**)&xh,  g_xh);
    cudaGetSymbolAddress((void**)&ch,  g_ch);
    cudaGetSymbolAddress((void**)&wqh, g_wqh);
    cudaGetSymbolAddress((void**)&wph, g_wph);
    cudaGetSymbolAddress((void**)&qh,  g_qh);
    cudaGetSymbolAddress((void**)&kvh, g_kvh);
    cudaGetSymbolAddress((void**)&ath, g_ath);
    cudaGetSymbolAddress((void**)&oparth, g_oparth);
    cudaGetSymbolAddress((void**)&mpart, g_mpart);
    cudaGetSymbolAddress((void**)&lpart, g_lpart);

    cudaFuncSetAttribute(gemm_mma<1>, cudaFuncAttributeMaxDynamicSharedMemorySize, GEMM_SMEM);
    cudaFuncSetAttribute(attn_mma, cudaFuncAttributeMaxDynamicSharedMemorySize, ATT_SMEM);

    const int n4 = MROWS * DIMSZ / 4;

    split_one<<<(n4 + 255) / 256, 256>>>(x, xh, n4);
    split_one<<<(n4 + 255) / 256, 256>>>(context, ch, n4);
    transpose_one<<<dim3(3 * DIMSZ / 32, DIMSZ / 32), 256>>>(W_qkv, wqh, DIMSZ, 3 * DIMSZ);
    transpose_one<<<dim3(DIMSZ / 32, DIMSZ / 32), 256>>>(W_proj, wph, DIMSZ, DIMSZ);

    // qkv GEMM: pure fp16, 1 pass; q outputs pre-scaled by SCALE*log2(e)
    gemm_mma<1><<<dim3(3 * DIMSZ / GBN, MROWS / GBM), 256, GEMM_SMEM>>>(
        xh, ch, wqh, nullptr, b_qkv,
        nullptr, DIMSZ, nullptr, 2 * DIMSZ,
        qh, kvh, DIMSZ, 2, SCALE_L2E, 1.0f);

    // split-KV attention (pure fp16, log2 softmax, BK=128)
    attn_mma<<<dim3(LSEQ / 128, NHEADS, 2 * BSZ), 256, ATT_SMEM>>>(
        qh, kvh, oparth, mpart, lpart);

    attn_combine<<<(n4 + 255) / 256, 256>>>(oparth, mpart, lpart, ath);

    // proj GEMM: pure fp16, 1 pass, fp32 out
    gemm_mma<1><<<dim3(DIMSZ / GBN, MROWS / GBM), 256, GEMM_SMEM>>>(
        ath, ath, wph, nullptr, b_proj,
        out, DIMSZ, out, DIMSZ,
        nullptr, nullptr, 1 << 30, 0, 1.0f, 1.0f);
}

// round 17
// speedup vs baseline: 2.6339x; 1.0055x over previous
#include <cuda_runtime.h>
#include <cuda_fp16.h>
#include <cstdint>

#define DIMSZ 2048
#define NHEADS 16
#define HDIM 128
#define BSZ 2
#define LSEQ 2048
#define MROWS (BSZ * LSEQ)   // 4096
#define KDIM 2048
#define SCALE_L2E 0.1275477292f   // (1/sqrt(128)) * log2(e)

// ---------------------------------------------------------------------------
// Scratch (__device__ globals; no allocation allowed)
// ---------------------------------------------------------------------------
__device__ __half g_xh[(size_t)MROWS * DIMSZ];
__device__ __half g_ch[(size_t)MROWS * DIMSZ];
__device__ __half g_wqh[(size_t)3 * DIMSZ * DIMSZ];
__device__ __half g_wph[(size_t)DIMSZ * DIMSZ];
__device__ __half g_qh[(size_t)MROWS * DIMSZ];              // q fp16 (pre-scaled by SCALE_L2E)
__device__ __half g_kvh[(size_t)MROWS * 2 * DIMSZ];
__device__ __half g_ath[(size_t)MROWS * DIMSZ];
__device__ __half g_oparth[(size_t)2 * MROWS * DIMSZ];
__device__ float g_mpart[(size_t)2 * BSZ * NHEADS * LSEQ];  // log2-domain m
__device__ float g_lpart[(size_t)2 * BSZ * NHEADS * LSEQ];

// ---------------------------------------------------------------------------
// PTX helpers
// ---------------------------------------------------------------------------
__device__ __forceinline__ uint32_t smem_to_u32(const void* p) {
    uint32_t a;
    asm("{ .reg .u64 t; cvta.to.shared.u64 t, %1; cvt.u32.u64 %0, t; }" : "=r"(a) : "l"(p));
    return a;
}

#define CP_ASYNC16(dst, src) \
    asm volatile("cp.async.cg.shared.global [%0], [%1], 16;" :: "r"(dst), "l"(src) : "memory")
#define CP_COMMIT() asm volatile("cp.async.commit_group;" ::: "memory")
#define CP_WAIT(n)  asm volatile("cp.async.wait_group %0;" :: "n"(n) : "memory")

#define LDSM_X4(r0, r1, r2, r3, addr) \
    asm volatile("ldmatrix.sync.aligned.m8n8.x4.shared.b16 {%0,%1,%2,%3}, [%4];" \
                 : "=r"(r0), "=r"(r1), "=r"(r2), "=r"(r3) : "r"(addr))
#define LDSM_X4_T(r0, r1, r2, r3, addr) \
    asm volatile("ldmatrix.sync.aligned.m8n8.x4.trans.shared.b16 {%0,%1,%2,%3}, [%4];" \
                 : "=r"(r0), "=r"(r1), "=r"(r2), "=r"(r3) : "r"(addr))
#define LDSM_X2_T(r0, r1, addr) \
    asm volatile("ldmatrix.sync.aligned.m8n8.x2.trans.shared.b16 {%0,%1}, [%2];" \
                 : "=r"(r0), "=r"(r1) : "r"(addr))

#define MMA16816(d, a, b0, b1) \
    asm volatile("mma.sync.aligned.m16n8k16.row.col.f32.f16.f16.f32 " \
                 "{%0,%1,%2,%3}, {%4,%5,%6,%7}, {%8,%9}, {%0,%1,%2,%3};" \
                 : "+f"((d)[0]), "+f"((d)[1]), "+f"((d)[2]), "+f"((d)[3]) \
                 : "r"((a)[0]), "r"((a)[1]), "r"((a)[2]), "r"((a)[3]), \
                   "r"(b0), "r"(b1))

__device__ __forceinline__ uint32_t packh(float lo, float hi) {
    uint32_t r;
    asm("cvt.rn.f16x2.f32 %0, %1, %2;" : "=r"(r) : "f"(hi), "f"(lo));
    return r;
}
__device__ __forceinline__ float hlo_f(uint32_t u) {
    unsigned short s = (unsigned short)(u & 0xffffu);
    float f; asm("cvt.f32.f16 %0, %1;" : "=f"(f) : "h"(s));
    return f;
}
__device__ __forceinline__ float hhi_f(uint32_t u) {
    unsigned short s = (unsigned short)(u >> 16);
    float f; asm("cvt.f32.f16 %0, %1;" : "=f"(f) : "h"(s));
    return f;
}
__device__ __forceinline__ float ex2f(float x) {
    float r; asm("ex2.approx.f32 %0, %1;" : "=f"(r) : "f"(x)); return r;
}
__device__ __forceinline__ uint32_t h2exp2(uint32_t x) {
    uint32_t r; asm("ex2.approx.f16x2 %0, %1;" : "=r"(r) : "r"(x)); return r;
}

// ---------------------------------------------------------------------------
// Conversion kernels
// ---------------------------------------------------------------------------
__global__ __launch_bounds__(256)
void split_one(const float* __restrict__ in, __half* __restrict__ h, int n4)
{
    int i = blockIdx.x * 256 + threadIdx.x;
    if (i >= n4) return;
    float4 v = ((const float4*)in)[i];
    ((uint32_t*)h)[2 * i]     = packh(v.x, v.y);
    ((uint32_t*)h)[2 * i + 1] = packh(v.z, v.w);
}

__global__ __launch_bounds__(256)
void transpose_one(const float* __restrict__ in, __half* __restrict__ h, int R, int C)
{
    __shared__ float tile[32][33];
    int c0 = blockIdx.x * 32, r0 = blockIdx.y * 32;
    int tx = threadIdx.x & 31, ty = threadIdx.x >> 5;
#pragma unroll
    for (int i = 0; i < 4; i++)
        tile[ty + 8 * i][tx] = in[(size_t)(r0 + ty + 8 * i) * C + c0 + tx];
    __syncthreads();
#pragma unroll
    for (int i = 0; i < 4; i++) {
        float v = tile[tx][ty + 8 * i];
        h[(size_t)(c0 + ty + 8 * i) * R + r0 + tx] = __float2half(v);
    }
}

// ---------------------------------------------------------------------------
// fp16 1-pass GEMM (R16, unchanged): C = Ah·Bh + bias
// ---------------------------------------------------------------------------
#define GBM 128
#define GBN 128
#define GBK 32
#define NCH (KDIM / GBK)
#define ROWB 80
#define ATB (128 * ROWB)
#define BTB (128 * ROWB)
#define STAGE_B (ATB + 2 * BTB)
#define GEMM_SMEM (2 * STAGE_B)

template<int NPASS>
__global__ __launch_bounds__(256, 2)
void gemm_mma(const __half* __restrict__ Ah0, const __half* __restrict__ Ah1,
              const __half* __restrict__ Bh, const __half* __restrict__ Bl,
              const float* __restrict__ bias,
              float* __restrict__ Cf0, int ldc0, float* __restrict__ Cf1, int ldc1,
              __half* __restrict__ Ch0, __half* __restrict__ Ch1,
              int nsplit, int outmode, float csc0, float csc1)
{
    extern __shared__ char sm[];
    const uint32_t sbase = smem_to_u32(sm);
    const int tid  = threadIdx.x;
    const int lane = tid & 31;
    const int wid  = tid >> 5;
    const int wm   = (wid & 3) * 32;
    const int wn   = (wid >> 2) * 64;
    const int n0 = blockIdx.x * GBN;
    const int m0 = blockIdx.y * GBM;

    const __half* Ah = (n0 < nsplit) ? Ah0 : Ah1;

    float acc[2][8][4];
#pragma unroll
    for (int i = 0; i < 2; i++)
#pragma unroll
        for (int j = 0; j < 8; j++)
#pragma unroll
            for (int r = 0; r < 4; r++) acc[i][j][r] = 0.f;

    uint32_t aoff[2][2];
#pragma unroll
    for (int mf = 0; mf < 2; mf++)
#pragma unroll
        for (int ks = 0; ks < 2; ks++)
            aoff[mf][ks] = (uint32_t)((wm + mf * 16 + (lane & 15)) * ROWB
                                      + (ks * 16 + 8 * (lane >> 4)) * 2);
    uint32_t boff[4][2];
#pragma unroll
    for (int jj = 0; jj < 4; jj++)
#pragma unroll
        for (int ks = 0; ks < 2; ks++)
            boff[jj][ks] = (uint32_t)((wn + jj * 16 + (lane & 7) + 8 * (lane >> 4)) * ROWB
                                      + (ks * 16 + 8 * ((lane >> 3) & 1)) * 2);

    auto load_chunk = [&](int ic, int s) {
        const int k0 = ic * GBK;
#pragma unroll
        for (int it = 0; it < 2 + 2 * NPASS; it++) {
            const int idx = (it & 1) * 256 + tid;
            const int row = idx >> 2, seg = idx & 3;
            const __half* src;
            uint32_t dst;
            if (it < 2) {
                src = Ah + (size_t)(m0 + row) * KDIM + k0 + seg * 8;
                dst = sbase + s * STAGE_B + row * ROWB + seg * 16;
            } else if (it < 4) {
                src = Bh + (size_t)(n0 + row) * KDIM + k0 + seg * 8;
                dst = sbase + s * STAGE_B + ATB + row * ROWB + seg * 16;
            } else {
                src = Bl + (size_t)(n0 + row) * KDIM + k0 + seg * 8;
                dst = sbase + s * STAGE_B + ATB + BTB + row * ROWB + seg * 16;
            }
            CP_ASYNC16(dst, src);
        }
        CP_COMMIT();
    };

    load_chunk(0, 0);

    for (int ic = 0; ic < NCH; ic++) {
        const int s = ic & 1;
        if (ic + 1 < NCH) { load_chunk(ic + 1, s ^ 1); CP_WAIT(1); }
        else              { CP_WAIT(0); }
        __syncthreads();

        const uint32_t stage = sbase + s * STAGE_B;
#pragma unroll
        for (int ks = 0; ks < 2; ks++) {
            uint32_t a[2][4];
            LDSM_X4(a[0][0], a[0][1], a[0][2], a[0][3], stage + aoff[0][ks]);
            LDSM_X4(a[1][0], a[1][1], a[1][2], a[1][3], stage + aoff[1][ks]);
#pragma unroll
            for (int pass = 0; pass < NPASS; pass++) {
                const uint32_t Bbase = stage + ATB + pass * BTB;
#pragma unroll
                for (int jj = 0; jj < 4; jj++) {
                    uint32_t b0, b1, b2, b3;
                    LDSM_X4(b0, b1, b2, b3, Bbase + boff[jj][ks]);
                    MMA16816(acc[0][jj * 2],     a[0], b0, b1);
                    MMA16816(acc[1][jj * 2],     a[1], b0, b1);
                    MMA16816(acc[0][jj * 2 + 1], a[0], b2, b3);
                    MMA16816(acc[1][jj * 2 + 1], a[1], b2, b3);
                }
            }
        }
        __syncthreads();
    }

    int ld, nc0;
    float* Cf; __half* Ch; float csc;
    if (n0 < nsplit) { Cf = Cf0; Ch = Ch0; ld = ldc0; nc0 = n0; csc = csc0; }
    else             { Cf = Cf1; Ch = Ch1; ld = ldc1; nc0 = n0 - nsplit; csc = csc1; }

#pragma unroll
    for (int mf = 0; mf < 2; mf++) {
#pragma unroll
        for (int nf = 0; nf < 8; nf++) {
            const int nl = wn + nf * 8 + 2 * (lane & 3);
            const float bx = bias[n0 + nl];
            const float by = bias[n0 + nl + 1];
            const int m_up = m0 + wm + mf * 16 + (lane >> 2);
#pragma unroll
            for (int half = 0; half < 2; half++) {
                const int m = m_up + 8 * half;
                float v0 = acc[mf][nf][2 * half]     + bx;
                float v1 = acc[mf][nf][2 * half + 1] + by;
                if (outmode == 0) {
                    float2 v; v.x = v0; v.y = v1;
                    *(float2*)(Cf + (size_t)m * ld + nc0 + nl) = v;
                } else {
                    *(uint32_t*)(Ch + (size_t)m * ld + nc0 + nl) = packh(v0 * csc, v1 * csc);
                }
            }
        }
    }
}

// ---------------------------------------------------------------------------
// Tensor-core flash attention (fp16, log2 softmax with f16x2 exp, BK=128,
// l computed as a 129th V column via tensor core), split-KV.
// ---------------------------------------------------------------------------
#define ASTR 272
#define Q_TILE (128 * ASTR)
#define KV_TILE (128 * ASTR)
#define KV_STAGE (2 * KV_TILE)
#define ATT_SMEM (Q_TILE + 2 * KV_STAGE)   // 174080
#define NTT (LSEQ / 128)                   // 16
#define NTH (NTT / 2)                      // 8 per half

__global__ __launch_bounds__(256, 1)
void attn_mma(const __half* __restrict__ Qh, const __half* __restrict__ KVh,
              __half* __restrict__ Opart, float* __restrict__ Mpart, float* __restrict__ Lpart)
{
    extern __shared__ char sm[];
    const uint32_t sQh = smem_to_u32(sm);
    const uint32_t sKV = sQh + Q_TILE;

    const int tid  = threadIdx.x;
    const int lane = tid & 31;
    const int wid  = tid >> 5;
    const int wm   = wid * 16;

    const int qt = blockIdx.x, h = blockIdx.y;
    const int half = blockIdx.z / BSZ;
    const int b    = blockIdx.z % BSZ;
    const int qrow0 = b * LSEQ + qt * 128;
    const int hcol  = h * HDIM;
    const int jt0 = half * NTH, jtN = jt0 + NTH;

#pragma unroll
    for (int i = 0; i < 8; i++) {
        int idx = i * 256 + tid;
        int row = idx >> 4, seg = idx & 15;
        size_t g = (size_t)(qrow0 + row) * DIMSZ + hcol + seg * 8;
        CP_ASYNC16(sQh + row * ASTR + seg * 16, Qh + g);
    }
    CP_COMMIT();

    // init V pad: col 128 = 1.0 (ones column for l), cols 129-135 = 0; both stages
    {
        const int st = tid & 1, row = tid >> 1;     // 128 rows x 2 stages
        char* p = sm + Q_TILE + st * KV_STAGE + KV_TILE + row * ASTR + 256;
        uint4 v; v.x = 0x00003C00u; v.y = 0u; v.z = 0u; v.w = 0u;
        *(uint4*)p = v;
    }

    auto load_kv = [&](int jt, int s) {
        const uint32_t base = sKV + s * KV_STAGE;
        const int krow0 = b * LSEQ + jt * 128;
#pragma unroll
        for (int i = 0; i < 8; i++) {
            int idx = i * 256 + tid;
            int row = idx >> 4, seg = idx & 15;
            size_t roff = (size_t)(krow0 + row) * (2 * DIMSZ);
            uint32_t d = row * ASTR + seg * 16;
            CP_ASYNC16(base + d,           KVh + roff + hcol + seg * 8);
            CP_ASYNC16(base + KV_TILE + d, KVh + roff + DIMSZ + hcol + seg * 8);
        }
        CP_COMMIT();
    };
    load_kv(jt0, 0);

    const uint32_t ab = (uint32_t)((wm + (lane & 15)) * ASTR + (lane >> 4) * 16);
    const uint32_t kb = (uint32_t)(((lane & 7) + 8 * (lane >> 4)) * ASTR
                                   + ((lane >> 3) & 1) * 16);
    const uint32_t vb = (uint32_t)(((lane & 7) + 8 * ((lane >> 3) & 1)) * ASTR
                                   + (lane >> 4) * 16);
    const uint32_t vpad = (uint32_t)(((lane & 7) + 8 * ((lane >> 3) & 1)) * ASTR + 256);

    float oacc[16][4];
#pragma unroll
    for (int f = 0; f < 16; f++)
#pragma unroll
        for (int e = 0; e < 4; e++) oacc[f][e] = 0.f;
    float lacc[4] = {0.f, 0.f, 0.f, 0.f};   // col-128 accumulator (l)
    float m_prev[2] = {-3.0e38f, -3.0e38f};

    for (int jt = jt0; jt < jtN; jt++) {
        const int s = jt & 1;
        const bool has_next = (jt + 1 < jtN);
        if (has_next) load_kv(jt + 1, s ^ 1);
        if (has_next) { CP_WAIT(1); } else { CP_WAIT(0); }
        __syncthreads();

        const uint32_t sK = sKV + s * KV_STAGE;
        const uint32_t sV = sK + KV_TILE;

        // ---- S = Qh Kh^T  (log2 domain; q pre-scaled) ----
        float sacc[16][4];
#pragma unroll
        for (int f = 0; f < 16; f++)
#pragma unroll
            for (int e = 0; e < 4; e++) sacc[f][e] = 0.f;

#pragma unroll
        for (int ks = 0; ks < 8; ks++) {
            uint32_t ah[4];
            LDSM_X4(ah[0], ah[1], ah[2], ah[3], sQh + ab + ks * 32);
#pragma unroll
            for (int jj = 0; jj < 8; jj++) {
                uint32_t h0, h1, h2, h3;
                LDSM_X4(h0, h1, h2, h3, sK + kb + jj * (16 * ASTR) + ks * 32);
                MMA16816(sacc[2 * jj],     ah, h0, h1);
                MMA16816(sacc[2 * jj + 1], ah, h2, h3);
            }
        }

        // ---- max reduce ----
        float mx0 = -3.0e38f, mx1 = -3.0e38f;
#pragma unroll
        for (int f = 0; f < 16; f++) {
            mx0 = fmaxf(mx0, fmaxf(sacc[f][0], sacc[f][1]));
            mx1 = fmaxf(mx1, fmaxf(sacc[f][2], sacc[f][3]));
        }
        mx0 = fmaxf(mx0, __shfl_xor_sync(0xffffffffu, mx0, 1));
        mx0 = fmaxf(mx0, __shfl_xor_sync(0xffffffffu, mx0, 2));
        mx1 = fmaxf(mx1, __shfl_xor_sync(0xffffffffu, mx1, 1));
        mx1 = fmaxf(mx1, __shfl_xor_sync(0xffffffffu, mx1, 2));

        float mnew0 = fmaxf(m_prev[0], mx0);
        float mnew1 = fmaxf(m_prev[1], mx1);
        float er0 = ex2f(m_prev[0] - mnew0);
        float er1 = ex2f(m_prev[1] - mnew1);
        m_prev[0] = mnew0; m_prev[1] = mnew1;

        // ---- rescale O (and l cols) ----
#pragma unroll
        for (int f = 0; f < 16; f++) {
            oacc[f][0] *= er0; oacc[f][1] *= er0;
            oacc[f][2] *= er1; oacc[f][3] *= er1;
        }
        lacc[0] *= er0; lacc[1] *= er0;
        lacc[2] *= er1; lacc[3] *= er1;

        // ---- P = 2^(s - m) via f16x2 exp (packed directly as A-fragments) ----
        uint32_t aph[8][4];
#pragma unroll
        for (int t = 0; t < 8; t++) {
#pragma unroll
            for (int hh = 0; hh < 2; hh++) {
                const int f = 2 * t + hh;
                aph[t][2 * hh]     = h2exp2(packh(sacc[f][0] - mnew0, sacc[f][1] - mnew0));
                aph[t][2 * hh + 1] = h2exp2(packh(sacc[f][2] - mnew1, sacc[f][3] - mnew1));
            }
        }

        // ---- O += Ph Vh  (+ ones-column MMA accumulates l) ----
#pragma unroll
        for (int t = 0; t < 8; t++) {
#pragma unroll
            for (int g = 0; g < 8; g++) {
                uint32_t h0, h1, h2, h3;
                LDSM_X4_T(h0, h1, h2, h3, sV + vb + t * (16 * ASTR) + g * 32);
                MMA16816(oacc[2 * g],     aph[t], h0, h1);
                MMA16816(oacc[2 * g + 1], aph[t], h2, h3);
            }
            uint32_t p0, p1;
            LDSM_X2_T(p0, p1, sV + vpad + t * (16 * ASTR));
            MMA16816(lacc, aph[t], p0, p1);
        }
        __syncthreads();
    }

    // ---- l broadcast (col 128 lives in lanes with lane%4==0) ----
    const int src = (lane >> 2) << 2;
    float l0 = __shfl_sync(0xffffffffu, lacc[0], src);
    float l1 = __shfl_sync(0xffffffffu, lacc[2], src);

    // ---- epilogue: locally-normalized fp16 partials + (m, l) ----
#pragma unroll
    for (int rs = 0; rs < 2; rs++) {
        const float lv = rs ? l1 : l0;
        const float inv = 1.0f / lv;
        const int lrow = qt * 128 + wm + (lane >> 2) + 8 * rs;
        const size_t orow = ((size_t)half * MROWS + b * LSEQ + lrow) * DIMSZ + hcol;
        if ((lane & 3) == 0) {
            size_t mi = (((size_t)half * BSZ + b) * NHEADS + h) * LSEQ + lrow;
            Mpart[mi] = m_prev[rs];
            Lpart[mi] = lv;
        }
#pragma unroll
        for (int f = 0; f < 16; f++) {
            *(uint32_t*)(Opart + orow + f * 8 + 2 * (lane & 3)) =
                packh(oacc[f][2 * rs] * inv, oacc[f][2 * rs + 1] * inv);
        }
    }
}

// ---------------------------------------------------------------------------
// Combine normalized KV-halves (log2-domain m): wi = li·2^(mi−m) / Σ
// ---------------------------------------------------------------------------
__global__ __launch_bounds__(256)
void attn_combine(const __half* __restrict__ Opart,
                  const float* __restrict__ Mpart, const float* __restrict__ Lpart,
                  __half* __restrict__ Oh)
{
    const size_t i = (size_t)blockIdx.x * 256 + threadIdx.x;
    const size_t e = i * 4;
    const int row = (int)(e / DIMSZ);
    const int col = (int)(e % DIMSZ);
    const int h = col >> 7;
    const int b = row / LSEQ;
    const int lr = row % LSEQ;

    const size_t mi0 = (((size_t)0 * BSZ + b) * NHEADS + h) * LSEQ + lr;
    const size_t mi1 = (((size_t)1 * BSZ + b) * NHEADS + h) * LSEQ + lr;
    const float m0 = Mpart[mi0], m1 = Mpart[mi1];
    const float l0 = Lpart[mi0], l1 = Lpart[mi1];
    const float m  = fmaxf(m0, m1);
    const float s0 = l0 * ex2f(m0 - m), s1 = l1 * ex2f(m1 - m);
    const float inv = 1.0f / (s0 + s1);
    const float w0 = s0 * inv, w1 = s1 * inv;

    uint2 a = ((const uint2*)Opart)[i];
    uint2 c = ((const uint2*)(Opart + (size_t)MROWS * DIMSZ))[i];
    float v0 = hlo_f(a.x) * w0 + hlo_f(c.x) * w1;
    float v1 = hhi_f(a.x) * w0 + hhi_f(c.x) * w1;
    float v2 = hlo_f(a.y) * w0 + hlo_f(c.y) * w1;
    float v3 = hhi_f(a.y) * w0 + hhi_f(c.y) * w1;

    uint2 o;
    o.x = packh(v0, v1);
    o.y = packh(v2, v3);
    ((uint2*)Oh)[i] = o;
}

// ---------------------------------------------------------------------------
extern "C" void kernel_launch(void* const* d_in, const int* in_sizes, int n_in,
                              void* d_out, int out_size)
{
    const float* x       = (const float*)d_in[0];
    const float* context = (const float*)d_in[1];
    const float* W_qkv   = (const float*)d_in[2];
    const float* b_qkv   = (const float*)d_in[3];
    const float* W_proj  = (const float*)d_in[4];
    const float* b_proj  = (const float*)d_in[5];
    float* out = (float*)d_out;

    __half *xh, *ch, *wqh, *wph;
    __half *qh, *kvh, *ath, *oparth;
    float *mpart, *lpart;
    cudaGetSymbolAddress((void**)&xh,  g_xh);
    cudaGetSymbolAddress((void**)&ch,  g_ch);
    cudaGetSymbolAddress((void**)&wqh, g_wqh);
    cudaGetSymbolAddress((void**)&wph, g_wph);
    cudaGetSymbolAddress((void**)&qh,  g_qh);
    cudaGetSymbolAddress((void**)&kvh, g_kvh);
    cudaGetSymbolAddress((void**)&ath, g_ath);
    cudaGetSymbolAddress((void**)&oparth, g_oparth);
    cudaGetSymbolAddress((void**)&mpart, g_mpart);
    cudaGetSymbolAddress((void**)&lpart, g_lpart);

    cudaFuncSetAttribute(gemm_mma<1>, cudaFuncAttributeMaxDynamicSharedMemorySize, GEMM_SMEM);
    cudaFuncSetAttribute(attn_mma, cudaFuncAttributeMaxDynamicSharedMemorySize, ATT_SMEM);

    const int n4 = MROWS * DIMSZ / 4;

    split_one<<<(n4 + 255) / 256, 256>>>(x, xh, n4);
    split_one<<<(n4 + 255) / 256, 256>>>(context, ch, n4);
    transpose_one<<<dim3(3 * DIMSZ / 32, DIMSZ / 32), 256>>>(W_qkv, wqh, DIMSZ, 3 * DIMSZ);
    transpose_one<<<dim3(DIMSZ / 32, DIMSZ / 32), 256>>>(W_proj, wph, DIMSZ, DIMSZ);

    // qkv GEMM: pure fp16, 1 pass; q outputs pre-scaled by SCALE*log2(e)
    gemm_mma<1><<<dim3(3 * DIMSZ / GBN, MROWS / GBM), 256, GEMM_SMEM>>>(
        xh, ch, wqh, nullptr, b_qkv,
        nullptr, DIMSZ, nullptr, 2 * DIMSZ,
        qh, kvh, DIMSZ, 2, SCALE_L2E, 1.0f);

    // split-KV attention (fp16, f16x2 exp, tensor-core l)
    attn_mma<<<dim3(LSEQ / 128, NHEADS, 2 * BSZ), 256, ATT_SMEM>>>(
        qh, kvh, oparth, mpart, lpart);

    attn_combine<<<(n4 + 255) / 256, 256>>>(oparth, mpart, lpart, ath);

    // proj GEMM: pure fp16, 1 pass, fp32 out
    gemm_mma<1><<<dim3(DIMSZ / GBN, MROWS / GBM), 256, GEMM_SMEM>>>(
        ath, ath, wph, nullptr, b_proj,
        out, DIMSZ, out, DIMSZ,
        nullptr, nullptr, 1 << 30, 0, 1.0f, 1.0f);
}